// round 9
// baseline (speedup 1.0000x reference)
#include <cuda_runtime.h>
#include <cuda_bf16.h>
#include <cstdint>
#include <math.h>

typedef __nv_bfloat16 bf16;

#define MBN   8
#define NQL   1024
#define NKVL  1024
#define HH    8
#define SCALE 0.125f
#define DD    512
#define N4    (MBN*NQL*DD)

__device__ bf16  g_xh[3][N4], g_xm[3][N4];
__device__ bf16  g_wh[4][DD*DD], g_wm[4][DD*DD];
__device__ bf16  g_qh[N4], g_qm[N4], g_kh[N4], g_km[N4];
__device__ float g_vf[N4];
__device__ bf16  g_vth[N4], g_vtm[N4];
__device__ bf16  g_cth[N4], g_ctm[N4];

// ---------------- helpers ----------------
__device__ __forceinline__ uint32_t smem_u32(const void* p){
    uint32_t a;
    asm("{ .reg .u64 t; cvta.to.shared.u64 t, %1; cvt.u32.u64 %0, t; }":"=r"(a):"l"(p));
    return a;
}
__device__ __forceinline__ void cp16(uint32_t s, const void* g){
    asm volatile("cp.async.cg.shared.global [%0], [%1], 16;"::"r"(s),"l"(g));
}
#define CP_COMMIT() asm volatile("cp.async.commit_group;":::"memory")

__device__ __forceinline__ void mma16816(float* c, const uint32_t* a,
                                         uint32_t b0, uint32_t b1){
    asm volatile(
      "mma.sync.aligned.m16n8k16.row.col.f32.bf16.bf16.f32 "
      "{%0,%1,%2,%3}, {%4,%5,%6,%7}, {%8,%9}, {%0,%1,%2,%3};"
      : "+f"(c[0]), "+f"(c[1]), "+f"(c[2]), "+f"(c[3])
      : "r"(a[0]), "r"(a[1]), "r"(a[2]), "r"(a[3]), "r"(b0), "r"(b1));
}
__device__ __forceinline__ void psplit2(float a, float b, uint32_t& h, uint32_t& m){
    bf16 ha = __float2bfloat16_rn(a), hb = __float2bfloat16_rn(b);
    bf16 ma = __float2bfloat16_rn(a - __bfloat162float(ha));
    bf16 mb = __float2bfloat16_rn(b - __bfloat162float(hb));
    __nv_bfloat162 H = __halves2bfloat162(ha, hb), M = __halves2bfloat162(ma, mb);
    h = *(uint32_t*)&H; m = *(uint32_t*)&M;
}

// ---------------- input split (3 inputs, one launch) ----------------
__global__ void xsplit3(const float* __restrict__ x0, const float* __restrict__ x1,
                        const float* __restrict__ x2,
                        bf16* __restrict__ xh, bf16* __restrict__ xm){
    int z = blockIdx.y;
    const float* x = (z == 0) ? x0 : (z == 1) ? x1 : x2;
    size_t base = (size_t)z * N4;
    int i = (blockIdx.x*256 + threadIdx.x)*4;
    float4 v = *(const float4*)(x + i);
    uint32_t h0,m0,h1,m1;
    psplit2(v.x,v.y,h0,m0); psplit2(v.z,v.w,h1,m1);
    *(uint32_t*)(xh+base+i) = h0; *(uint32_t*)(xh+base+i+2) = h1;
    *(uint32_t*)(xm+base+i) = m0; *(uint32_t*)(xm+base+i+2) = m1;
}

// ---------------- W[k][n] -> split Wt[n][k] (4 weights, one launch) --------
__global__ void wtrans4(const float* __restrict__ W0, const float* __restrict__ W1,
                        const float* __restrict__ W2, const float* __restrict__ W3,
                        bf16* __restrict__ Wh, bf16* __restrict__ Wm){
    int z = blockIdx.z;
    const float* W = (z==0)?W0:(z==1)?W1:(z==2)?W2:W3;
    bf16* wh = Wh + (size_t)z*DD*DD;
    bf16* wm = Wm + (size_t)z*DD*DD;
    __shared__ float t[32][33];
    int n0 = blockIdx.x*32, k0 = blockIdx.y*32;
    int tx = threadIdx.x, ty = threadIdx.y;
#pragma unroll
    for (int i=0;i<32;i+=8) t[ty+i][tx] = W[(size_t)(k0+ty+i)*DD + n0+tx];
    __syncthreads();
#pragma unroll
    for (int i=0;i<32;i+=8){
        float v = t[tx][ty+i];
        bf16 hh = __float2bfloat16_rn(v);
        size_t idx = (size_t)(n0+ty+i)*DD + k0+tx;
        wh[idx] = hh;
        wm[idx] = __float2bfloat16_rn(v - __bfloat162float(hh));
    }
}

// ---------------- V f32 -> split transposed ----------------
__global__ void vtrans(const float* __restrict__ V, bf16* __restrict__ Vh,
                       bf16* __restrict__ Vm){
    __shared__ float t[32][33];
    int z = blockIdx.z, m = z>>3, h = z&7;
    int kk0 = blockIdx.x*32, d0 = blockIdx.y*32;
    int tx = threadIdx.x, ty = threadIdx.y;
#pragma unroll
    for (int i=0;i<32;i+=8)
        t[ty+i][tx] = V[(size_t)(m*NKVL + kk0+ty+i)*DD + h*64 + d0+tx];
    __syncthreads();
#pragma unroll
    for (int i=0;i<32;i+=8){
        float v = t[tx][ty+i];
        bf16 hh = __float2bfloat16_rn(v);
        size_t idx = (size_t)(z*64 + d0+ty+i)*NKVL + kk0 + tx;
        Vh[idx] = hh;
        Vm[idx] = __float2bfloat16_rn(v - __bfloat162float(hh));
    }
}

// ---------------- GEMM core macro ----------------
#define PSTG 40960
#define PJ_SMEM (2*PSTG)

#define PJ_ISSUE(kt, s) do{ \
    uint32_t st = sb + (s)*PSTG; int k0 = (kt)*32; \
    for (int i = tid; i < 512; i += 256){ \
        int r = i>>2; uint32_t ro = r*80 + (i&3)*16; int c8 = (i&3)*8; \
        size_t ga = (size_t)(bm+r)*DD + k0 + c8; \
        cp16(st + ro,         Ah + ga); \
        cp16(st + 10240 + ro, Am + ga); \
        size_t gb = (size_t)(bn+r)*DD + k0 + c8; \
        cp16(st + 20480 + ro, Bh + gb); \
        cp16(st + 30720 + ro, Bm + gb); \
    } CP_COMMIT(); }while(0)

#define PJ_MAINLOOP() \
    PJ_ISSUE(0, 0); \
    _Pragma("unroll 1") \
    for (int kt = 0; kt < 16; kt++){ \
        if (kt < 15){ \
            PJ_ISSUE(kt+1, (kt+1)&1); \
            asm volatile("cp.async.wait_group 1;":::"memory"); \
        } else { \
            asm volatile("cp.async.wait_group 0;":::"memory"); \
        } \
        __syncthreads(); \
        const bf16* sAh = (const bf16*)(sp + (kt&1)*PSTG); \
        const bf16* sAm = sAh + 5120; \
        const bf16* sBh = sAm + 5120; \
        const bf16* sBm = sBh + 5120; \
        _Pragma("unroll") \
        for (int ks = 0; ks < 2; ks++){ \
            int kb = ks*16 + q2; \
            uint32_t ah[4][4], am[4][4]; \
            _Pragma("unroll") \
            for (int mi = 0; mi < 4; mi++){ \
                const bf16* p = sAh + (wm + mi*16 + ln4)*40 + kb; \
                ah[mi][0]=*(const uint32_t*)p;     ah[mi][1]=*(const uint32_t*)(p+8*40); \
                ah[mi][2]=*(const uint32_t*)(p+8); ah[mi][3]=*(const uint32_t*)(p+8*40+8); \
                const bf16* pm = sAm + (wm + mi*16 + ln4)*40 + kb; \
                am[mi][0]=*(const uint32_t*)pm;     am[mi][1]=*(const uint32_t*)(pm+8*40); \
                am[mi][2]=*(const uint32_t*)(pm+8); am[mi][3]=*(const uint32_t*)(pm+8*40+8); \
            } \
            _Pragma("unroll") \
            for (int nj = 0; nj < 4; nj++){ \
                const bf16* p = sBh + (wn + nj*8 + ln4)*40 + kb; \
                uint32_t bh0 = *(const uint32_t*)p, bh1 = *(const uint32_t*)(p+8); \
                const bf16* pm = sBm + (wn + nj*8 + ln4)*40 + kb; \
                uint32_t bm0 = *(const uint32_t*)pm, bm1 = *(const uint32_t*)(pm+8); \
                _Pragma("unroll") \
                for (int mi = 0; mi < 4; mi++){ \
                    mma16816(acc[mi][nj], ah[mi], bh0, bh1); \
                    mma16816(acc[mi][nj], ah[mi], bm0, bm1); \
                    mma16816(acc[mi][nj], am[mi], bh0, bh1); \
                } \
            } \
        } \
        __syncthreads(); \
    }

// ---------------- merged QKV projection (z = 0:Q 1:K 2:V) ----------------
__global__ void __launch_bounds__(256) qkv_proj(
    const bf16* __restrict__ Xh, const bf16* __restrict__ Xm,
    const bf16* __restrict__ Wh, const bf16* __restrict__ Wm,
    bf16* __restrict__ Qh, bf16* __restrict__ Qm,
    bf16* __restrict__ Kh, bf16* __restrict__ Km,
    float* __restrict__ Vf)
{
    extern __shared__ char sp[];
    uint32_t sb = smem_u32(sp);
    const int tid = threadIdx.x, lane = tid & 31, wid = tid >> 5;
    const int ln4 = lane >> 2, q2 = (lane & 3)*2;
    const int wm = (wid & 1)*64, wn = (wid >> 1)*32;
    const int bm = blockIdx.y*128, bn = blockIdx.x*128;
    const int z = blockIdx.z;
    const bf16* Ah = Xh + (size_t)z*N4;
    const bf16* Am = Xm + (size_t)z*N4;
    const bf16* Bh = Wh + (size_t)z*DD*DD;
    const bf16* Bm = Wm + (size_t)z*DD*DD;
    float acc[4][4][4];
#pragma unroll
    for (int a=0;a<4;a++)
#pragma unroll
      for (int b=0;b<4;b++)
#pragma unroll
        for (int c=0;c<4;c++) acc[a][b][c]=0.f;

    PJ_MAINLOOP();

    const float scale = (z == 0) ? SCALE : 1.0f;
#pragma unroll
    for (int mi = 0; mi < 4; mi++){
        int r0 = bm + wm + mi*16 + ln4;
#pragma unroll
        for (int nj = 0; nj < 4; nj++){
            int c = bn + wn + nj*8 + q2;
            float v0 = acc[mi][nj][0]*scale, v1 = acc[mi][nj][1]*scale;
            float v2 = acc[mi][nj][2]*scale, v3 = acc[mi][nj][3]*scale;
            if (z == 2){
                *(float2*)(Vf + (size_t)r0*DD + c)     = make_float2(v0, v1);
                *(float2*)(Vf + (size_t)(r0+8)*DD + c) = make_float2(v2, v3);
            } else {
                bf16* Ch = (z == 0) ? Qh : Kh;
                bf16* Cm = (z == 0) ? Qm : Km;
                uint32_t h, m;
                psplit2(v0, v1, h, m);
                *(uint32_t*)(Ch + (size_t)r0*DD + c) = h;
                *(uint32_t*)(Cm + (size_t)r0*DD + c) = m;
                psplit2(v2, v3, h, m);
                *(uint32_t*)(Ch + (size_t)(r0+8)*DD + c) = h;
                *(uint32_t*)(Cm + (size_t)(r0+8)*DD + c) = m;
            }
        }
    }
}

// ---------------- output projection ----------------
__global__ void __launch_bounds__(256) out_proj(
    const bf16* __restrict__ Ah, const bf16* __restrict__ Am,
    const bf16* __restrict__ Bh, const bf16* __restrict__ Bm,
    const float* __restrict__ bias, float* __restrict__ Cf)
{
    extern __shared__ char sp[];
    uint32_t sb = smem_u32(sp);
    const int tid = threadIdx.x, lane = tid & 31, wid = tid >> 5;
    const int ln4 = lane >> 2, q2 = (lane & 3)*2;
    const int wm = (wid & 1)*64, wn = (wid >> 1)*32;
    const int bm = blockIdx.y*128, bn = blockIdx.x*128;
    float acc[4][4][4];
#pragma unroll
    for (int a=0;a<4;a++)
#pragma unroll
      for (int b=0;b<4;b++)
#pragma unroll
        for (int c=0;c<4;c++) acc[a][b][c]=0.f;

    PJ_MAINLOOP();

#pragma unroll
    for (int mi = 0; mi < 4; mi++){
        int r0 = bm + wm + mi*16 + ln4;
#pragma unroll
        for (int nj = 0; nj < 4; nj++){
            int c = bn + wn + nj*8 + q2;
            float b0 = bias[c], b1 = bias[c+1];
            *(float2*)(Cf + (size_t)r0*DD + c) =
                make_float2(acc[mi][nj][0] + b0, acc[mi][nj][1] + b1);
            *(float2*)(Cf + (size_t)(r0+8)*DD + c) =
                make_float2(acc[mi][nj][2] + b0, acc[mi][nj][3] + b1);
        }
    }
}

// ---------------- fused attention: 3-stage pipeline, j-outer overlap --------
#define O_QH 0
#define O_QM 18432
#define O_KV 36864
#define KVSTG 36864
#define S_KH 0
#define S_KM 9216
#define S_VH 18432
#define S_VM 27648
#define O_HK (O_KV + 3*KVSTG)
#define HKSTG 5120
#define O_V1 (O_HK + 3*HKSTG)
#define AT_SMEM (O_V1 + 3*256)

__global__ void __launch_bounds__(256) attn_bf(
    const bf16* __restrict__ Qh_g, const bf16* __restrict__ Qm_g,
    const bf16* __restrict__ Kh_g, const bf16* __restrict__ Km_g,
    const bf16* __restrict__ Vh_g, const bf16* __restrict__ Vm_g,
    const float* __restrict__ Tq, const float* __restrict__ Tk,
    const float* __restrict__ kw1, const float* __restrict__ kb1,
    const float* __restrict__ kw2, const float* __restrict__ kb2,
    bf16* __restrict__ Cth, bf16* __restrict__ Ctm)
{
    extern __shared__ char sp[];
    uint32_t sb = smem_u32(sp);

    const int tid = threadIdx.x, lane = tid & 31, wid = tid >> 5;
    const int ln4 = lane >> 2, q2 = (lane & 3)*2;
    const int m = blockIdx.z, h = blockIdx.y, q0 = blockIdx.x*128;
    const int rl0 = wid*16 + ln4;

    for (int i = tid; i < 1024; i += 256){
        int r = i>>3; uint32_t ro = r*144 + (i&7)*16;
        size_t g = (size_t)(m*NQL+q0+r)*DD + h*64 + (i&7)*8;
        cp16(sb + O_QH + ro, Qh_g + g);
        cp16(sb + O_QM + ro, Qm_g + g);
    }
#define KV_ISSUE(kk0, s) do{ \
    uint32_t st = sb + O_KV + (s)*KVSTG; \
    for (int i = tid; i < 512; i += 256){ \
        int r = i>>3; uint32_t ro = r*144 + (i&7)*16; int c8 = (i&7)*8; \
        size_t gk = (size_t)(m*NKVL + (kk0) + r)*DD + h*64 + c8; \
        cp16(st + S_KH + ro, Kh_g + gk); \
        cp16(st + S_KM + ro, Km_g + gk); \
        size_t gv = (size_t)((m*HH+h)*64 + r)*NKVL + (kk0) + c8; \
        cp16(st + S_VH + ro, Vh_g + gv); \
        cp16(st + S_VM + ro, Vm_g + gv); \
    } CP_COMMIT(); }while(0)

#define HK_GEN(tile, s) do{ \
    if (tid < 64){ \
        float2 tk2 = *(const float2*)(Tk + (size_t)(m*NKVL + (tile)*64 + tid)*2); \
        float v1 = 0.f; \
        float* Hb = (float*)(sp + O_HK + (s)*HKSTG); \
        _Pragma("unroll") \
        for (int j = 0; j < 16; j++){ \
            float hk = tk2.x*kw1[j] + tk2.y*kw1[16+j]; \
            Hb[tid*20 + j] = hk; \
            v1 = fmaf(ws[j], hk, v1); \
        } \
        ((float*)(sp + O_V1))[(s)*64 + tid] = v1; \
    } }while(0)

    KV_ISSUE(0, 0);
    KV_ISSUE(64, 1);

    float ws[16], uq0[16], uq1[16];
    float2 ta = *(const float2*)(Tq + (size_t)(m*NQL + q0 + rl0)*2);
    float2 tb = *(const float2*)(Tq + (size_t)(m*NQL + q0 + rl0 + 8)*2);
    float U1r0 = kb2[h] - 10.f, U1r1 = U1r0;
#pragma unroll
    for (int j = 0; j < 16; j++){
        ws[j] = 0.5f*kw2[j*HH + h];
        float w0 = kw1[j], w1 = kw1[16+j], b = kb1[j];
        uq0[j] = ta.x*w0 + ta.y*w1 + b;
        uq1[j] = tb.x*w0 + tb.y*w1 + b;
        U1r0 = fmaf(ws[j], uq0[j], U1r0);
        U1r1 = fmaf(ws[j], uq1[j], U1r1);
    }
    HK_GEN(0, 0);
    HK_GEN(1, 1);

    // wait for Q + KV0 (group 0), then hoist Q fragments into registers
    asm volatile("cp.async.wait_group 1;":::"memory");
    __syncthreads();
    uint32_t qa[4][4], qb[4][4];
    {
        const bf16* Qh = (const bf16*)(sp + O_QH);
        const bf16* Qm = (const bf16*)(sp + O_QM);
#pragma unroll
        for (int ks = 0; ks < 4; ks++){
            int kb = ks*16 + q2;
            const bf16* p = Qh + rl0*72 + kb;
            qa[ks][0]=*(const uint32_t*)p;     qa[ks][1]=*(const uint32_t*)(p+8*72);
            qa[ks][2]=*(const uint32_t*)(p+8); qa[ks][3]=*(const uint32_t*)(p+8*72+8);
            const bf16* pm = Qm + rl0*72 + kb;
            qb[ks][0]=*(const uint32_t*)pm;     qb[ks][1]=*(const uint32_t*)(pm+8*72);
            qb[ks][2]=*(const uint32_t*)(pm+8); qb[ks][3]=*(const uint32_t*)(pm+8*72+8);
        }
    }

    float oacc[8][4];
#pragma unroll
    for (int j=0;j<8;j++)
#pragma unroll
        for (int c=0;c<4;c++) oacc[j][c]=0.f;
    float l0 = 0.f, l1 = 0.f;

#pragma unroll 1
    for (int t = 0; t < 16; t++){
        if (t > 0){
            if (t < 15){
                asm volatile("cp.async.wait_group 1;":::"memory");
            } else {
                asm volatile("cp.async.wait_group 0;":::"memory");
            }
            __syncthreads();
        }
        if (t <= 13){
            int s2 = (t+2) % 3;
            KV_ISSUE((t+2)*64, s2);
            HK_GEN(t+2, s2);
        }
        const int scur = t % 3;
        const char* st = sp + O_KV + scur*KVSTG;
        const bf16* Kh = (const bf16*)(st + S_KH);
        const bf16* Km = (const bf16*)(st + S_KM);
        const bf16* Vh = (const bf16*)(st + S_VH);
        const bf16* Vm = (const bf16*)(st + S_VM);
        const float* Hc = (const float*)(sp + O_HK + scur*HKSTG);
        const float* Vc = (const float*)(sp + O_V1) + scur*64;

        // j-outer: sacc[j] completes early so bias/exp (fma pipe) overlaps
        // with the HMMAs of subsequent j (tensor pipe).
        uint32_t pah[4][4], pam[4][4];
        float sacc[8][4];
#pragma unroll
        for (int j = 0; j < 8; j++){
#pragma unroll
            for (int c = 0; c < 4; c++) sacc[j][c] = 0.f;
#pragma unroll
            for (int ks = 0; ks < 4; ks++){
                int kb = ks*16 + q2;
                const bf16* pk = Kh + (j*8 + ln4)*72 + kb;
                uint32_t bh0 = *(const uint32_t*)pk, bh1 = *(const uint32_t*)(pk+8);
                const bf16* pk2 = Km + (j*8 + ln4)*72 + kb;
                uint32_t bm0 = *(const uint32_t*)pk2, bm1 = *(const uint32_t*)(pk2+8);
                mma16816(sacc[j], qa[ks], bh0, bh1);
                mma16816(sacc[j], qa[ks], bm0, bm1);
                mma16816(sacc[j], qb[ks], bh0, bh1);
            }
            float pe[4];
#pragma unroll
            for (int e = 0; e < 2; e++){
                int c = j*8 + q2 + e;
                const float4* hp = (const float4*)(Hc + c*20);
                float4 f0 = hp[0], f1 = hp[1], f2 = hp[2], f3 = hp[3];
                float hv[16] = {f0.x,f0.y,f0.z,f0.w, f1.x,f1.y,f1.z,f1.w,
                                f2.x,f2.y,f2.z,f2.w, f3.x,f3.y,f3.z,f3.w};
                float v1c = Vc[c];
                float s0 = sacc[j][e]   + U1r0 - v1c;
                float s1 = sacc[j][2+e] + U1r1 - v1c;
#pragma unroll
                for (int jj = 0; jj < 16; jj++){
                    s0 = fmaf(ws[jj], fabsf(uq0[jj] - hv[jj]), s0);
                    s1 = fmaf(ws[jj], fabsf(uq1[jj] - hv[jj]), s1);
                }
                float e0 = __expf(s0), e1 = __expf(s1);
                l0 += e0; l1 += e1;
                pe[e] = e0; pe[2+e] = e1;
            }
            int tt2 = j >> 1, base = (j & 1)*2;
            psplit2(pe[0], pe[1], pah[tt2][base],   pam[tt2][base]);
            psplit2(pe[2], pe[3], pah[tt2][base+1], pam[tt2][base+1]);
        }
#pragma unroll
        for (int tt = 0; tt < 4; tt++){
            int kb = tt*16 + q2;
#pragma unroll
            for (int j2 = 0; j2 < 8; j2++){
                const bf16* pv = Vh + (j2*8 + ln4)*72 + kb;
                uint32_t bh0 = *(const uint32_t*)pv, bh1 = *(const uint32_t*)(pv+8);
                const bf16* pv2 = Vm + (j2*8 + ln4)*72 + kb;
                uint32_t bm0 = *(const uint32_t*)pv2, bm1 = *(const uint32_t*)(pv2+8);
                mma16816(oacc[j2], pah[tt], bh0, bh1);
                mma16816(oacc[j2], pah[tt], bm0, bm1);
                mma16816(oacc[j2], pam[tt], bh0, bh1);
            }
        }
    }

    l0 += __shfl_xor_sync(0xffffffffu, l0, 1);
    l0 += __shfl_xor_sync(0xffffffffu, l0, 2);
    l1 += __shfl_xor_sync(0xffffffffu, l1, 1);
    l1 += __shfl_xor_sync(0xffffffffu, l1, 2);
    float inv0 = 1.f/l0, inv1 = 1.f/l1;
    size_t o0 = (size_t)(m*NQL + q0 + rl0)*DD + h*64;
    size_t o1 = o0 + 8*DD;
#pragma unroll
    for (int j2 = 0; j2 < 8; j2++){
        int c = j2*8 + q2;
        uint32_t hh, mm;
        psplit2(oacc[j2][0]*inv0, oacc[j2][1]*inv0, hh, mm);
        *(uint32_t*)(Cth + o0 + c) = hh; *(uint32_t*)(Ctm + o0 + c) = mm;
        psplit2(oacc[j2][2]*inv1, oacc[j2][3]*inv1, hh, mm);
        *(uint32_t*)(Cth + o1 + c) = hh; *(uint32_t*)(Ctm + o1 + c) = mm;
    }
}

// ---------------- host launcher ----------------
extern "C" void kernel_launch(void* const* d_in, const int* in_sizes, int n_in,
                              void* d_out, int out_size)
{
    const float* xq    = (const float*)d_in[0];
    const float* xk    = (const float*)d_in[1];
    const float* xv    = (const float*)d_in[2];
    const float* tq    = (const float*)d_in[3];
    const float* tk    = (const float*)d_in[4];
    const float* w_q   = (const float*)d_in[5];
    const float* w_k   = (const float*)d_in[6];
    const float* w_v   = (const float*)d_in[7];
    const float* w_out = (const float*)d_in[8];
    const float* b_out = (const float*)d_in[9];
    const float* kw1   = (const float*)d_in[10];
    const float* kb1   = (const float*)d_in[11];
    const float* kw2   = (const float*)d_in[12];
    const float* kb2   = (const float*)d_in[13];
    float* out = (float*)d_out;

    bf16 *xh,*xm,*wh,*wm,*qh,*qm,*kh,*km,*vth,*vtm,*cth,*ctm;
    float *vf;
    cudaGetSymbolAddress((void**)&xh,  g_xh);
    cudaGetSymbolAddress((void**)&xm,  g_xm);
    cudaGetSymbolAddress((void**)&wh,  g_wh);
    cudaGetSymbolAddress((void**)&wm,  g_wm);
    cudaGetSymbolAddress((void**)&qh,  g_qh);
    cudaGetSymbolAddress((void**)&qm,  g_qm);
    cudaGetSymbolAddress((void**)&kh,  g_kh);
    cudaGetSymbolAddress((void**)&km,  g_km);
    cudaGetSymbolAddress((void**)&vf,  g_vf);
    cudaGetSymbolAddress((void**)&vth, g_vth);
    cudaGetSymbolAddress((void**)&vtm, g_vtm);
    cudaGetSymbolAddress((void**)&cth, g_cth);
    cudaGetSymbolAddress((void**)&ctm, g_ctm);

    cudaFuncSetAttribute(qkv_proj, cudaFuncAttributeMaxDynamicSharedMemorySize, PJ_SMEM);
    cudaFuncSetAttribute(out_proj, cudaFuncAttributeMaxDynamicSharedMemorySize, PJ_SMEM);
    cudaFuncSetAttribute(attn_bf,  cudaFuncAttributeMaxDynamicSharedMemorySize, AT_SMEM);

    dim3 gx(N4/1024, 3);
    xsplit3<<<gx, 256>>>(xq, xk, xv, xh, xm);

    dim3 tg(16,16,4), tb(32,8);
    wtrans4<<<tg,tb>>>(w_q, w_k, w_v, w_out, wh, wm);

    dim3 gq(4, 64, 3);
    qkv_proj<<<gq,256,PJ_SMEM>>>(xh, xm, wh, wm, qh, qm, kh, km, vf);

    dim3 gv(32, 2, 64);
    vtrans<<<gv,tb>>>(vf, vth, vtm);

    dim3 ga(8, HH, MBN);
    attn_bf<<<ga,256,AT_SMEM>>>(qh, qm, kh, km, vth, vtm,
                                tq, tk, kw1, kb1, kw2, kb2, cth, ctm);

    dim3 go(4, 64);
    out_proj<<<go,256,PJ_SMEM>>>(cth, ctm, wh+3*(size_t)DD*DD, wm+3*(size_t)DD*DD,
                                 b_out, out);
}

// round 10
// speedup vs baseline: 1.1074x; 1.1074x over previous
#include <cuda_runtime.h>
#include <cuda_bf16.h>
#include <cstdint>
#include <math.h>

typedef __nv_bfloat16 bf16;

#define MBN   8
#define NQL   1024
#define NKVL  1024
#define HH    8
#define SCALE 0.125f
#define DD    512
#define N4    (MBN*NQL*DD)

__device__ bf16  g_xh[3][N4], g_xm[3][N4];
__device__ bf16  g_wh[4][DD*DD], g_wm[4][DD*DD];
__device__ bf16  g_qh[N4], g_qm[N4], g_kh[N4], g_km[N4];
__device__ float g_vf[N4];
__device__ bf16  g_vth[N4], g_vtm[N4];
__device__ bf16  g_cth[N4], g_ctm[N4];

// ---------------- helpers ----------------
__device__ __forceinline__ uint32_t smem_u32(const void* p){
    uint32_t a;
    asm("{ .reg .u64 t; cvta.to.shared.u64 t, %1; cvt.u32.u64 %0, t; }":"=r"(a):"l"(p));
    return a;
}
__device__ __forceinline__ void cp16(uint32_t s, const void* g){
    asm volatile("cp.async.cg.shared.global [%0], [%1], 16;"::"r"(s),"l"(g));
}
#define CP_COMMIT() asm volatile("cp.async.commit_group;":::"memory")

__device__ __forceinline__ void mma16816(float* c, const uint32_t* a,
                                         uint32_t b0, uint32_t b1){
    asm volatile(
      "mma.sync.aligned.m16n8k16.row.col.f32.bf16.bf16.f32 "
      "{%0,%1,%2,%3}, {%4,%5,%6,%7}, {%8,%9}, {%0,%1,%2,%3};"
      : "+f"(c[0]), "+f"(c[1]), "+f"(c[2]), "+f"(c[3])
      : "r"(a[0]), "r"(a[1]), "r"(a[2]), "r"(a[3]), "r"(b0), "r"(b1));
}
__device__ __forceinline__ void ldm4(uint32_t& r0, uint32_t& r1,
                                     uint32_t& r2, uint32_t& r3, uint32_t a){
    asm volatile("ldmatrix.sync.aligned.m8n8.x4.shared.b16 {%0,%1,%2,%3}, [%4];"
      : "=r"(r0),"=r"(r1),"=r"(r2),"=r"(r3) : "r"(a));
}
__device__ __forceinline__ void psplit2(float a, float b, uint32_t& h, uint32_t& m){
    bf16 ha = __float2bfloat16_rn(a), hb = __float2bfloat16_rn(b);
    bf16 ma = __float2bfloat16_rn(a - __bfloat162float(ha));
    bf16 mb = __float2bfloat16_rn(b - __bfloat162float(hb));
    __nv_bfloat162 H = __halves2bfloat162(ha, hb), M = __halves2bfloat162(ma, mb);
    h = *(uint32_t*)&H; m = *(uint32_t*)&M;
}

// ---------------- input split (3 inputs, one launch) ----------------
__global__ void xsplit3(const float* __restrict__ x0, const float* __restrict__ x1,
                        const float* __restrict__ x2,
                        bf16* __restrict__ xh, bf16* __restrict__ xm){
    int z = blockIdx.y;
    const float* x = (z == 0) ? x0 : (z == 1) ? x1 : x2;
    size_t base = (size_t)z * N4;
    int i = (blockIdx.x*256 + threadIdx.x)*4;
    float4 v = *(const float4*)(x + i);
    uint32_t h0,m0,h1,m1;
    psplit2(v.x,v.y,h0,m0); psplit2(v.z,v.w,h1,m1);
    *(uint32_t*)(xh+base+i) = h0; *(uint32_t*)(xh+base+i+2) = h1;
    *(uint32_t*)(xm+base+i) = m0; *(uint32_t*)(xm+base+i+2) = m1;
}

// ---------------- W[k][n] -> split Wt[n][k] (4 weights, one launch) --------
__global__ void wtrans4(const float* __restrict__ W0, const float* __restrict__ W1,
                        const float* __restrict__ W2, const float* __restrict__ W3,
                        bf16* __restrict__ Wh, bf16* __restrict__ Wm){
    int z = blockIdx.z;
    const float* W = (z==0)?W0:(z==1)?W1:(z==2)?W2:W3;
    bf16* wh = Wh + (size_t)z*DD*DD;
    bf16* wm = Wm + (size_t)z*DD*DD;
    __shared__ float t[32][33];
    int n0 = blockIdx.x*32, k0 = blockIdx.y*32;
    int tx = threadIdx.x, ty = threadIdx.y;
#pragma unroll
    for (int i=0;i<32;i+=8) t[ty+i][tx] = W[(size_t)(k0+ty+i)*DD + n0+tx];
    __syncthreads();
#pragma unroll
    for (int i=0;i<32;i+=8){
        float v = t[tx][ty+i];
        bf16 hh = __float2bfloat16_rn(v);
        size_t idx = (size_t)(n0+ty+i)*DD + k0+tx;
        wh[idx] = hh;
        wm[idx] = __float2bfloat16_rn(v - __bfloat162float(hh));
    }
}

// ---------------- V f32 -> split transposed ----------------
__global__ void vtrans(const float* __restrict__ V, bf16* __restrict__ Vh,
                       bf16* __restrict__ Vm){
    __shared__ float t[32][33];
    int z = blockIdx.z, m = z>>3, h = z&7;
    int kk0 = blockIdx.x*32, d0 = blockIdx.y*32;
    int tx = threadIdx.x, ty = threadIdx.y;
#pragma unroll
    for (int i=0;i<32;i+=8)
        t[ty+i][tx] = V[(size_t)(m*NKVL + kk0+ty+i)*DD + h*64 + d0+tx];
    __syncthreads();
#pragma unroll
    for (int i=0;i<32;i+=8){
        float v = t[tx][ty+i];
        bf16 hh = __float2bfloat16_rn(v);
        size_t idx = (size_t)(z*64 + d0+ty+i)*NKVL + kk0 + tx;
        Vh[idx] = hh;
        Vm[idx] = __float2bfloat16_rn(v - __bfloat162float(hh));
    }
}

// ---------------- GEMM core macro ----------------
#define PSTG 40960
#define PJ_SMEM (2*PSTG)

#define PJ_ISSUE(kt, s) do{ \
    uint32_t st = sb + (s)*PSTG; int k0 = (kt)*32; \
    for (int i = tid; i < 512; i += 256){ \
        int r = i>>2; uint32_t ro = r*80 + (i&3)*16; int c8 = (i&3)*8; \
        size_t ga = (size_t)(bm+r)*DD + k0 + c8; \
        cp16(st + ro,         Ah + ga); \
        cp16(st + 10240 + ro, Am + ga); \
        size_t gb = (size_t)(bn+r)*DD + k0 + c8; \
        cp16(st + 20480 + ro, Bh + gb); \
        cp16(st + 30720 + ro, Bm + gb); \
    } CP_COMMIT(); }while(0)

#define PJ_MAINLOOP() \
    PJ_ISSUE(0, 0); \
    _Pragma("unroll 1") \
    for (int kt = 0; kt < 16; kt++){ \
        if (kt < 15){ \
            PJ_ISSUE(kt+1, (kt+1)&1); \
            asm volatile("cp.async.wait_group 1;":::"memory"); \
        } else { \
            asm volatile("cp.async.wait_group 0;":::"memory"); \
        } \
        __syncthreads(); \
        const bf16* sAh = (const bf16*)(sp + (kt&1)*PSTG); \
        const bf16* sAm = sAh + 5120; \
        const bf16* sBh = sAm + 5120; \
        const bf16* sBm = sBh + 5120; \
        _Pragma("unroll") \
        for (int ks = 0; ks < 2; ks++){ \
            int kb = ks*16 + q2; \
            uint32_t ah[4][4], am[4][4]; \
            _Pragma("unroll") \
            for (int mi = 0; mi < 4; mi++){ \
                const bf16* p = sAh + (wm + mi*16 + ln4)*40 + kb; \
                ah[mi][0]=*(const uint32_t*)p;     ah[mi][1]=*(const uint32_t*)(p+8*40); \
                ah[mi][2]=*(const uint32_t*)(p+8); ah[mi][3]=*(const uint32_t*)(p+8*40+8); \
                const bf16* pm = sAm + (wm + mi*16 + ln4)*40 + kb; \
                am[mi][0]=*(const uint32_t*)pm;     am[mi][1]=*(const uint32_t*)(pm+8*40); \
                am[mi][2]=*(const uint32_t*)(pm+8); am[mi][3]=*(const uint32_t*)(pm+8*40+8); \
            } \
            _Pragma("unroll") \
            for (int nj = 0; nj < 4; nj++){ \
                const bf16* p = sBh + (wn + nj*8 + ln4)*40 + kb; \
                uint32_t bh0 = *(const uint32_t*)p, bh1 = *(const uint32_t*)(p+8); \
                const bf16* pm = sBm + (wn + nj*8 + ln4)*40 + kb; \
                uint32_t bm0 = *(const uint32_t*)pm, bm1 = *(const uint32_t*)(pm+8); \
                _Pragma("unroll") \
                for (int mi = 0; mi < 4; mi++){ \
                    mma16816(acc[mi][nj], ah[mi], bh0, bh1); \
                    mma16816(acc[mi][nj], ah[mi], bm0, bm1); \
                    mma16816(acc[mi][nj], am[mi], bh0, bh1); \
                } \
            } \
        } \
        __syncthreads(); \
    }

// ---------------- merged QKV projection (z = 0:Q 1:K 2:V) ----------------
__global__ void __launch_bounds__(256) qkv_proj(
    const bf16* __restrict__ Xh, const bf16* __restrict__ Xm,
    const bf16* __restrict__ Wh, const bf16* __restrict__ Wm,
    bf16* __restrict__ Qh, bf16* __restrict__ Qm,
    bf16* __restrict__ Kh, bf16* __restrict__ Km,
    float* __restrict__ Vf)
{
    extern __shared__ char sp[];
    uint32_t sb = smem_u32(sp);
    const int tid = threadIdx.x, lane = tid & 31, wid = tid >> 5;
    const int ln4 = lane >> 2, q2 = (lane & 3)*2;
    const int wm = (wid & 1)*64, wn = (wid >> 1)*32;
    const int bm = blockIdx.y*128, bn = blockIdx.x*128;
    const int z = blockIdx.z;
    const bf16* Ah = Xh + (size_t)z*N4;
    const bf16* Am = Xm + (size_t)z*N4;
    const bf16* Bh = Wh + (size_t)z*DD*DD;
    const bf16* Bm = Wm + (size_t)z*DD*DD;
    float acc[4][4][4];
#pragma unroll
    for (int a=0;a<4;a++)
#pragma unroll
      for (int b=0;b<4;b++)
#pragma unroll
        for (int c=0;c<4;c++) acc[a][b][c]=0.f;

    PJ_MAINLOOP();

    const float scale = (z == 0) ? SCALE : 1.0f;
#pragma unroll
    for (int mi = 0; mi < 4; mi++){
        int r0 = bm + wm + mi*16 + ln4;
#pragma unroll
        for (int nj = 0; nj < 4; nj++){
            int c = bn + wn + nj*8 + q2;
            float v0 = acc[mi][nj][0]*scale, v1 = acc[mi][nj][1]*scale;
            float v2 = acc[mi][nj][2]*scale, v3 = acc[mi][nj][3]*scale;
            if (z == 2){
                *(float2*)(Vf + (size_t)r0*DD + c)     = make_float2(v0, v1);
                *(float2*)(Vf + (size_t)(r0+8)*DD + c) = make_float2(v2, v3);
            } else {
                bf16* Ch = (z == 0) ? Qh : Kh;
                bf16* Cm = (z == 0) ? Qm : Km;
                uint32_t h, m;
                psplit2(v0, v1, h, m);
                *(uint32_t*)(Ch + (size_t)r0*DD + c) = h;
                *(uint32_t*)(Cm + (size_t)r0*DD + c) = m;
                psplit2(v2, v3, h, m);
                *(uint32_t*)(Ch + (size_t)(r0+8)*DD + c) = h;
                *(uint32_t*)(Cm + (size_t)(r0+8)*DD + c) = m;
            }
        }
    }
}

// ---------------- output projection ----------------
__global__ void __launch_bounds__(256) out_proj(
    const bf16* __restrict__ Ah, const bf16* __restrict__ Am,
    const bf16* __restrict__ Bh, const bf16* __restrict__ Bm,
    const float* __restrict__ bias, float* __restrict__ Cf)
{
    extern __shared__ char sp[];
    uint32_t sb = smem_u32(sp);
    const int tid = threadIdx.x, lane = tid & 31, wid = tid >> 5;
    const int ln4 = lane >> 2, q2 = (lane & 3)*2;
    const int wm = (wid & 1)*64, wn = (wid >> 1)*32;
    const int bm = blockIdx.y*128, bn = blockIdx.x*128;
    float acc[4][4][4];
#pragma unroll
    for (int a=0;a<4;a++)
#pragma unroll
      for (int b=0;b<4;b++)
#pragma unroll
        for (int c=0;c<4;c++) acc[a][b][c]=0.f;

    PJ_MAINLOOP();

#pragma unroll
    for (int mi = 0; mi < 4; mi++){
        int r0 = bm + wm + mi*16 + ln4;
#pragma unroll
        for (int nj = 0; nj < 4; nj++){
            int c = bn + wn + nj*8 + q2;
            float b0 = bias[c], b1 = bias[c+1];
            *(float2*)(Cf + (size_t)r0*DD + c) =
                make_float2(acc[mi][nj][0] + b0, acc[mi][nj][1] + b1);
            *(float2*)(Cf + (size_t)(r0+8)*DD + c) =
                make_float2(acc[mi][nj][2] + b0, acc[mi][nj][3] + b1);
        }
    }
}

// ---------------- fused attention: 3-stage pipeline + ldmatrix ----------------
#define O_QH 0
#define O_QM 18432
#define O_KV 36864
#define KVSTG 36864
#define S_KH 0
#define S_KM 9216
#define S_VH 18432
#define S_VM 27648
#define O_HK (O_KV + 3*KVSTG)
#define HKSTG 5120
#define O_V1 (O_HK + 3*HKSTG)
#define AT_SMEM (O_V1 + 3*256)

__global__ void __launch_bounds__(256) attn_bf(
    const bf16* __restrict__ Qh_g, const bf16* __restrict__ Qm_g,
    const bf16* __restrict__ Kh_g, const bf16* __restrict__ Km_g,
    const bf16* __restrict__ Vh_g, const bf16* __restrict__ Vm_g,
    const float* __restrict__ Tq, const float* __restrict__ Tk,
    const float* __restrict__ kw1, const float* __restrict__ kb1,
    const float* __restrict__ kw2, const float* __restrict__ kb2,
    bf16* __restrict__ Cth, bf16* __restrict__ Ctm)
{
    extern __shared__ char sp[];
    uint32_t sb = smem_u32(sp);

    const int tid = threadIdx.x, lane = tid & 31, wid = tid >> 5;
    const int ln4 = lane >> 2, q2 = (lane & 3)*2;
    const int m = blockIdx.z, h = blockIdx.y, q0 = blockIdx.x*128;
    const int rl0 = wid*16 + ln4;
    // ldmatrix lane offset (bytes): row = lane&7 (stride 144B),
    // matrix = lane>>3: (mat>>1) selects ks in pair (+32B), (mat&1) col-block (+16B)
    const uint32_t lmo = (uint32_t)((lane & 7)*144 + ((lane >> 3) >> 1)*32
                                    + ((lane >> 3) & 1)*16);

    for (int i = tid; i < 1024; i += 256){
        int r = i>>3; uint32_t ro = r*144 + (i&7)*16;
        size_t g = (size_t)(m*NQL+q0+r)*DD + h*64 + (i&7)*8;
        cp16(sb + O_QH + ro, Qh_g + g);
        cp16(sb + O_QM + ro, Qm_g + g);
    }
#define KV_ISSUE(kk0, s) do{ \
    uint32_t st = sb + O_KV + (s)*KVSTG; \
    for (int i = tid; i < 512; i += 256){ \
        int r = i>>3; uint32_t ro = r*144 + (i&7)*16; int c8 = (i&7)*8; \
        size_t gk = (size_t)(m*NKVL + (kk0) + r)*DD + h*64 + c8; \
        cp16(st + S_KH + ro, Kh_g + gk); \
        cp16(st + S_KM + ro, Km_g + gk); \
        size_t gv = (size_t)((m*HH+h)*64 + r)*NKVL + (kk0) + c8; \
        cp16(st + S_VH + ro, Vh_g + gv); \
        cp16(st + S_VM + ro, Vm_g + gv); \
    } CP_COMMIT(); }while(0)

#define HK_GEN(tile, s) do{ \
    if (tid < 64){ \
        float2 tk2 = *(const float2*)(Tk + (size_t)(m*NKVL + (tile)*64 + tid)*2); \
        float v1 = 0.f; \
        float* Hb = (float*)(sp + O_HK + (s)*HKSTG); \
        _Pragma("unroll") \
        for (int j = 0; j < 16; j++){ \
            float hk = tk2.x*kw1[j] + tk2.y*kw1[16+j]; \
            Hb[tid*20 + j] = hk; \
            v1 = fmaf(ws[j], hk, v1); \
        } \
        ((float*)(sp + O_V1))[(s)*64 + tid] = v1; \
    } }while(0)

    KV_ISSUE(0, 0);
    KV_ISSUE(64, 1);

    float ws[16], uq0[16], uq1[16];
    float2 ta = *(const float2*)(Tq + (size_t)(m*NQL + q0 + rl0)*2);
    float2 tb = *(const float2*)(Tq + (size_t)(m*NQL + q0 + rl0 + 8)*2);
    float U1r0 = kb2[h] - 10.f, U1r1 = U1r0;
#pragma unroll
    for (int j = 0; j < 16; j++){
        ws[j] = 0.5f*kw2[j*HH + h];
        float w0 = kw1[j], w1 = kw1[16+j], b = kb1[j];
        uq0[j] = ta.x*w0 + ta.y*w1 + b;
        uq1[j] = tb.x*w0 + tb.y*w1 + b;
        U1r0 = fmaf(ws[j], uq0[j], U1r0);
        U1r1 = fmaf(ws[j], uq1[j], U1r1);
    }
    HK_GEN(0, 0);
    HK_GEN(1, 1);

    // wait for Q + KV0, hoist Q fragments into registers
    asm volatile("cp.async.wait_group 1;":::"memory");
    __syncthreads();
    uint32_t qa[4][4], qb[4][4];
    {
        const bf16* Qh = (const bf16*)(sp + O_QH);
        const bf16* Qm = (const bf16*)(sp + O_QM);
#pragma unroll
        for (int ks = 0; ks < 4; ks++){
            int kb = ks*16 + q2;
            const bf16* p = Qh + rl0*72 + kb;
            qa[ks][0]=*(const uint32_t*)p;     qa[ks][1]=*(const uint32_t*)(p+8*72);
            qa[ks][2]=*(const uint32_t*)(p+8); qa[ks][3]=*(const uint32_t*)(p+8*72+8);
            const bf16* pm = Qm + rl0*72 + kb;
            qb[ks][0]=*(const uint32_t*)pm;     qb[ks][1]=*(const uint32_t*)(pm+8*72);
            qb[ks][2]=*(const uint32_t*)(pm+8); qb[ks][3]=*(const uint32_t*)(pm+8*72+8);
        }
    }

    float oacc[8][4];
#pragma unroll
    for (int j=0;j<8;j++)
#pragma unroll
        for (int c=0;c<4;c++) oacc[j][c]=0.f;
    float l0 = 0.f, l1 = 0.f;

#pragma unroll 1
    for (int t = 0; t < 16; t++){
        if (t > 0){
            if (t < 15){
                asm volatile("cp.async.wait_group 1;":::"memory");
            } else {
                asm volatile("cp.async.wait_group 0;":::"memory");
            }
            __syncthreads();
        }
        if (t <= 13){
            int s2 = (t+2) % 3;
            KV_ISSUE((t+2)*64, s2);
            HK_GEN(t+2, s2);
        }
        const int scur = t % 3;
        const uint32_t stb = sb + O_KV + scur*KVSTG;
        const uint32_t kh_a = stb + S_KH + lmo;
        const uint32_t km_a = stb + S_KM + lmo;
        const uint32_t vh_a = stb + S_VH + lmo;
        const uint32_t vm_a = stb + S_VM + lmo;
        const float* Hc = (const float*)(sp + O_HK + scur*HKSTG);
        const float* Vc = (const float*)(sp + O_V1) + scur*64;

        // ---- S = Q @ K^T (ldmatrix fragment loads) ----
        float sacc[8][4];
#pragma unroll
        for (int j = 0; j < 8; j++){
#pragma unroll
            for (int c = 0; c < 4; c++) sacc[j][c] = 0.f;
#pragma unroll
            for (int p = 0; p < 2; p++){
                uint32_t kh0,kh1,kh2,kh3, km0,km1,km2,km3;
                ldm4(kh0,kh1,kh2,kh3, kh_a + j*1152 + p*64);
                ldm4(km0,km1,km2,km3, km_a + j*1152 + p*64);
                mma16816(sacc[j], qa[2*p],   kh0, kh1);
                mma16816(sacc[j], qa[2*p],   km0, km1);
                mma16816(sacc[j], qb[2*p],   kh0, kh1);
                mma16816(sacc[j], qa[2*p+1], kh2, kh3);
                mma16816(sacc[j], qa[2*p+1], km2, km3);
                mma16816(sacc[j], qb[2*p+1], kh2, kh3);
            }
        }

        // ---- bias + exp + split ----
        uint32_t pah[4][4], pam[4][4];
#pragma unroll
        for (int j = 0; j < 8; j++){
            float pe[4];
#pragma unroll
            for (int e = 0; e < 2; e++){
                int c = j*8 + q2 + e;
                const float4* hp = (const float4*)(Hc + c*20);
                float4 f0 = hp[0], f1 = hp[1], f2 = hp[2], f3 = hp[3];
                float hv[16] = {f0.x,f0.y,f0.z,f0.w, f1.x,f1.y,f1.z,f1.w,
                                f2.x,f2.y,f2.z,f2.w, f3.x,f3.y,f3.z,f3.w};
                float v1c = Vc[c];
                float s0 = sacc[j][e]   + U1r0 - v1c;
                float s1 = sacc[j][2+e] + U1r1 - v1c;
#pragma unroll
                for (int jj = 0; jj < 16; jj++){
                    s0 = fmaf(ws[jj], fabsf(uq0[jj] - hv[jj]), s0);
                    s1 = fmaf(ws[jj], fabsf(uq1[jj] - hv[jj]), s1);
                }
                float e0 = __expf(s0), e1 = __expf(s1);
                l0 += e0; l1 += e1;
                pe[e] = e0; pe[2+e] = e1;
            }
            int tt2 = j >> 1, base = (j & 1)*2;
            psplit2(pe[0], pe[1], pah[tt2][base],   pam[tt2][base]);
            psplit2(pe[2], pe[3], pah[tt2][base+1], pam[tt2][base+1]);
        }

        // ---- O += P @ V^T (ldmatrix fragment loads) ----
#pragma unroll
        for (int j2 = 0; j2 < 8; j2++){
#pragma unroll
            for (int p = 0; p < 2; p++){
                uint32_t vh0,vh1,vh2,vh3, vm0,vm1,vm2,vm3;
                ldm4(vh0,vh1,vh2,vh3, vh_a + j2*1152 + p*64);
                ldm4(vm0,vm1,vm2,vm3, vm_a + j2*1152 + p*64);
                mma16816(oacc[j2], pah[2*p],   vh0, vh1);
                mma16816(oacc[j2], pah[2*p],   vm0, vm1);
                mma16816(oacc[j2], pam[2*p],   vh0, vh1);
                mma16816(oacc[j2], pah[2*p+1], vh2, vh3);
                mma16816(oacc[j2], pah[2*p+1], vm2, vm3);
                mma16816(oacc[j2], pam[2*p+1], vh2, vh3);
            }
        }
    }

    l0 += __shfl_xor_sync(0xffffffffu, l0, 1);
    l0 += __shfl_xor_sync(0xffffffffu, l0, 2);
    l1 += __shfl_xor_sync(0xffffffffu, l1, 1);
    l1 += __shfl_xor_sync(0xffffffffu, l1, 2);
    float inv0 = 1.f/l0, inv1 = 1.f/l1;
    size_t o0 = (size_t)(m*NQL + q0 + rl0)*DD + h*64;
    size_t o1 = o0 + 8*DD;
#pragma unroll
    for (int j2 = 0; j2 < 8; j2++){
        int c = j2*8 + q2;
        uint32_t hh, mm;
        psplit2(oacc[j2][0]*inv0, oacc[j2][1]*inv0, hh, mm);
        *(uint32_t*)(Cth + o0 + c) = hh; *(uint32_t*)(Ctm + o0 + c) = mm;
        psplit2(oacc[j2][2]*inv1, oacc[j2][3]*inv1, hh, mm);
        *(uint32_t*)(Cth + o1 + c) = hh; *(uint32_t*)(Ctm + o1 + c) = mm;
    }
}

// ---------------- host launcher ----------------
extern "C" void kernel_launch(void* const* d_in, const int* in_sizes, int n_in,
                              void* d_out, int out_size)
{
    const float* xq    = (const float*)d_in[0];
    const float* xk    = (const float*)d_in[1];
    const float* xv    = (const float*)d_in[2];
    const float* tq    = (const float*)d_in[3];
    const float* tk    = (const float*)d_in[4];
    const float* w_q   = (const float*)d_in[5];
    const float* w_k   = (const float*)d_in[6];
    const float* w_v   = (const float*)d_in[7];
    const float* w_out = (const float*)d_in[8];
    const float* b_out = (const float*)d_in[9];
    const float* kw1   = (const float*)d_in[10];
    const float* kb1   = (const float*)d_in[11];
    const float* kw2   = (const float*)d_in[12];
    const float* kb2   = (const float*)d_in[13];
    float* out = (float*)d_out;

    bf16 *xh,*xm,*wh,*wm,*qh,*qm,*kh,*km,*vth,*vtm,*cth,*ctm;
    float *vf;
    cudaGetSymbolAddress((void**)&xh,  g_xh);
    cudaGetSymbolAddress((void**)&xm,  g_xm);
    cudaGetSymbolAddress((void**)&wh,  g_wh);
    cudaGetSymbolAddress((void**)&wm,  g_wm);
    cudaGetSymbolAddress((void**)&qh,  g_qh);
    cudaGetSymbolAddress((void**)&qm,  g_qm);
    cudaGetSymbolAddress((void**)&kh,  g_kh);
    cudaGetSymbolAddress((void**)&km,  g_km);
    cudaGetSymbolAddress((void**)&vf,  g_vf);
    cudaGetSymbolAddress((void**)&vth, g_vth);
    cudaGetSymbolAddress((void**)&vtm, g_vtm);
    cudaGetSymbolAddress((void**)&cth, g_cth);
    cudaGetSymbolAddress((void**)&ctm, g_ctm);

    cudaFuncSetAttribute(qkv_proj, cudaFuncAttributeMaxDynamicSharedMemorySize, PJ_SMEM);
    cudaFuncSetAttribute(out_proj, cudaFuncAttributeMaxDynamicSharedMemorySize, PJ_SMEM);
    cudaFuncSetAttribute(attn_bf,  cudaFuncAttributeMaxDynamicSharedMemorySize, AT_SMEM);

    dim3 gx(N4/1024, 3);
    xsplit3<<<gx, 256>>>(xq, xk, xv, xh, xm);

    dim3 tg(16,16,4), tb(32,8);
    wtrans4<<<tg,tb>>>(w_q, w_k, w_v, w_out, wh, wm);

    dim3 gq(4, 64, 3);
    qkv_proj<<<gq,256,PJ_SMEM>>>(xh, xm, wh, wm, qh, qm, kh, km, vf);

    dim3 gv(32, 2, 64);
    vtrans<<<gv,tb>>>(vf, vth, vtm);

    dim3 ga(8, HH, MBN);
    attn_bf<<<ga,256,AT_SMEM>>>(qh, qm, kh, km, vth, vtm,
                                tq, tk, kw1, kb1, kw2, kb2, cth, ctm);

    dim3 go(4, 64);
    out_proj<<<go,256,PJ_SMEM>>>(cth, ctm, wh+3*(size_t)DD*DD, wm+3*(size_t)DD*DD,
                                 b_out, out);
}

// round 11
// speedup vs baseline: 1.1148x; 1.0067x over previous
#include <cuda_runtime.h>
#include <cuda_bf16.h>
#include <cstdint>
#include <math.h>

typedef __nv_bfloat16 bf16;

#define MBN   8
#define NQL   1024
#define NKVL  1024
#define HH    8
#define SCALE 0.125f
#define DD    512
#define N4    (MBN*NQL*DD)

__device__ bf16  g_xh[3][N4], g_xm[3][N4];
__device__ bf16  g_wh[4][DD*DD], g_wm[4][DD*DD];
__device__ bf16  g_qh[N4], g_qm[N4], g_kh[N4], g_km[N4];
__device__ float g_vf[N4];
__device__ bf16  g_vth[N4], g_vtm[N4];
__device__ bf16  g_cth[N4], g_ctm[N4];

// ---------------- helpers ----------------
__device__ __forceinline__ uint32_t smem_u32(const void* p){
    uint32_t a;
    asm("{ .reg .u64 t; cvta.to.shared.u64 t, %1; cvt.u32.u64 %0, t; }":"=r"(a):"l"(p));
    return a;
}
__device__ __forceinline__ void cp16(uint32_t s, const void* g){
    asm volatile("cp.async.cg.shared.global [%0], [%1], 16;"::"r"(s),"l"(g));
}
#define CP_COMMIT() asm volatile("cp.async.commit_group;":::"memory")

__device__ __forceinline__ void mma16816(float* c, const uint32_t* a,
                                         uint32_t b0, uint32_t b1){
    asm volatile(
      "mma.sync.aligned.m16n8k16.row.col.f32.bf16.bf16.f32 "
      "{%0,%1,%2,%3}, {%4,%5,%6,%7}, {%8,%9}, {%0,%1,%2,%3};"
      : "+f"(c[0]), "+f"(c[1]), "+f"(c[2]), "+f"(c[3])
      : "r"(a[0]), "r"(a[1]), "r"(a[2]), "r"(a[3]), "r"(b0), "r"(b1));
}
__device__ __forceinline__ void ldm4(uint32_t& r0, uint32_t& r1,
                                     uint32_t& r2, uint32_t& r3, uint32_t a){
    asm volatile("ldmatrix.sync.aligned.m8n8.x4.shared.b16 {%0,%1,%2,%3}, [%4];"
      : "=r"(r0),"=r"(r1),"=r"(r2),"=r"(r3) : "r"(a));
}
__device__ __forceinline__ void psplit2(float a, float b, uint32_t& h, uint32_t& m){
    bf16 ha = __float2bfloat16_rn(a), hb = __float2bfloat16_rn(b);
    bf16 ma = __float2bfloat16_rn(a - __bfloat162float(ha));
    bf16 mb = __float2bfloat16_rn(b - __bfloat162float(hb));
    __nv_bfloat162 H = __halves2bfloat162(ha, hb), M = __halves2bfloat162(ma, mb);
    h = *(uint32_t*)&H; m = *(uint32_t*)&M;
}

// ---------------- input split (3 inputs, one launch) ----------------
__global__ void xsplit3(const float* __restrict__ x0, const float* __restrict__ x1,
                        const float* __restrict__ x2,
                        bf16* __restrict__ xh, bf16* __restrict__ xm){
    int z = blockIdx.y;
    const float* x = (z == 0) ? x0 : (z == 1) ? x1 : x2;
    size_t base = (size_t)z * N4;
    int i = (blockIdx.x*256 + threadIdx.x)*4;
    float4 v = *(const float4*)(x + i);
    uint32_t h0,m0,h1,m1;
    psplit2(v.x,v.y,h0,m0); psplit2(v.z,v.w,h1,m1);
    *(uint32_t*)(xh+base+i) = h0; *(uint32_t*)(xh+base+i+2) = h1;
    *(uint32_t*)(xm+base+i) = m0; *(uint32_t*)(xm+base+i+2) = m1;
}

// ---------------- W[k][n] -> split Wt[n][k] (4 weights, one launch) --------
__global__ void wtrans4(const float* __restrict__ W0, const float* __restrict__ W1,
                        const float* __restrict__ W2, const float* __restrict__ W3,
                        bf16* __restrict__ Wh, bf16* __restrict__ Wm){
    int z = blockIdx.z;
    const float* W = (z==0)?W0:(z==1)?W1:(z==2)?W2:W3;
    bf16* wh = Wh + (size_t)z*DD*DD;
    bf16* wm = Wm + (size_t)z*DD*DD;
    __shared__ float t[32][33];
    int n0 = blockIdx.x*32, k0 = blockIdx.y*32;
    int tx = threadIdx.x, ty = threadIdx.y;
#pragma unroll
    for (int i=0;i<32;i+=8) t[ty+i][tx] = W[(size_t)(k0+ty+i)*DD + n0+tx];
    __syncthreads();
#pragma unroll
    for (int i=0;i<32;i+=8){
        float v = t[tx][ty+i];
        bf16 hh = __float2bfloat16_rn(v);
        size_t idx = (size_t)(n0+ty+i)*DD + k0+tx;
        wh[idx] = hh;
        wm[idx] = __float2bfloat16_rn(v - __bfloat162float(hh));
    }
}

// ---------------- V f32 -> split transposed ----------------
__global__ void vtrans(const float* __restrict__ V, bf16* __restrict__ Vh,
                       bf16* __restrict__ Vm){
    __shared__ float t[32][33];
    int z = blockIdx.z, m = z>>3, h = z&7;
    int kk0 = blockIdx.x*32, d0 = blockIdx.y*32;
    int tx = threadIdx.x, ty = threadIdx.y;
#pragma unroll
    for (int i=0;i<32;i+=8)
        t[ty+i][tx] = V[(size_t)(m*NKVL + kk0+ty+i)*DD + h*64 + d0+tx];
    __syncthreads();
#pragma unroll
    for (int i=0;i<32;i+=8){
        float v = t[tx][ty+i];
        bf16 hh = __float2bfloat16_rn(v);
        size_t idx = (size_t)(z*64 + d0+ty+i)*NKVL + kk0 + tx;
        Vh[idx] = hh;
        Vm[idx] = __float2bfloat16_rn(v - __bfloat162float(hh));
    }
}

// ---------------- GEMM core macro (ldmatrix fragment loads) ----------------
#define PSTG 40960
#define PJ_SMEM (2*PSTG)

#define PJ_ISSUE(kt, s) do{ \
    uint32_t st = sb + (s)*PSTG; int k0 = (kt)*32; \
    for (int i = tid; i < 512; i += 256){ \
        int r = i>>2; uint32_t ro = r*80 + (i&3)*16; int c8 = (i&3)*8; \
        size_t ga = (size_t)(bm+r)*DD + k0 + c8; \
        cp16(st + ro,         Ah + ga); \
        cp16(st + 10240 + ro, Am + ga); \
        size_t gb = (size_t)(bn+r)*DD + k0 + c8; \
        cp16(st + 20480 + ro, Bh + gb); \
        cp16(st + 30720 + ro, Bm + gb); \
    } CP_COMMIT(); }while(0)

// A frag mats: (m+0,k0),(m+8,k0),(m+0,k8),(m+8,k8) -> a0..a3
// B frag mats: (n+0,k0),(n+0,k8),(n+8,k0),(n+8,k8) -> nj0{b0,b1}, nj1{b0,b1}
#define PJ_MAINLOOP() \
    PJ_ISSUE(0, 0); \
    _Pragma("unroll 1") \
    for (int kt = 0; kt < 16; kt++){ \
        if (kt < 15){ \
            PJ_ISSUE(kt+1, (kt+1)&1); \
            asm volatile("cp.async.wait_group 1;":::"memory"); \
        } else { \
            asm volatile("cp.async.wait_group 0;":::"memory"); \
        } \
        __syncthreads(); \
        uint32_t sA  = sb + (kt&1)*PSTG; \
        uint32_t sAm = sA + 10240, sB = sA + 20480, sBm = sA + 30720; \
        _Pragma("unroll") \
        for (int ks = 0; ks < 2; ks++){ \
            uint32_t ah[4][4], am[4][4]; \
            _Pragma("unroll") \
            for (int mi = 0; mi < 4; mi++){ \
                uint32_t abase = (uint32_t)((wm + mi*16)*80 + ks*32) + aoffA; \
                ldm4(ah[mi][0],ah[mi][1],ah[mi][2],ah[mi][3], sA  + abase); \
                ldm4(am[mi][0],am[mi][1],am[mi][2],am[mi][3], sAm + abase); \
            } \
            _Pragma("unroll") \
            for (int njp = 0; njp < 2; njp++){ \
                uint32_t bbase = (uint32_t)((wn + njp*16)*80 + ks*32) + aoffB; \
                uint32_t bh0,bh1,bh2,bh3, bm0,bm1,bm2,bm3; \
                ldm4(bh0,bh1,bh2,bh3, sB  + bbase); \
                ldm4(bm0,bm1,bm2,bm3, sBm + bbase); \
                _Pragma("unroll") \
                for (int mi = 0; mi < 4; mi++){ \
                    mma16816(acc[mi][njp*2],   ah[mi], bh0, bh1); \
                    mma16816(acc[mi][njp*2],   ah[mi], bm0, bm1); \
                    mma16816(acc[mi][njp*2],   am[mi], bh0, bh1); \
                    mma16816(acc[mi][njp*2+1], ah[mi], bh2, bh3); \
                    mma16816(acc[mi][njp*2+1], ah[mi], bm2, bm3); \
                    mma16816(acc[mi][njp*2+1], am[mi], bh2, bh3); \
                } \
            } \
        } \
        __syncthreads(); \
    }

#define PJ_LANEOFF() \
    const uint32_t aoffA = (uint32_t)((lane & 7)*80 + ((lane >> 3) & 1)*640 \
                                      + (lane >> 4)*16); \
    const uint32_t aoffB = (uint32_t)((lane & 7)*80 + ((lane >> 3) & 1)*16 \
                                      + (lane >> 4)*640);

// ---------------- merged QKV projection (z = 0:Q 1:K 2:V) ----------------
__global__ void __launch_bounds__(256) qkv_proj(
    const bf16* __restrict__ Xh, const bf16* __restrict__ Xm,
    const bf16* __restrict__ Wh, const bf16* __restrict__ Wm,
    bf16* __restrict__ Qh, bf16* __restrict__ Qm,
    bf16* __restrict__ Kh, bf16* __restrict__ Km,
    float* __restrict__ Vf)
{
    extern __shared__ char sp[];
    uint32_t sb = smem_u32(sp);
    const int tid = threadIdx.x, lane = tid & 31, wid = tid >> 5;
    const int ln4 = lane >> 2, q2 = (lane & 3)*2;
    const int wm = (wid & 1)*64, wn = (wid >> 1)*32;
    const int bm = blockIdx.y*128, bn = blockIdx.x*128;
    const int z = blockIdx.z;
    PJ_LANEOFF();
    const bf16* Ah = Xh + (size_t)z*N4;
    const bf16* Am = Xm + (size_t)z*N4;
    const bf16* Bh = Wh + (size_t)z*DD*DD;
    const bf16* Bm = Wm + (size_t)z*DD*DD;
    float acc[4][4][4];
#pragma unroll
    for (int a=0;a<4;a++)
#pragma unroll
      for (int b=0;b<4;b++)
#pragma unroll
        for (int c=0;c<4;c++) acc[a][b][c]=0.f;

    PJ_MAINLOOP();

    const float scale = (z == 0) ? SCALE : 1.0f;
#pragma unroll
    for (int mi = 0; mi < 4; mi++){
        int r0 = bm + wm + mi*16 + ln4;
#pragma unroll
        for (int nj = 0; nj < 4; nj++){
            int c = bn + wn + nj*8 + q2;
            float v0 = acc[mi][nj][0]*scale, v1 = acc[mi][nj][1]*scale;
            float v2 = acc[mi][nj][2]*scale, v3 = acc[mi][nj][3]*scale;
            if (z == 2){
                *(float2*)(Vf + (size_t)r0*DD + c)     = make_float2(v0, v1);
                *(float2*)(Vf + (size_t)(r0+8)*DD + c) = make_float2(v2, v3);
            } else {
                bf16* Ch = (z == 0) ? Qh : Kh;
                bf16* Cm = (z == 0) ? Qm : Km;
                uint32_t h, m;
                psplit2(v0, v1, h, m);
                *(uint32_t*)(Ch + (size_t)r0*DD + c) = h;
                *(uint32_t*)(Cm + (size_t)r0*DD + c) = m;
                psplit2(v2, v3, h, m);
                *(uint32_t*)(Ch + (size_t)(r0+8)*DD + c) = h;
                *(uint32_t*)(Cm + (size_t)(r0+8)*DD + c) = m;
            }
        }
    }
}

// ---------------- output projection ----------------
__global__ void __launch_bounds__(256) out_proj(
    const bf16* __restrict__ Ah, const bf16* __restrict__ Am,
    const bf16* __restrict__ Bh, const bf16* __restrict__ Bm,
    const float* __restrict__ bias, float* __restrict__ Cf)
{
    extern __shared__ char sp[];
    uint32_t sb = smem_u32(sp);
    const int tid = threadIdx.x, lane = tid & 31, wid = tid >> 5;
    const int ln4 = lane >> 2, q2 = (lane & 3)*2;
    const int wm = (wid & 1)*64, wn = (wid >> 1)*32;
    const int bm = blockIdx.y*128, bn = blockIdx.x*128;
    PJ_LANEOFF();
    float acc[4][4][4];
#pragma unroll
    for (int a=0;a<4;a++)
#pragma unroll
      for (int b=0;b<4;b++)
#pragma unroll
        for (int c=0;c<4;c++) acc[a][b][c]=0.f;

    PJ_MAINLOOP();

#pragma unroll
    for (int mi = 0; mi < 4; mi++){
        int r0 = bm + wm + mi*16 + ln4;
#pragma unroll
        for (int nj = 0; nj < 4; nj++){
            int c = bn + wn + nj*8 + q2;
            float b0 = bias[c], b1 = bias[c+1];
            *(float2*)(Cf + (size_t)r0*DD + c) =
                make_float2(acc[mi][nj][0] + b0, acc[mi][nj][1] + b1);
            *(float2*)(Cf + (size_t)(r0+8)*DD + c) =
                make_float2(acc[mi][nj][2] + b0, acc[mi][nj][3] + b1);
        }
    }
}

// ---------------- fused attention: 3-stage pipeline + ldmatrix ----------------
#define O_QH 0
#define O_QM 18432
#define O_KV 36864
#define KVSTG 36864
#define S_KH 0
#define S_KM 9216
#define S_VH 18432
#define S_VM 27648
#define O_HK (O_KV + 3*KVSTG)
#define HKSTG 5120
#define O_V1 (O_HK + 3*HKSTG)
#define AT_SMEM (O_V1 + 3*256)

__global__ void __launch_bounds__(256) attn_bf(
    const bf16* __restrict__ Qh_g, const bf16* __restrict__ Qm_g,
    const bf16* __restrict__ Kh_g, const bf16* __restrict__ Km_g,
    const bf16* __restrict__ Vh_g, const bf16* __restrict__ Vm_g,
    const float* __restrict__ Tq, const float* __restrict__ Tk,
    const float* __restrict__ kw1, const float* __restrict__ kb1,
    const float* __restrict__ kw2, const float* __restrict__ kb2,
    bf16* __restrict__ Cth, bf16* __restrict__ Ctm)
{
    extern __shared__ char sp[];
    uint32_t sb = smem_u32(sp);

    const int tid = threadIdx.x, lane = tid & 31, wid = tid >> 5;
    const int ln4 = lane >> 2, q2 = (lane & 3)*2;
    const int m = blockIdx.z, h = blockIdx.y, q0 = blockIdx.x*128;
    const int rl0 = wid*16 + ln4;
    const uint32_t lmo = (uint32_t)((lane & 7)*144 + ((lane >> 3) >> 1)*32
                                    + ((lane >> 3) & 1)*16);

    for (int i = tid; i < 1024; i += 256){
        int r = i>>3; uint32_t ro = r*144 + (i&7)*16;
        size_t g = (size_t)(m*NQL+q0+r)*DD + h*64 + (i&7)*8;
        cp16(sb + O_QH + ro, Qh_g + g);
        cp16(sb + O_QM + ro, Qm_g + g);
    }
#define KV_ISSUE(kk0, s) do{ \
    uint32_t st = sb + O_KV + (s)*KVSTG; \
    for (int i = tid; i < 512; i += 256){ \
        int r = i>>3; uint32_t ro = r*144 + (i&7)*16; int c8 = (i&7)*8; \
        size_t gk = (size_t)(m*NKVL + (kk0) + r)*DD + h*64 + c8; \
        cp16(st + S_KH + ro, Kh_g + gk); \
        cp16(st + S_KM + ro, Km_g + gk); \
        size_t gv = (size_t)((m*HH+h)*64 + r)*NKVL + (kk0) + c8; \
        cp16(st + S_VH + ro, Vh_g + gv); \
        cp16(st + S_VM + ro, Vm_g + gv); \
    } CP_COMMIT(); }while(0)

#define HK_GEN(tile, s) do{ \
    if (tid < 64){ \
        float2 tk2 = *(const float2*)(Tk + (size_t)(m*NKVL + (tile)*64 + tid)*2); \
        float v1 = 0.f; \
        float* Hb = (float*)(sp + O_HK + (s)*HKSTG); \
        _Pragma("unroll") \
        for (int j = 0; j < 16; j++){ \
            float hk = tk2.x*kw1[j] + tk2.y*kw1[16+j]; \
            Hb[tid*20 + j] = hk; \
            v1 = fmaf(ws[j], hk, v1); \
        } \
        ((float*)(sp + O_V1))[(s)*64 + tid] = v1; \
    } }while(0)

    KV_ISSUE(0, 0);
    KV_ISSUE(64, 1);

    float ws[16], uq0[16], uq1[16];
    float2 ta = *(const float2*)(Tq + (size_t)(m*NQL + q0 + rl0)*2);
    float2 tb = *(const float2*)(Tq + (size_t)(m*NQL + q0 + rl0 + 8)*2);
    float U1r0 = kb2[h] - 10.f, U1r1 = U1r0;
#pragma unroll
    for (int j = 0; j < 16; j++){
        ws[j] = 0.5f*kw2[j*HH + h];
        float w0 = kw1[j], w1 = kw1[16+j], b = kb1[j];
        uq0[j] = ta.x*w0 + ta.y*w1 + b;
        uq1[j] = tb.x*w0 + tb.y*w1 + b;
        U1r0 = fmaf(ws[j], uq0[j], U1r0);
        U1r1 = fmaf(ws[j], uq1[j], U1r1);
    }
    HK_GEN(0, 0);
    HK_GEN(1, 1);

    asm volatile("cp.async.wait_group 1;":::"memory");
    __syncthreads();
    uint32_t qa[4][4], qb[4][4];
    {
        const bf16* Qh = (const bf16*)(sp + O_QH);
        const bf16* Qm = (const bf16*)(sp + O_QM);
#pragma unroll
        for (int ks = 0; ks < 4; ks++){
            int kb = ks*16 + q2;
            const bf16* p = Qh + rl0*72 + kb;
            qa[ks][0]=*(const uint32_t*)p;     qa[ks][1]=*(const uint32_t*)(p+8*72);
            qa[ks][2]=*(const uint32_t*)(p+8); qa[ks][3]=*(const uint32_t*)(p+8*72+8);
            const bf16* pm = Qm + rl0*72 + kb;
            qb[ks][0]=*(const uint32_t*)pm;     qb[ks][1]=*(const uint32_t*)(pm+8*72);
            qb[ks][2]=*(const uint32_t*)(pm+8); qb[ks][3]=*(const uint32_t*)(pm+8*72+8);
        }
    }

    float oacc[8][4];
#pragma unroll
    for (int j=0;j<8;j++)
#pragma unroll
        for (int c=0;c<4;c++) oacc[j][c]=0.f;
    float l0 = 0.f, l1 = 0.f;

#pragma unroll 1
    for (int t = 0; t < 16; t++){
        if (t > 0){
            if (t < 15){
                asm volatile("cp.async.wait_group 1;":::"memory");
            } else {
                asm volatile("cp.async.wait_group 0;":::"memory");
            }
            __syncthreads();
        }
        if (t <= 13){
            int s2 = (t+2) % 3;
            KV_ISSUE((t+2)*64, s2);
            HK_GEN(t+2, s2);
        }
        const int scur = t % 3;
        const uint32_t stb = sb + O_KV + scur*KVSTG;
        const uint32_t kh_a = stb + S_KH + lmo;
        const uint32_t km_a = stb + S_KM + lmo;
        const uint32_t vh_a = stb + S_VH + lmo;
        const uint32_t vm_a = stb + S_VM + lmo;
        const float* Hc = (const float*)(sp + O_HK + scur*HKSTG);
        const float* Vc = (const float*)(sp + O_V1) + scur*64;

        float sacc[8][4];
#pragma unroll
        for (int j = 0; j < 8; j++){
#pragma unroll
            for (int c = 0; c < 4; c++) sacc[j][c] = 0.f;
#pragma unroll
            for (int p = 0; p < 2; p++){
                uint32_t kh0,kh1,kh2,kh3, km0,km1,km2,km3;
                ldm4(kh0,kh1,kh2,kh3, kh_a + j*1152 + p*64);
                ldm4(km0,km1,km2,km3, km_a + j*1152 + p*64);
                mma16816(sacc[j], qa[2*p],   kh0, kh1);
                mma16816(sacc[j], qa[2*p],   km0, km1);
                mma16816(sacc[j], qb[2*p],   kh0, kh1);
                mma16816(sacc[j], qa[2*p+1], kh2, kh3);
                mma16816(sacc[j], qa[2*p+1], km2, km3);
                mma16816(sacc[j], qb[2*p+1], kh2, kh3);
            }
        }

        uint32_t pah[4][4], pam[4][4];
#pragma unroll
        for (int j = 0; j < 8; j++){
            float pe[4];
#pragma unroll
            for (int e = 0; e < 2; e++){
                int c = j*8 + q2 + e;
                const float4* hp = (const float4*)(Hc + c*20);
                float4 f0 = hp[0], f1 = hp[1], f2 = hp[2], f3 = hp[3];
                float hv[16] = {f0.x,f0.y,f0.z,f0.w, f1.x,f1.y,f1.z,f1.w,
                                f2.x,f2.y,f2.z,f2.w, f3.x,f3.y,f3.z,f3.w};
                float v1c = Vc[c];
                float s0 = sacc[j][e]   + U1r0 - v1c;
                float s1 = sacc[j][2+e] + U1r1 - v1c;
#pragma unroll
                for (int jj = 0; jj < 16; jj++){
                    s0 = fmaf(ws[jj], fabsf(uq0[jj] - hv[jj]), s0);
                    s1 = fmaf(ws[jj], fabsf(uq1[jj] - hv[jj]), s1);
                }
                float e0 = __expf(s0), e1 = __expf(s1);
                l0 += e0; l1 += e1;
                pe[e] = e0; pe[2+e] = e1;
            }
            int tt2 = j >> 1, base = (j & 1)*2;
            psplit2(pe[0], pe[1], pah[tt2][base],   pam[tt2][base]);
            psplit2(pe[2], pe[3], pah[tt2][base+1], pam[tt2][base+1]);
        }

#pragma unroll
        for (int j2 = 0; j2 < 8; j2++){
#pragma unroll
            for (int p = 0; p < 2; p++){
                uint32_t vh0,vh1,vh2,vh3, vm0,vm1,vm2,vm3;
                ldm4(vh0,vh1,vh2,vh3, vh_a + j2*1152 + p*64);
                ldm4(vm0,vm1,vm2,vm3, vm_a + j2*1152 + p*64);
                mma16816(oacc[j2], pah[2*p],   vh0, vh1);
                mma16816(oacc[j2], pah[2*p],   vm0, vm1);
                mma16816(oacc[j2], pam[2*p],   vh0, vh1);
                mma16816(oacc[j2], pah[2*p+1], vh2, vh3);
                mma16816(oacc[j2], pah[2*p+1], vm2, vm3);
                mma16816(oacc[j2], pam[2*p+1], vh2, vh3);
            }
        }
    }

    l0 += __shfl_xor_sync(0xffffffffu, l0, 1);
    l0 += __shfl_xor_sync(0xffffffffu, l0, 2);
    l1 += __shfl_xor_sync(0xffffffffu, l1, 1);
    l1 += __shfl_xor_sync(0xffffffffu, l1, 2);
    float inv0 = 1.f/l0, inv1 = 1.f/l1;
    size_t o0 = (size_t)(m*NQL + q0 + rl0)*DD + h*64;
    size_t o1 = o0 + 8*DD;
#pragma unroll
    for (int j2 = 0; j2 < 8; j2++){
        int c = j2*8 + q2;
        uint32_t hh, mm;
        psplit2(oacc[j2][0]*inv0, oacc[j2][1]*inv0, hh, mm);
        *(uint32_t*)(Cth + o0 + c) = hh; *(uint32_t*)(Ctm + o0 + c) = mm;
        psplit2(oacc[j2][2]*inv1, oacc[j2][3]*inv1, hh, mm);
        *(uint32_t*)(Cth + o1 + c) = hh; *(uint32_t*)(Ctm + o1 + c) = mm;
    }
}

// ---------------- host launcher ----------------
extern "C" void kernel_launch(void* const* d_in, const int* in_sizes, int n_in,
                              void* d_out, int out_size)
{
    const float* xq    = (const float*)d_in[0];
    const float* xk    = (const float*)d_in[1];
    const float* xv    = (const float*)d_in[2];
    const float* tq    = (const float*)d_in[3];
    const float* tk    = (const float*)d_in[4];
    const float* w_q   = (const float*)d_in[5];
    const float* w_k   = (const float*)d_in[6];
    const float* w_v   = (const float*)d_in[7];
    const float* w_out = (const float*)d_in[8];
    const float* b_out = (const float*)d_in[9];
    const float* kw1   = (const float*)d_in[10];
    const float* kb1   = (const float*)d_in[11];
    const float* kw2   = (const float*)d_in[12];
    const float* kb2   = (const float*)d_in[13];
    float* out = (float*)d_out;

    bf16 *xh,*xm,*wh,*wm,*qh,*qm,*kh,*km,*vth,*vtm,*cth,*ctm;
    float *vf;
    cudaGetSymbolAddress((void**)&xh,  g_xh);
    cudaGetSymbolAddress((void**)&xm,  g_xm);
    cudaGetSymbolAddress((void**)&wh,  g_wh);
    cudaGetSymbolAddress((void**)&wm,  g_wm);
    cudaGetSymbolAddress((void**)&qh,  g_qh);
    cudaGetSymbolAddress((void**)&qm,  g_qm);
    cudaGetSymbolAddress((void**)&kh,  g_kh);
    cudaGetSymbolAddress((void**)&km,  g_km);
    cudaGetSymbolAddress((void**)&vf,  g_vf);
    cudaGetSymbolAddress((void**)&vth, g_vth);
    cudaGetSymbolAddress((void**)&vtm, g_vtm);
    cudaGetSymbolAddress((void**)&cth, g_cth);
    cudaGetSymbolAddress((void**)&ctm, g_ctm);

    cudaFuncSetAttribute(qkv_proj, cudaFuncAttributeMaxDynamicSharedMemorySize, PJ_SMEM);
    cudaFuncSetAttribute(out_proj, cudaFuncAttributeMaxDynamicSharedMemorySize, PJ_SMEM);
    cudaFuncSetAttribute(attn_bf,  cudaFuncAttributeMaxDynamicSharedMemorySize, AT_SMEM);

    dim3 gx(N4/1024, 3);
    xsplit3<<<gx, 256>>>(xq, xk, xv, xh, xm);

    dim3 tg(16,16,4), tb(32,8);
    wtrans4<<<tg,tb>>>(w_q, w_k, w_v, w_out, wh, wm);

    dim3 gq(4, 64, 3);
    qkv_proj<<<gq,256,PJ_SMEM>>>(xh, xm, wh, wm, qh, qm, kh, km, vf);

    dim3 gv(32, 2, 64);
    vtrans<<<gv,tb>>>(vf, vth, vtm);

    dim3 ga(8, HH, MBN);
    attn_bf<<<ga,256,AT_SMEM>>>(qh, qm, kh, km, vth, vtm,
                                tq, tk, kw1, kb1, kw2, kb2, cth, ctm);

    dim3 go(4, 64);
    out_proj<<<go,256,PJ_SMEM>>>(cth, ctm, wh+3*(size_t)DD*DD, wm+3*(size_t)DD*DD,
                                 b_out, out);
}

// round 13
// speedup vs baseline: 1.1363x; 1.0193x over previous
#include <cuda_runtime.h>
#include <cuda_bf16.h>
#include <cstdint>
#include <math.h>

typedef __nv_bfloat16 bf16;

#define MBN   8
#define NQL   1024
#define NKVL  1024
#define HH    8
#define LOG2E 1.4426950408889634f
#define SCALE 0.125f
#define DD    512
#define N4    (MBN*NQL*DD)

__device__ bf16  g_xh[3][N4], g_xm[3][N4];
__device__ bf16  g_wh[4][DD*DD], g_wm[4][DD*DD];
__device__ bf16  g_qh[N4], g_qm[N4], g_kh[N4], g_km[N4];
__device__ float g_vf[N4];
__device__ bf16  g_vth[N4], g_vtm[N4];
__device__ bf16  g_cth[N4], g_ctm[N4];

// ---------------- helpers ----------------
__device__ __forceinline__ uint32_t smem_u32(const void* p){
    uint32_t a;
    asm("{ .reg .u64 t; cvta.to.shared.u64 t, %1; cvt.u32.u64 %0, t; }":"=r"(a):"l"(p));
    return a;
}
__device__ __forceinline__ void cp16(uint32_t s, const void* g){
    asm volatile("cp.async.cg.shared.global [%0], [%1], 16;"::"r"(s),"l"(g));
}
#define CP_COMMIT() asm volatile("cp.async.commit_group;":::"memory")

__device__ __forceinline__ void mma16816(float* c, const uint32_t* a,
                                         uint32_t b0, uint32_t b1){
    asm volatile(
      "mma.sync.aligned.m16n8k16.row.col.f32.bf16.bf16.f32 "
      "{%0,%1,%2,%3}, {%4,%5,%6,%7}, {%8,%9}, {%0,%1,%2,%3};"
      : "+f"(c[0]), "+f"(c[1]), "+f"(c[2]), "+f"(c[3])
      : "r"(a[0]), "r"(a[1]), "r"(a[2]), "r"(a[3]), "r"(b0), "r"(b1));
}
__device__ __forceinline__ void ldm4(uint32_t& r0, uint32_t& r1,
                                     uint32_t& r2, uint32_t& r3, uint32_t a){
    asm volatile("ldmatrix.sync.aligned.m8n8.x4.shared.b16 {%0,%1,%2,%3}, [%4];"
      : "=r"(r0),"=r"(r1),"=r"(r2),"=r"(r3) : "r"(a));
}
__device__ __forceinline__ void psplit2(float a, float b, uint32_t& h, uint32_t& m){
    bf16 ha = __float2bfloat16_rn(a), hb = __float2bfloat16_rn(b);
    bf16 ma = __float2bfloat16_rn(a - __bfloat162float(ha));
    bf16 mb = __float2bfloat16_rn(b - __bfloat162float(hb));
    __nv_bfloat162 H = __halves2bfloat162(ha, hb), M = __halves2bfloat162(ma, mb);
    h = *(uint32_t*)&H; m = *(uint32_t*)&M;
}

// ---------------- prep: xsplit (z<3) + wtrans (z==3), one launch -----------
__global__ void prep(const float* __restrict__ x0, const float* __restrict__ x1,
                     const float* __restrict__ x2,
                     const float* __restrict__ W0, const float* __restrict__ W1,
                     const float* __restrict__ W2, const float* __restrict__ W3,
                     bf16* __restrict__ xh, bf16* __restrict__ xm,
                     bf16* __restrict__ Wh, bf16* __restrict__ Wm){
    int z = blockIdx.y;
    if (z < 3){
        const float* x = (z == 0) ? x0 : (z == 1) ? x1 : x2;
        size_t base = (size_t)z * N4;
        int i = (blockIdx.x*256 + threadIdx.x)*4;
        float4 v = *(const float4*)(x + i);
        uint32_t h0,m0,h1,m1;
        psplit2(v.x,v.y,h0,m0); psplit2(v.z,v.w,h1,m1);
        *(uint32_t*)(xh+base+i) = h0; *(uint32_t*)(xh+base+i+2) = h1;
        *(uint32_t*)(xm+base+i) = m0; *(uint32_t*)(xm+base+i+2) = m1;
    } else {
        // weight transpose: 4 weights x 256 tiles = 1024 active blocks only
        int bidx = blockIdx.x;
        if (bidx >= 1024) return;
        int w  = bidx >> 8;     // 0..3
        int tI = bidx & 255;    // 0..255 (16x16 tiles of 32x32)
        const float* W = (w==0)?W0:(w==1)?W1:(w==2)?W2:W3;
        bf16* wh = Wh + (size_t)w*DD*DD;
        bf16* wm = Wm + (size_t)w*DD*DD;
        __shared__ float t[32][33];
        int n0 = (tI & 15)*32, k0 = (tI >> 4)*32;
        int tx = threadIdx.x & 31, ty = threadIdx.x >> 5;
#pragma unroll
        for (int i=0;i<32;i+=8) t[ty+i][tx] = W[(size_t)(k0+ty+i)*DD + n0+tx];
        __syncthreads();
#pragma unroll
        for (int i=0;i<32;i+=8){
            float v = t[tx][ty+i];
            bf16 hh = __float2bfloat16_rn(v);
            size_t idx = (size_t)(n0+ty+i)*DD + k0+tx;
            wh[idx] = hh;
            wm[idx] = __float2bfloat16_rn(v - __bfloat162float(hh));
        }
    }
}

// ---------------- V f32 -> split transposed ----------------
__global__ void vtrans(const float* __restrict__ V, bf16* __restrict__ Vh,
                       bf16* __restrict__ Vm){
    __shared__ float t[32][33];
    int z = blockIdx.z, m = z>>3, h = z&7;
    int kk0 = blockIdx.x*32, d0 = blockIdx.y*32;
    int tx = threadIdx.x, ty = threadIdx.y;
#pragma unroll
    for (int i=0;i<32;i+=8)
        t[ty+i][tx] = V[(size_t)(m*NKVL + kk0+ty+i)*DD + h*64 + d0+tx];
    __syncthreads();
#pragma unroll
    for (int i=0;i<32;i+=8){
        float v = t[tx][ty+i];
        bf16 hh = __float2bfloat16_rn(v);
        size_t idx = (size_t)(z*64 + d0+ty+i)*NKVL + kk0 + tx;
        Vh[idx] = hh;
        Vm[idx] = __float2bfloat16_rn(v - __bfloat162float(hh));
    }
}

// ---------------- GEMM core macro (ldmatrix fragment loads) ----------------
#define PSTG 40960
#define PJ_SMEM (2*PSTG)

#define PJ_ISSUE(kt, s) do{ \
    uint32_t st = sb + (s)*PSTG; int k0 = (kt)*32; \
    for (int i = tid; i < 512; i += 256){ \
        int r = i>>2; uint32_t ro = r*80 + (i&3)*16; int c8 = (i&3)*8; \
        size_t ga = (size_t)(bm+r)*DD + k0 + c8; \
        cp16(st + ro,         Ah + ga); \
        cp16(st + 10240 + ro, Am + ga); \
        size_t gb = (size_t)(bn+r)*DD + k0 + c8; \
        cp16(st + 20480 + ro, Bh + gb); \
        cp16(st + 30720 + ro, Bm + gb); \
    } CP_COMMIT(); }while(0)

#define PJ_MAINLOOP() \
    PJ_ISSUE(0, 0); \
    _Pragma("unroll 1") \
    for (int kt = 0; kt < 16; kt++){ \
        if (kt < 15){ \
            PJ_ISSUE(kt+1, (kt+1)&1); \
            asm volatile("cp.async.wait_group 1;":::"memory"); \
        } else { \
            asm volatile("cp.async.wait_group 0;":::"memory"); \
        } \
        __syncthreads(); \
        uint32_t sA  = sb + (kt&1)*PSTG; \
        uint32_t sAm = sA + 10240, sB = sA + 20480, sBm = sA + 30720; \
        _Pragma("unroll") \
        for (int ks = 0; ks < 2; ks++){ \
            uint32_t ah[4][4], am[4][4]; \
            _Pragma("unroll") \
            for (int mi = 0; mi < 4; mi++){ \
                uint32_t abase = (uint32_t)((wm + mi*16)*80 + ks*32) + aoffA; \
                ldm4(ah[mi][0],ah[mi][1],ah[mi][2],ah[mi][3], sA  + abase); \
                ldm4(am[mi][0],am[mi][1],am[mi][2],am[mi][3], sAm + abase); \
            } \
            _Pragma("unroll") \
            for (int njp = 0; njp < 2; njp++){ \
                uint32_t bbase = (uint32_t)((wn + njp*16)*80 + ks*32) + aoffB; \
                uint32_t bh0,bh1,bh2,bh3, bm0,bm1,bm2,bm3; \
                ldm4(bh0,bh1,bh2,bh3, sB  + bbase); \
                ldm4(bm0,bm1,bm2,bm3, sBm + bbase); \
                _Pragma("unroll") \
                for (int mi = 0; mi < 4; mi++){ \
                    mma16816(acc[mi][njp*2],   ah[mi], bh0, bh1); \
                    mma16816(acc[mi][njp*2],   ah[mi], bm0, bm1); \
                    mma16816(acc[mi][njp*2],   am[mi], bh0, bh1); \
                    mma16816(acc[mi][njp*2+1], ah[mi], bh2, bh3); \
                    mma16816(acc[mi][njp*2+1], ah[mi], bm2, bm3); \
                    mma16816(acc[mi][njp*2+1], am[mi], bh2, bh3); \
                } \
            } \
        } \
        __syncthreads(); \
    }

#define PJ_LANEOFF() \
    const uint32_t aoffA = (uint32_t)((lane & 7)*80 + ((lane >> 3) & 1)*640 \
                                      + (lane >> 4)*16); \
    const uint32_t aoffB = (uint32_t)((lane & 7)*80 + ((lane >> 3) & 1)*16 \
                                      + (lane >> 4)*640);

// ---------------- merged QKV projection (z = 0:Q 1:K 2:V) ----------------
__global__ void __launch_bounds__(256,2) qkv_proj(
    const bf16* __restrict__ Xh, const bf16* __restrict__ Xm,
    const bf16* __restrict__ Wh, const bf16* __restrict__ Wm,
    bf16* __restrict__ Qh, bf16* __restrict__ Qm,
    bf16* __restrict__ Kh, bf16* __restrict__ Km,
    float* __restrict__ Vf)
{
    extern __shared__ char sp[];
    uint32_t sb = smem_u32(sp);
    const int tid = threadIdx.x, lane = tid & 31, wid = tid >> 5;
    const int ln4 = lane >> 2, q2 = (lane & 3)*2;
    const int wm = (wid & 1)*64, wn = (wid >> 1)*32;
    const int bm = blockIdx.y*128, bn = blockIdx.x*128;
    const int z = blockIdx.z;
    PJ_LANEOFF();
    const bf16* Ah = Xh + (size_t)z*N4;
    const bf16* Am = Xm + (size_t)z*N4;
    const bf16* Bh = Wh + (size_t)z*DD*DD;
    const bf16* Bm = Wm + (size_t)z*DD*DD;
    float acc[4][4][4];
#pragma unroll
    for (int a=0;a<4;a++)
#pragma unroll
      for (int b=0;b<4;b++)
#pragma unroll
        for (int c=0;c<4;c++) acc[a][b][c]=0.f;

    PJ_MAINLOOP();

    // Q pre-scaled by SCALE*LOG2E (exp2 folding)
    const float scale = (z == 0) ? SCALE*LOG2E : 1.0f;
#pragma unroll
    for (int mi = 0; mi < 4; mi++){
        int r0 = bm + wm + mi*16 + ln4;
#pragma unroll
        for (int nj = 0; nj < 4; nj++){
            int c = bn + wn + nj*8 + q2;
            float v0 = acc[mi][nj][0]*scale, v1 = acc[mi][nj][1]*scale;
            float v2 = acc[mi][nj][2]*scale, v3 = acc[mi][nj][3]*scale;
            if (z == 2){
                *(float2*)(Vf + (size_t)r0*DD + c)     = make_float2(v0, v1);
                *(float2*)(Vf + (size_t)(r0+8)*DD + c) = make_float2(v2, v3);
            } else {
                bf16* Ch = (z == 0) ? Qh : Kh;
                bf16* Cm = (z == 0) ? Qm : Km;
                uint32_t h, m;
                psplit2(v0, v1, h, m);
                *(uint32_t*)(Ch + (size_t)r0*DD + c) = h;
                *(uint32_t*)(Cm + (size_t)r0*DD + c) = m;
                psplit2(v2, v3, h, m);
                *(uint32_t*)(Ch + (size_t)(r0+8)*DD + c) = h;
                *(uint32_t*)(Cm + (size_t)(r0+8)*DD + c) = m;
            }
        }
    }
}

// ---------------- output projection ----------------
__global__ void __launch_bounds__(256,2) out_proj(
    const bf16* __restrict__ Ah, const bf16* __restrict__ Am,
    const bf16* __restrict__ Bh, const bf16* __restrict__ Bm,
    const float* __restrict__ bias, float* __restrict__ Cf)
{
    extern __shared__ char sp[];
    uint32_t sb = smem_u32(sp);
    const int tid = threadIdx.x, lane = tid & 31, wid = tid >> 5;
    const int ln4 = lane >> 2, q2 = (lane & 3)*2;
    const int wm = (wid & 1)*64, wn = (wid >> 1)*32;
    const int bm = blockIdx.y*128, bn = blockIdx.x*128;
    PJ_LANEOFF();
    float acc[4][4][4];
#pragma unroll
    for (int a=0;a<4;a++)
#pragma unroll
      for (int b=0;b<4;b++)
#pragma unroll
        for (int c=0;c<4;c++) acc[a][b][c]=0.f;

    PJ_MAINLOOP();

#pragma unroll
    for (int mi = 0; mi < 4; mi++){
        int r0 = bm + wm + mi*16 + ln4;
#pragma unroll
        for (int nj = 0; nj < 4; nj++){
            int c = bn + wn + nj*8 + q2;
            float b0 = bias[c], b1 = bias[c+1];
            *(float2*)(Cf + (size_t)r0*DD + c) =
                make_float2(acc[mi][nj][0] + b0, acc[mi][nj][1] + b1);
            *(float2*)(Cf + (size_t)(r0+8)*DD + c) =
                make_float2(acc[mi][nj][2] + b0, acc[mi][nj][3] + b1);
        }
    }
}

// ---------------- fused attention: 3-stage pipeline + ldmatrix ----------------
#define O_QH 0
#define O_QM 18432
#define O_KV 36864
#define KVSTG 36864
#define S_KH 0
#define S_KM 9216
#define S_VH 18432
#define S_VM 27648
#define O_HK (O_KV + 3*KVSTG)
#define HKSTG 5120
#define O_V1 (O_HK + 3*HKSTG)
#define AT_SMEM (O_V1 + 3*256)

__global__ void __launch_bounds__(256) attn_bf(
    const bf16* __restrict__ Qh_g, const bf16* __restrict__ Qm_g,
    const bf16* __restrict__ Kh_g, const bf16* __restrict__ Km_g,
    const bf16* __restrict__ Vh_g, const bf16* __restrict__ Vm_g,
    const float* __restrict__ Tq, const float* __restrict__ Tk,
    const float* __restrict__ kw1, const float* __restrict__ kb1,
    const float* __restrict__ kw2, const float* __restrict__ kb2,
    bf16* __restrict__ Cth, bf16* __restrict__ Ctm)
{
    extern __shared__ char sp[];
    uint32_t sb = smem_u32(sp);

    const int tid = threadIdx.x, lane = tid & 31, wid = tid >> 5;
    const int ln4 = lane >> 2, q2 = (lane & 3)*2;
    const int m = blockIdx.z, h = blockIdx.y, q0 = blockIdx.x*128;
    const int rl0 = wid*16 + ln4;
    const uint32_t lmo = (uint32_t)((lane & 7)*144 + ((lane >> 3) >> 1)*32
                                    + ((lane >> 3) & 1)*16);

    for (int i = tid; i < 1024; i += 256){
        int r = i>>3; uint32_t ro = r*144 + (i&7)*16;
        size_t g = (size_t)(m*NQL+q0+r)*DD + h*64 + (i&7)*8;
        cp16(sb + O_QH + ro, Qh_g + g);
        cp16(sb + O_QM + ro, Qm_g + g);
    }
#define KV_ISSUE(kk0, s) do{ \
    uint32_t st = sb + O_KV + (s)*KVSTG; \
    for (int i = tid; i < 512; i += 256){ \
        int r = i>>3; uint32_t ro = r*144 + (i&7)*16; int c8 = (i&7)*8; \
        size_t gk = (size_t)(m*NKVL + (kk0) + r)*DD + h*64 + c8; \
        cp16(st + S_KH + ro, Kh_g + gk); \
        cp16(st + S_KM + ro, Km_g + gk); \
        size_t gv = (size_t)((m*HH+h)*64 + r)*NKVL + (kk0) + c8; \
        cp16(st + S_VH + ro, Vh_g + gv); \
        cp16(st + S_VM + ro, Vm_g + gv); \
    } CP_COMMIT(); }while(0)

// ws/U1/V1 all pre-scaled by LOG2E (exp2 folding)
#define HK_GEN(tile, s) do{ \
    if (tid < 64){ \
        float2 tk2 = *(const float2*)(Tk + (size_t)(m*NKVL + (tile)*64 + tid)*2); \
        float v1 = 0.f; \
        float* Hb = (float*)(sp + O_HK + (s)*HKSTG); \
        _Pragma("unroll") \
        for (int j = 0; j < 16; j++){ \
            float hk = tk2.x*kw1[j] + tk2.y*kw1[16+j]; \
            Hb[tid*20 + j] = hk; \
            v1 = fmaf(ws[j], hk, v1); \
        } \
        ((float*)(sp + O_V1))[(s)*64 + tid] = v1; \
    } }while(0)

    KV_ISSUE(0, 0);
    KV_ISSUE(64, 1);

    float ws[16], uq0[16], uq1[16];
    float2 ta = *(const float2*)(Tq + (size_t)(m*NQL + q0 + rl0)*2);
    float2 tb = *(const float2*)(Tq + (size_t)(m*NQL + q0 + rl0 + 8)*2);
    float U1r0 = (kb2[h] - 10.f)*LOG2E, U1r1 = U1r0;
#pragma unroll
    for (int j = 0; j < 16; j++){
        ws[j] = 0.5f*LOG2E*kw2[j*HH + h];
        float w0 = kw1[j], w1 = kw1[16+j], b = kb1[j];
        uq0[j] = ta.x*w0 + ta.y*w1 + b;
        uq1[j] = tb.x*w0 + tb.y*w1 + b;
        U1r0 = fmaf(ws[j], uq0[j], U1r0);
        U1r1 = fmaf(ws[j], uq1[j], U1r1);
    }
    HK_GEN(0, 0);
    HK_GEN(1, 1);

    asm volatile("cp.async.wait_group 1;":::"memory");
    __syncthreads();
    uint32_t qa[4][4], qb[4][4];
    {
        const bf16* Qh = (const bf16*)(sp + O_QH);
        const bf16* Qm = (const bf16*)(sp + O_QM);
#pragma unroll
        for (int ks = 0; ks < 4; ks++){
            int kb = ks*16 + q2;
            const bf16* p = Qh + rl0*72 + kb;
            qa[ks][0]=*(const uint32_t*)p;     qa[ks][1]=*(const uint32_t*)(p+8*72);
            qa[ks][2]=*(const uint32_t*)(p+8); qa[ks][3]=*(const uint32_t*)(p+8*72+8);
            const bf16* pm = Qm + rl0*72 + kb;
            qb[ks][0]=*(const uint32_t*)pm;     qb[ks][1]=*(const uint32_t*)(pm+8*72);
            qb[ks][2]=*(const uint32_t*)(pm+8); qb[ks][3]=*(const uint32_t*)(pm+8*72+8);
        }
    }

    float oacc[8][4];
#pragma unroll
    for (int j=0;j<8;j++)
#pragma unroll
        for (int c=0;c<4;c++) oacc[j][c]=0.f;
    float l0 = 0.f, l1 = 0.f;

#pragma unroll 1
    for (int t = 0; t < 16; t++){
        if (t > 0){
            if (t < 15){
                asm volatile("cp.async.wait_group 1;":::"memory");
            } else {
                asm volatile("cp.async.wait_group 0;":::"memory");
            }
            __syncthreads();
        }
        if (t <= 13){
            int s2 = (t+2) % 3;
            KV_ISSUE((t+2)*64, s2);
            HK_GEN(t+2, s2);
        }
        const int scur = t % 3;
        const uint32_t stb = sb + O_KV + scur*KVSTG;
        const uint32_t kh_a = stb + S_KH + lmo;
        const uint32_t km_a = stb + S_KM + lmo;
        const uint32_t vh_a = stb + S_VH + lmo;
        const uint32_t vm_a = stb + S_VM + lmo;
        const float* Hc = (const float*)(sp + O_HK + scur*HKSTG);
        const float* Vc = (const float*)(sp + O_V1) + scur*64;

        float sacc[8][4];
#pragma unroll
        for (int j = 0; j < 8; j++){
#pragma unroll
            for (int c = 0; c < 4; c++) sacc[j][c] = 0.f;
#pragma unroll
            for (int p = 0; p < 2; p++){
                uint32_t kh0,kh1,kh2,kh3, km0,km1,km2,km3;
                ldm4(kh0,kh1,kh2,kh3, kh_a + j*1152 + p*64);
                ldm4(km0,km1,km2,km3, km_a + j*1152 + p*64);
                mma16816(sacc[j], qa[2*p],   kh0, kh1);
                mma16816(sacc[j], qa[2*p],   km0, km1);
                mma16816(sacc[j], qb[2*p],   kh0, kh1);
                mma16816(sacc[j], qa[2*p+1], kh2, kh3);
                mma16816(sacc[j], qa[2*p+1], km2, km3);
                mma16816(sacc[j], qb[2*p+1], kh2, kh3);
            }
        }

        uint32_t pah[4][4], pam[4][4];
#pragma unroll
        for (int j = 0; j < 8; j++){
            float pe[4];
#pragma unroll
            for (int e = 0; e < 2; e++){
                int c = j*8 + q2 + e;
                const float4* hp = (const float4*)(Hc + c*20);
                float4 f0 = hp[0], f1 = hp[1], f2 = hp[2], f3 = hp[3];
                float hv[16] = {f0.x,f0.y,f0.z,f0.w, f1.x,f1.y,f1.z,f1.w,
                                f2.x,f2.y,f2.z,f2.w, f3.x,f3.y,f3.z,f3.w};
                float v1c = Vc[c];
                float s0 = sacc[j][e]   + U1r0 - v1c;
                float s1 = sacc[j][2+e] + U1r1 - v1c;
#pragma unroll
                for (int jj = 0; jj < 16; jj++){
                    s0 = fmaf(ws[jj], fabsf(uq0[jj] - hv[jj]), s0);
                    s1 = fmaf(ws[jj], fabsf(uq1[jj] - hv[jj]), s1);
                }
                float e0 = exp2f(s0), e1 = exp2f(s1);
                l0 += e0; l1 += e1;
                pe[e] = e0; pe[2+e] = e1;
            }
            int tt2 = j >> 1, base = (j & 1)*2;
            psplit2(pe[0], pe[1], pah[tt2][base],   pam[tt2][base]);
            psplit2(pe[2], pe[3], pah[tt2][base+1], pam[tt2][base+1]);
        }

#pragma unroll
        for (int j2 = 0; j2 < 8; j2++){
#pragma unroll
            for (int p = 0; p < 2; p++){
                uint32_t vh0,vh1,vh2,vh3, vm0,vm1,vm2,vm3;
                ldm4(vh0,vh1,vh2,vh3, vh_a + j2*1152 + p*64);
                ldm4(vm0,vm1,vm2,vm3, vm_a + j2*1152 + p*64);
                mma16816(oacc[j2], pah[2*p],   vh0, vh1);
                mma16816(oacc[j2], pah[2*p],   vm0, vm1);
                mma16816(oacc[j2], pam[2*p],   vh0, vh1);
                mma16816(oacc[j2], pah[2*p+1], vh2, vh3);
                mma16816(oacc[j2], pah[2*p+1], vm2, vm3);
                mma16816(oacc[j2], pam[2*p+1], vh2, vh3);
            }
        }
    }

    l0 += __shfl_xor_sync(0xffffffffu, l0, 1);
    l0 += __shfl_xor_sync(0xffffffffu, l0, 2);
    l1 += __shfl_xor_sync(0xffffffffu, l1, 1);
    l1 += __shfl_xor_sync(0xffffffffu, l1, 2);
    float inv0 = 1.f/l0, inv1 = 1.f/l1;
    size_t o0 = (size_t)(m*NQL + q0 + rl0)*DD + h*64;
    size_t o1 = o0 + 8*DD;
#pragma unroll
    for (int j2 = 0; j2 < 8; j2++){
        int c = j2*8 + q2;
        uint32_t hh, mm;
        psplit2(oacc[j2][0]*inv0, oacc[j2][1]*inv0, hh, mm);
        *(uint32_t*)(Cth + o0 + c) = hh; *(uint32_t*)(Ctm + o0 + c) = mm;
        psplit2(oacc[j2][2]*inv1, oacc[j2][3]*inv1, hh, mm);
        *(uint32_t*)(Cth + o1 + c) = hh; *(uint32_t*)(Ctm + o1 + c) = mm;
    }
}

// ---------------- host launcher ----------------
extern "C" void kernel_launch(void* const* d_in, const int* in_sizes, int n_in,
                              void* d_out, int out_size)
{
    const float* xq    = (const float*)d_in[0];
    const float* xk    = (const float*)d_in[1];
    const float* xv    = (const float*)d_in[2];
    const float* tq    = (const float*)d_in[3];
    const float* tk    = (const float*)d_in[4];
    const float* w_q   = (const float*)d_in[5];
    const float* w_k   = (const float*)d_in[6];
    const float* w_v   = (const float*)d_in[7];
    const float* w_out = (const float*)d_in[8];
    const float* b_out = (const float*)d_in[9];
    const float* kw1   = (const float*)d_in[10];
    const float* kb1   = (const float*)d_in[11];
    const float* kw2   = (const float*)d_in[12];
    const float* kb2   = (const float*)d_in[13];
    float* out = (float*)d_out;

    bf16 *xh,*xm,*wh,*wm,*qh,*qm,*kh,*km,*vth,*vtm,*cth,*ctm;
    float *vf;
    cudaGetSymbolAddress((void**)&xh,  g_xh);
    cudaGetSymbolAddress((void**)&xm,  g_xm);
    cudaGetSymbolAddress((void**)&wh,  g_wh);
    cudaGetSymbolAddress((void**)&wm,  g_wm);
    cudaGetSymbolAddress((void**)&qh,  g_qh);
    cudaGetSymbolAddress((void**)&qm,  g_qm);
    cudaGetSymbolAddress((void**)&kh,  g_kh);
    cudaGetSymbolAddress((void**)&km,  g_km);
    cudaGetSymbolAddress((void**)&vf,  g_vf);
    cudaGetSymbolAddress((void**)&vth, g_vth);
    cudaGetSymbolAddress((void**)&vtm, g_vtm);
    cudaGetSymbolAddress((void**)&cth, g_cth);
    cudaGetSymbolAddress((void**)&ctm, g_ctm);

    cudaFuncSetAttribute(qkv_proj, cudaFuncAttributeMaxDynamicSharedMemorySize, PJ_SMEM);
    cudaFuncSetAttribute(out_proj, cudaFuncAttributeMaxDynamicSharedMemorySize, PJ_SMEM);
    cudaFuncSetAttribute(attn_bf,  cudaFuncAttributeMaxDynamicSharedMemorySize, AT_SMEM);

    dim3 gp(N4/1024, 4);
    prep<<<gp, 256>>>(xq, xk, xv, w_q, w_k, w_v, w_out, xh, xm, wh, wm);

    dim3 gq(4, 64, 3);
    qkv_proj<<<gq,256,PJ_SMEM>>>(xh, xm, wh, wm, qh, qm, kh, km, vf);

    dim3 gv(32, 2, 64), tb(32,8);
    vtrans<<<gv,tb>>>(vf, vth, vtm);

    dim3 ga(8, HH, MBN);
    attn_bf<<<ga,256,AT_SMEM>>>(qh, qm, kh, km, vth, vtm,
                                tq, tk, kw1, kb1, kw2, kb2, cth, ctm);

    dim3 go(4, 64);
    out_proj<<<go,256,PJ_SMEM>>>(cth, ctm, wh+3*(size_t)DD*DD, wm+3*(size_t)DD*DD,
                                 b_out, out);
}

// round 14
// speedup vs baseline: 1.2541x; 1.1037x over previous
#include <cuda_runtime.h>
#include <cuda_fp16.h>
#include <cstdint>
#include <math.h>

typedef __half hf;

#define MBN   8
#define NQL   1024
#define NKVL  1024
#define HH    8
#define LOG2E 1.4426950408889634f
#define SCALE 0.125f
#define DD    512
#define N4    (MBN*NQL*DD)

__device__ hf    g_xh[3][N4], g_xm[3][N4];
__device__ hf    g_wh[4][DD*DD], g_wm[4][DD*DD];
__device__ hf    g_qh[N4], g_qm[N4], g_kh[N4], g_km[N4];
__device__ float g_vf[N4];
__device__ hf    g_vth[N4];
__device__ hf    g_cth[N4], g_ctm[N4];

// ---------------- helpers ----------------
__device__ __forceinline__ uint32_t smem_u32(const void* p){
    uint32_t a;
    asm("{ .reg .u64 t; cvta.to.shared.u64 t, %1; cvt.u32.u64 %0, t; }":"=r"(a):"l"(p));
    return a;
}
__device__ __forceinline__ void cp16(uint32_t s, const void* g){
    asm volatile("cp.async.cg.shared.global [%0], [%1], 16;"::"r"(s),"l"(g));
}
#define CP_COMMIT() asm volatile("cp.async.commit_group;":::"memory")

__device__ __forceinline__ void mma16816(float* c, const uint32_t* a,
                                         uint32_t b0, uint32_t b1){
    asm volatile(
      "mma.sync.aligned.m16n8k16.row.col.f32.f16.f16.f32 "
      "{%0,%1,%2,%3}, {%4,%5,%6,%7}, {%8,%9}, {%0,%1,%2,%3};"
      : "+f"(c[0]), "+f"(c[1]), "+f"(c[2]), "+f"(c[3])
      : "r"(a[0]), "r"(a[1]), "r"(a[2]), "r"(a[3]), "r"(b0), "r"(b1));
}
__device__ __forceinline__ void ldm4(uint32_t& r0, uint32_t& r1,
                                     uint32_t& r2, uint32_t& r3, uint32_t a){
    asm volatile("ldmatrix.sync.aligned.m8n8.x4.shared.b16 {%0,%1,%2,%3}, [%4];"
      : "=r"(r0),"=r"(r1),"=r"(r2),"=r"(r3) : "r"(a));
}
__device__ __forceinline__ void hsplit2(float a, float b, uint32_t& h, uint32_t& m){
    hf ha = __float2half_rn(a), hb = __float2half_rn(b);
    hf ma = __float2half_rn(a - __half2float(ha));
    hf mb = __float2half_rn(b - __half2float(hb));
    __half2 H = __halves2half2(ha, hb), M = __halves2half2(ma, mb);
    h = *(uint32_t*)&H; m = *(uint32_t*)&M;
}

// ---------------- prep: xsplit (z<3) + wtrans (z==3), one launch -----------
__global__ void prep(const float* __restrict__ x0, const float* __restrict__ x1,
                     const float* __restrict__ x2,
                     const float* __restrict__ W0, const float* __restrict__ W1,
                     const float* __restrict__ W2, const float* __restrict__ W3,
                     hf* __restrict__ xh, hf* __restrict__ xm,
                     hf* __restrict__ Wh, hf* __restrict__ Wm){
    int z = blockIdx.y;
    if (z < 3){
        const float* x = (z == 0) ? x0 : (z == 1) ? x1 : x2;
        size_t base = (size_t)z * N4;
        int i = (blockIdx.x*256 + threadIdx.x)*4;
        float4 v = *(const float4*)(x + i);
        uint32_t h0,m0,h1,m1;
        hsplit2(v.x,v.y,h0,m0); hsplit2(v.z,v.w,h1,m1);
        *(uint32_t*)(xh+base+i) = h0; *(uint32_t*)(xh+base+i+2) = h1;
        *(uint32_t*)(xm+base+i) = m0; *(uint32_t*)(xm+base+i+2) = m1;
    } else {
        int bidx = blockIdx.x;
        if (bidx >= 1024) return;
        int w  = bidx >> 8;
        int tI = bidx & 255;
        const float* W = (w==0)?W0:(w==1)?W1:(w==2)?W2:W3;
        hf* wh = Wh + (size_t)w*DD*DD;
        hf* wm = Wm + (size_t)w*DD*DD;
        __shared__ float t[32][33];
        int n0 = (tI & 15)*32, k0 = (tI >> 4)*32;
        int tx = threadIdx.x & 31, ty = threadIdx.x >> 5;
#pragma unroll
        for (int i=0;i<32;i+=8) t[ty+i][tx] = W[(size_t)(k0+ty+i)*DD + n0+tx];
        __syncthreads();
#pragma unroll
        for (int i=0;i<32;i+=8){
            float v = t[tx][ty+i];
            hf hh = __float2half_rn(v);
            size_t idx = (size_t)(n0+ty+i)*DD + k0+tx;
            wh[idx] = hh;
            wm[idx] = __float2half_rn(v - __half2float(hh));
        }
    }
}

// ---------------- V f32 -> fp16 transposed (single precision pass) ---------
__global__ void vtrans(const float* __restrict__ V, hf* __restrict__ Vh){
    __shared__ float t[32][33];
    int z = blockIdx.z, m = z>>3, h = z&7;
    int kk0 = blockIdx.x*32, d0 = blockIdx.y*32;
    int tx = threadIdx.x, ty = threadIdx.y;
#pragma unroll
    for (int i=0;i<32;i+=8)
        t[ty+i][tx] = V[(size_t)(m*NKVL + kk0+ty+i)*DD + h*64 + d0+tx];
    __syncthreads();
#pragma unroll
    for (int i=0;i<32;i+=8){
        size_t idx = (size_t)(z*64 + d0+ty+i)*NKVL + kk0 + tx;
        Vh[idx] = __float2half_rn(t[tx][ty+i]);
    }
}

// ---------------- GEMM core macro (ldmatrix fragment loads) ----------------
#define PSTG 40960
#define PJ_SMEM (2*PSTG)

#define PJ_ISSUE(kt, s) do{ \
    uint32_t st = sb + (s)*PSTG; int k0 = (kt)*32; \
    for (int i = tid; i < 512; i += 256){ \
        int r = i>>2; uint32_t ro = r*80 + (i&3)*16; int c8 = (i&3)*8; \
        size_t ga = (size_t)(bm+r)*DD + k0 + c8; \
        cp16(st + ro,         Ah + ga); \
        cp16(st + 10240 + ro, Am + ga); \
        size_t gb = (size_t)(bn+r)*DD + k0 + c8; \
        cp16(st + 20480 + ro, Bh + gb); \
        cp16(st + 30720 + ro, Bm + gb); \
    } CP_COMMIT(); }while(0)

#define PJ_MAINLOOP() \
    PJ_ISSUE(0, 0); \
    _Pragma("unroll 1") \
    for (int kt = 0; kt < 16; kt++){ \
        if (kt < 15){ \
            PJ_ISSUE(kt+1, (kt+1)&1); \
            asm volatile("cp.async.wait_group 1;":::"memory"); \
        } else { \
            asm volatile("cp.async.wait_group 0;":::"memory"); \
        } \
        __syncthreads(); \
        uint32_t sA  = sb + (kt&1)*PSTG; \
        uint32_t sAm = sA + 10240, sB = sA + 20480, sBm = sA + 30720; \
        _Pragma("unroll") \
        for (int ks = 0; ks < 2; ks++){ \
            uint32_t ah[4][4], am[4][4]; \
            _Pragma("unroll") \
            for (int mi = 0; mi < 4; mi++){ \
                uint32_t abase = (uint32_t)((wm + mi*16)*80 + ks*32) + aoffA; \
                ldm4(ah[mi][0],ah[mi][1],ah[mi][2],ah[mi][3], sA  + abase); \
                ldm4(am[mi][0],am[mi][1],am[mi][2],am[mi][3], sAm + abase); \
            } \
            _Pragma("unroll") \
            for (int njp = 0; njp < 2; njp++){ \
                uint32_t bbase = (uint32_t)((wn + njp*16)*80 + ks*32) + aoffB; \
                uint32_t bh0,bh1,bh2,bh3, bm0,bm1,bm2,bm3; \
                ldm4(bh0,bh1,bh2,bh3, sB  + bbase); \
                ldm4(bm0,bm1,bm2,bm3, sBm + bbase); \
                _Pragma("unroll") \
                for (int mi = 0; mi < 4; mi++){ \
                    mma16816(acc[mi][njp*2],   ah[mi], bh0, bh1); \
                    mma16816(acc[mi][njp*2],   ah[mi], bm0, bm1); \
                    mma16816(acc[mi][njp*2],   am[mi], bh0, bh1); \
                    mma16816(acc[mi][njp*2+1], ah[mi], bh2, bh3); \
                    mma16816(acc[mi][njp*2+1], ah[mi], bm2, bm3); \
                    mma16816(acc[mi][njp*2+1], am[mi], bh2, bh3); \
                } \
            } \
        } \
        __syncthreads(); \
    }

#define PJ_LANEOFF() \
    const uint32_t aoffA = (uint32_t)((lane & 7)*80 + ((lane >> 3) & 1)*640 \
                                      + (lane >> 4)*16); \
    const uint32_t aoffB = (uint32_t)((lane & 7)*80 + ((lane >> 3) & 1)*16 \
                                      + (lane >> 4)*640);

// ---------------- merged QKV projection (z = 0:Q 1:K 2:V) ----------------
__global__ void __launch_bounds__(256,2) qkv_proj(
    const hf* __restrict__ Xh, const hf* __restrict__ Xm,
    const hf* __restrict__ Wh, const hf* __restrict__ Wm,
    hf* __restrict__ Qh, hf* __restrict__ Qm,
    hf* __restrict__ Kh, hf* __restrict__ Km,
    float* __restrict__ Vf)
{
    extern __shared__ char sp[];
    uint32_t sb = smem_u32(sp);
    const int tid = threadIdx.x, lane = tid & 31, wid = tid >> 5;
    const int ln4 = lane >> 2, q2 = (lane & 3)*2;
    const int wm = (wid & 1)*64, wn = (wid >> 1)*32;
    const int bm = blockIdx.y*128, bn = blockIdx.x*128;
    const int z = blockIdx.z;
    PJ_LANEOFF();
    const hf* Ah = Xh + (size_t)z*N4;
    const hf* Am = Xm + (size_t)z*N4;
    const hf* Bh = Wh + (size_t)z*DD*DD;
    const hf* Bm = Wm + (size_t)z*DD*DD;
    float acc[4][4][4];
#pragma unroll
    for (int a=0;a<4;a++)
#pragma unroll
      for (int b=0;b<4;b++)
#pragma unroll
        for (int c=0;c<4;c++) acc[a][b][c]=0.f;

    PJ_MAINLOOP();

    const float scale = (z == 0) ? SCALE*LOG2E : 1.0f;
#pragma unroll
    for (int mi = 0; mi < 4; mi++){
        int r0 = bm + wm + mi*16 + ln4;
#pragma unroll
        for (int nj = 0; nj < 4; nj++){
            int c = bn + wn + nj*8 + q2;
            float v0 = acc[mi][nj][0]*scale, v1 = acc[mi][nj][1]*scale;
            float v2 = acc[mi][nj][2]*scale, v3 = acc[mi][nj][3]*scale;
            if (z == 2){
                *(float2*)(Vf + (size_t)r0*DD + c)     = make_float2(v0, v1);
                *(float2*)(Vf + (size_t)(r0+8)*DD + c) = make_float2(v2, v3);
            } else {
                hf* Ch = (z == 0) ? Qh : Kh;
                hf* Cm = (z == 0) ? Qm : Km;
                uint32_t h, m;
                hsplit2(v0, v1, h, m);
                *(uint32_t*)(Ch + (size_t)r0*DD + c) = h;
                *(uint32_t*)(Cm + (size_t)r0*DD + c) = m;
                hsplit2(v2, v3, h, m);
                *(uint32_t*)(Ch + (size_t)(r0+8)*DD + c) = h;
                *(uint32_t*)(Cm + (size_t)(r0+8)*DD + c) = m;
            }
        }
    }
}

// ---------------- output projection ----------------
__global__ void __launch_bounds__(256,2) out_proj(
    const hf* __restrict__ Ah, const hf* __restrict__ Am,
    const hf* __restrict__ Bh, const hf* __restrict__ Bm,
    const float* __restrict__ bias, float* __restrict__ Cf)
{
    extern __shared__ char sp[];
    uint32_t sb = smem_u32(sp);
    const int tid = threadIdx.x, lane = tid & 31, wid = tid >> 5;
    const int ln4 = lane >> 2, q2 = (lane & 3)*2;
    const int wm = (wid & 1)*64, wn = (wid >> 1)*32;
    const int bm = blockIdx.y*128, bn = blockIdx.x*128;
    PJ_LANEOFF();
    float acc[4][4][4];
#pragma unroll
    for (int a=0;a<4;a++)
#pragma unroll
      for (int b=0;b<4;b++)
#pragma unroll
        for (int c=0;c<4;c++) acc[a][b][c]=0.f;

    PJ_MAINLOOP();

#pragma unroll
    for (int mi = 0; mi < 4; mi++){
        int r0 = bm + wm + mi*16 + ln4;
#pragma unroll
        for (int nj = 0; nj < 4; nj++){
            int c = bn + wn + nj*8 + q2;
            float b0 = bias[c], b1 = bias[c+1];
            *(float2*)(Cf + (size_t)r0*DD + c) =
                make_float2(acc[mi][nj][0] + b0, acc[mi][nj][1] + b1);
            *(float2*)(Cf + (size_t)(r0+8)*DD + c) =
                make_float2(acc[mi][nj][2] + b0, acc[mi][nj][3] + b1);
        }
    }
}

// ---------------- fused attention: fp16, 3-stage pipeline + ldmatrix --------
#define O_QH 0
#define O_QM 18432
#define O_KV 36864
#define KVSTG 27648
#define S_KH 0
#define S_KM 9216
#define S_VH 18432
#define O_HK (O_KV + 3*KVSTG)
#define HKSTG 5120
#define O_V1 (O_HK + 3*HKSTG)
#define AT_SMEM (O_V1 + 3*256)

__global__ void __launch_bounds__(256) attn_bf(
    const hf* __restrict__ Qh_g, const hf* __restrict__ Qm_g,
    const hf* __restrict__ Kh_g, const hf* __restrict__ Km_g,
    const hf* __restrict__ Vh_g,
    const float* __restrict__ Tq, const float* __restrict__ Tk,
    const float* __restrict__ kw1, const float* __restrict__ kb1,
    const float* __restrict__ kw2, const float* __restrict__ kb2,
    hf* __restrict__ Cth, hf* __restrict__ Ctm)
{
    extern __shared__ char sp[];
    uint32_t sb = smem_u32(sp);

    const int tid = threadIdx.x, lane = tid & 31, wid = tid >> 5;
    const int ln4 = lane >> 2, q2 = (lane & 3)*2;
    const int m = blockIdx.z, h = blockIdx.y, q0 = blockIdx.x*128;
    const int rl0 = wid*16 + ln4;
    const uint32_t lmo = (uint32_t)((lane & 7)*144 + ((lane >> 3) >> 1)*32
                                    + ((lane >> 3) & 1)*16);

    for (int i = tid; i < 1024; i += 256){
        int r = i>>3; uint32_t ro = r*144 + (i&7)*16;
        size_t g = (size_t)(m*NQL+q0+r)*DD + h*64 + (i&7)*8;
        cp16(sb + O_QH + ro, Qh_g + g);
        cp16(sb + O_QM + ro, Qm_g + g);
    }
#define KV_ISSUE(kk0, s) do{ \
    uint32_t st = sb + O_KV + (s)*KVSTG; \
    for (int i = tid; i < 512; i += 256){ \
        int r = i>>3; uint32_t ro = r*144 + (i&7)*16; int c8 = (i&7)*8; \
        size_t gk = (size_t)(m*NKVL + (kk0) + r)*DD + h*64 + c8; \
        cp16(st + S_KH + ro, Kh_g + gk); \
        cp16(st + S_KM + ro, Km_g + gk); \
        size_t gv = (size_t)((m*HH+h)*64 + r)*NKVL + (kk0) + c8; \
        cp16(st + S_VH + ro, Vh_g + gv); \
    } CP_COMMIT(); }while(0)

#define HK_GEN(tile, s) do{ \
    if (tid < 64){ \
        float2 tk2 = *(const float2*)(Tk + (size_t)(m*NKVL + (tile)*64 + tid)*2); \
        float v1 = 0.f; \
        float* Hb = (float*)(sp + O_HK + (s)*HKSTG); \
        _Pragma("unroll") \
        for (int j = 0; j < 16; j++){ \
            float hk = tk2.x*kw1[j] + tk2.y*kw1[16+j]; \
            Hb[tid*20 + j] = hk; \
            v1 = fmaf(ws[j], hk, v1); \
        } \
        ((float*)(sp + O_V1))[(s)*64 + tid] = v1; \
    } }while(0)

    KV_ISSUE(0, 0);
    KV_ISSUE(64, 1);

    float ws[16], uq0[16], uq1[16];
    float2 ta = *(const float2*)(Tq + (size_t)(m*NQL + q0 + rl0)*2);
    float2 tb = *(const float2*)(Tq + (size_t)(m*NQL + q0 + rl0 + 8)*2);
    // shift -2 keeps p=2^s' in fp16 range (max ~2^15 at s~+13)
    float U1r0 = (kb2[h] - 2.f)*LOG2E, U1r1 = U1r0;
#pragma unroll
    for (int j = 0; j < 16; j++){
        ws[j] = 0.5f*LOG2E*kw2[j*HH + h];
        float w0 = kw1[j], w1 = kw1[16+j], b = kb1[j];
        uq0[j] = ta.x*w0 + ta.y*w1 + b;
        uq1[j] = tb.x*w0 + tb.y*w1 + b;
        U1r0 = fmaf(ws[j], uq0[j], U1r0);
        U1r1 = fmaf(ws[j], uq1[j], U1r1);
    }
    HK_GEN(0, 0);
    HK_GEN(1, 1);

    asm volatile("cp.async.wait_group 1;":::"memory");
    __syncthreads();
    uint32_t qa[4][4], qb[4][4];
    {
        const hf* Qh = (const hf*)(sp + O_QH);
        const hf* Qm = (const hf*)(sp + O_QM);
#pragma unroll
        for (int ks = 0; ks < 4; ks++){
            int kb = ks*16 + q2;
            const hf* p = Qh + rl0*72 + kb;
            qa[ks][0]=*(const uint32_t*)p;     qa[ks][1]=*(const uint32_t*)(p+8*72);
            qa[ks][2]=*(const uint32_t*)(p+8); qa[ks][3]=*(const uint32_t*)(p+8*72+8);
            const hf* pm = Qm + rl0*72 + kb;
            qb[ks][0]=*(const uint32_t*)pm;     qb[ks][1]=*(const uint32_t*)(pm+8*72);
            qb[ks][2]=*(const uint32_t*)(pm+8); qb[ks][3]=*(const uint32_t*)(pm+8*72+8);
        }
    }

    float oacc[8][4];
#pragma unroll
    for (int j=0;j<8;j++)
#pragma unroll
        for (int c=0;c<4;c++) oacc[j][c]=0.f;
    float l0 = 0.f, l1 = 0.f;

#pragma unroll 1
    for (int t = 0; t < 16; t++){
        if (t > 0){
            if (t < 15){
                asm volatile("cp.async.wait_group 1;":::"memory");
            } else {
                asm volatile("cp.async.wait_group 0;":::"memory");
            }
            __syncthreads();
        }
        if (t <= 13){
            int s2 = (t+2) % 3;
            KV_ISSUE((t+2)*64, s2);
            HK_GEN(t+2, s2);
        }
        const int scur = t % 3;
        const uint32_t stb = sb + O_KV + scur*KVSTG;
        const uint32_t kh_a = stb + S_KH + lmo;
        const uint32_t km_a = stb + S_KM + lmo;
        const uint32_t vh_a = stb + S_VH + lmo;
        const float* Hc = (const float*)(sp + O_HK + scur*HKSTG);
        const float* Vc = (const float*)(sp + O_V1) + scur*64;

        float sacc[8][4];
#pragma unroll
        for (int j = 0; j < 8; j++){
#pragma unroll
            for (int c = 0; c < 4; c++) sacc[j][c] = 0.f;
#pragma unroll
            for (int p = 0; p < 2; p++){
                uint32_t kh0,kh1,kh2,kh3, km0,km1,km2,km3;
                ldm4(kh0,kh1,kh2,kh3, kh_a + j*1152 + p*64);
                ldm4(km0,km1,km2,km3, km_a + j*1152 + p*64);
                mma16816(sacc[j], qa[2*p],   kh0, kh1);
                mma16816(sacc[j], qa[2*p],   km0, km1);
                mma16816(sacc[j], qb[2*p],   kh0, kh1);
                mma16816(sacc[j], qa[2*p+1], kh2, kh3);
                mma16816(sacc[j], qa[2*p+1], km2, km3);
                mma16816(sacc[j], qb[2*p+1], kh2, kh3);
            }
        }

        uint32_t pa[4][4];
#pragma unroll
        for (int j = 0; j < 8; j++){
            float pe[4];
#pragma unroll
            for (int e = 0; e < 2; e++){
                int c = j*8 + q2 + e;
                const float4* hp = (const float4*)(Hc + c*20);
                float4 f0 = hp[0], f1 = hp[1], f2 = hp[2], f3 = hp[3];
                float hv[16] = {f0.x,f0.y,f0.z,f0.w, f1.x,f1.y,f1.z,f1.w,
                                f2.x,f2.y,f2.z,f2.w, f3.x,f3.y,f3.z,f3.w};
                float v1c = Vc[c];
                float s0 = sacc[j][e]   + U1r0 - v1c;
                float s1 = sacc[j][2+e] + U1r1 - v1c;
#pragma unroll
                for (int jj = 0; jj < 16; jj++){
                    s0 = fmaf(ws[jj], fabsf(uq0[jj] - hv[jj]), s0);
                    s1 = fmaf(ws[jj], fabsf(uq1[jj] - hv[jj]), s1);
                }
                float e0 = exp2f(s0), e1 = exp2f(s1);
                l0 += e0; l1 += e1;
                pe[e] = e0; pe[2+e] = e1;
            }
            int tt2 = j >> 1, base = (j & 1)*2;
            __half2 P0 = __floats2half2_rn(pe[0], pe[1]);
            __half2 P1 = __floats2half2_rn(pe[2], pe[3]);
            pa[tt2][base]   = *(uint32_t*)&P0;
            pa[tt2][base+1] = *(uint32_t*)&P1;
        }

#pragma unroll
        for (int j2 = 0; j2 < 8; j2++){
#pragma unroll
            for (int p = 0; p < 2; p++){
                uint32_t vh0,vh1,vh2,vh3;
                ldm4(vh0,vh1,vh2,vh3, vh_a + j2*1152 + p*64);
                mma16816(oacc[j2], pa[2*p],   vh0, vh1);
                mma16816(oacc[j2], pa[2*p+1], vh2, vh3);
            }
        }
    }

    l0 += __shfl_xor_sync(0xffffffffu, l0, 1);
    l0 += __shfl_xor_sync(0xffffffffu, l0, 2);
    l1 += __shfl_xor_sync(0xffffffffu, l1, 1);
    l1 += __shfl_xor_sync(0xffffffffu, l1, 2);
    float inv0 = 1.f/l0, inv1 = 1.f/l1;
    size_t o0 = (size_t)(m*NQL + q0 + rl0)*DD + h*64;
    size_t o1 = o0 + 8*DD;
#pragma unroll
    for (int j2 = 0; j2 < 8; j2++){
        int c = j2*8 + q2;
        uint32_t hh, mm;
        hsplit2(oacc[j2][0]*inv0, oacc[j2][1]*inv0, hh, mm);
        *(uint32_t*)(Cth + o0 + c) = hh; *(uint32_t*)(Ctm + o0 + c) = mm;
        hsplit2(oacc[j2][2]*inv1, oacc[j2][3]*inv1, hh, mm);
        *(uint32_t*)(Cth + o1 + c) = hh; *(uint32_t*)(Ctm + o1 + c) = mm;
    }
}

// ---------------- host launcher ----------------
extern "C" void kernel_launch(void* const* d_in, const int* in_sizes, int n_in,
                              void* d_out, int out_size)
{
    const float* xq    = (const float*)d_in[0];
    const float* xk    = (const float*)d_in[1];
    const float* xv    = (const float*)d_in[2];
    const float* tq    = (const float*)d_in[3];
    const float* tk    = (const float*)d_in[4];
    const float* w_q   = (const float*)d_in[5];
    const float* w_k   = (const float*)d_in[6];
    const float* w_v   = (const float*)d_in[7];
    const float* w_out = (const float*)d_in[8];
    const float* b_out = (const float*)d_in[9];
    const float* kw1   = (const float*)d_in[10];
    const float* kb1   = (const float*)d_in[11];
    const float* kw2   = (const float*)d_in[12];
    const float* kb2   = (const float*)d_in[13];
    float* out = (float*)d_out;

    hf *xh,*xm,*wh,*wm,*qh,*qm,*kh,*km,*vth,*cth,*ctm;
    float *vf;
    cudaGetSymbolAddress((void**)&xh,  g_xh);
    cudaGetSymbolAddress((void**)&xm,  g_xm);
    cudaGetSymbolAddress((void**)&wh,  g_wh);
    cudaGetSymbolAddress((void**)&wm,  g_wm);
    cudaGetSymbolAddress((void**)&qh,  g_qh);
    cudaGetSymbolAddress((void**)&qm,  g_qm);
    cudaGetSymbolAddress((void**)&kh,  g_kh);
    cudaGetSymbolAddress((void**)&km,  g_km);
    cudaGetSymbolAddress((void**)&vf,  g_vf);
    cudaGetSymbolAddress((void**)&vth, g_vth);
    cudaGetSymbolAddress((void**)&cth, g_cth);
    cudaGetSymbolAddress((void**)&ctm, g_ctm);

    cudaFuncSetAttribute(qkv_proj, cudaFuncAttributeMaxDynamicSharedMemorySize, PJ_SMEM);
    cudaFuncSetAttribute(out_proj, cudaFuncAttributeMaxDynamicSharedMemorySize, PJ_SMEM);
    cudaFuncSetAttribute(attn_bf,  cudaFuncAttributeMaxDynamicSharedMemorySize, AT_SMEM);

    dim3 gp(N4/1024, 4);
    prep<<<gp, 256>>>(xq, xk, xv, w_q, w_k, w_v, w_out, xh, xm, wh, wm);

    dim3 gq(4, 64, 3);
    qkv_proj<<<gq,256,PJ_SMEM>>>(xh, xm, wh, wm, qh, qm, kh, km, vf);

    dim3 gv(32, 2, 64), tb(32,8);
    vtrans<<<gv,tb>>>(vf, vth);

    dim3 ga(8, HH, MBN);
    attn_bf<<<ga,256,AT_SMEM>>>(qh, qm, kh, km, vth,
                                tq, tk, kw1, kb1, kw2, kb2, cth, ctm);

    dim3 go(4, 64);
    out_proj<<<go,256,PJ_SMEM>>>(cth, ctm, wh+3*(size_t)DD*DD, wm+3*(size_t)DD*DD,
                                 b_out, out);
}

// round 15
// speedup vs baseline: 1.3877x; 1.1066x over previous
#include <cuda_runtime.h>
#include <cuda_fp16.h>
#include <cstdint>
#include <math.h>

typedef __half hf;

#define MBN   8
#define NQL   1024
#define NKVL  1024
#define HH    8
#define LOG2E 1.4426950408889634f
#define SCALE 0.125f
#define DD    512
#define N4    (MBN*NQL*DD)

__device__ hf    g_xh[3][N4], g_xm[3][N4];
__device__ hf    g_wh[4][DD*DD], g_wm[4][DD*DD];
__device__ hf    g_qh[N4], g_kh[N4];
__device__ float g_vf[N4];
__device__ hf    g_vth[N4];
__device__ hf    g_cth[N4], g_ctm[N4];

// ---------------- helpers ----------------
__device__ __forceinline__ uint32_t smem_u32(const void* p){
    uint32_t a;
    asm("{ .reg .u64 t; cvta.to.shared.u64 t, %1; cvt.u32.u64 %0, t; }":"=r"(a):"l"(p));
    return a;
}
__device__ __forceinline__ void cp16(uint32_t s, const void* g){
    asm volatile("cp.async.cg.shared.global [%0], [%1], 16;"::"r"(s),"l"(g));
}
#define CP_COMMIT() asm volatile("cp.async.commit_group;":::"memory")

__device__ __forceinline__ void mma16816(float* c, const uint32_t* a,
                                         uint32_t b0, uint32_t b1){
    asm volatile(
      "mma.sync.aligned.m16n8k16.row.col.f32.f16.f16.f32 "
      "{%0,%1,%2,%3}, {%4,%5,%6,%7}, {%8,%9}, {%0,%1,%2,%3};"
      : "+f"(c[0]), "+f"(c[1]), "+f"(c[2]), "+f"(c[3])
      : "r"(a[0]), "r"(a[1]), "r"(a[2]), "r"(a[3]), "r"(b0), "r"(b1));
}
__device__ __forceinline__ void ldm4(uint32_t& r0, uint32_t& r1,
                                     uint32_t& r2, uint32_t& r3, uint32_t a){
    asm volatile("ldmatrix.sync.aligned.m8n8.x4.shared.b16 {%0,%1,%2,%3}, [%4];"
      : "=r"(r0),"=r"(r1),"=r"(r2),"=r"(r3) : "r"(a));
}
__device__ __forceinline__ void hsplit2(float a, float b, uint32_t& h, uint32_t& m){
    hf ha = __float2half_rn(a), hb = __float2half_rn(b);
    hf ma = __float2half_rn(a - __half2float(ha));
    hf mb = __float2half_rn(b - __half2float(hb));
    __half2 H = __halves2half2(ha, hb), M = __halves2half2(ma, mb);
    h = *(uint32_t*)&H; m = *(uint32_t*)&M;
}

// ---------------- prep: xsplit (z<3) + wtrans (z==3) ----------------
__global__ void prep(const float* __restrict__ x0, const float* __restrict__ x1,
                     const float* __restrict__ x2,
                     const float* __restrict__ W0, const float* __restrict__ W1,
                     const float* __restrict__ W2, const float* __restrict__ W3,
                     hf* __restrict__ xh, hf* __restrict__ xm,
                     hf* __restrict__ Wh, hf* __restrict__ Wm){
    int z = blockIdx.y;
    if (z < 3){
        const float* x = (z == 0) ? x0 : (z == 1) ? x1 : x2;
        size_t base = (size_t)z * N4;
        int i = (blockIdx.x*256 + threadIdx.x)*4;
        float4 v = *(const float4*)(x + i);
        uint32_t h0,m0,h1,m1;
        hsplit2(v.x,v.y,h0,m0); hsplit2(v.z,v.w,h1,m1);
        *(uint32_t*)(xh+base+i) = h0; *(uint32_t*)(xh+base+i+2) = h1;
        *(uint32_t*)(xm+base+i) = m0; *(uint32_t*)(xm+base+i+2) = m1;
    } else {
        int bidx = blockIdx.x;
        if (bidx >= 1024) return;
        int w  = bidx >> 8;
        int tI = bidx & 255;
        const float* W = (w==0)?W0:(w==1)?W1:(w==2)?W2:W3;
        hf* wh = Wh + (size_t)w*DD*DD;
        hf* wm = Wm + (size_t)w*DD*DD;
        __shared__ float t[32][33];
        int n0 = (tI & 15)*32, k0 = (tI >> 4)*32;
        int tx = threadIdx.x & 31, ty = threadIdx.x >> 5;
#pragma unroll
        for (int i=0;i<32;i+=8) t[ty+i][tx] = W[(size_t)(k0+ty+i)*DD + n0+tx];
        __syncthreads();
#pragma unroll
        for (int i=0;i<32;i+=8){
            float v = t[tx][ty+i];
            hf hh = __float2half_rn(v);
            size_t idx = (size_t)(n0+ty+i)*DD + k0+tx;
            wh[idx] = hh;
            wm[idx] = __float2half_rn(v - __half2float(hh));
        }
    }
}

// ---------------- V f32 -> fp16 transposed ----------------
__global__ void vtrans(const float* __restrict__ V, hf* __restrict__ Vh){
    __shared__ float t[32][33];
    int z = blockIdx.z, m = z>>3, h = z&7;
    int kk0 = blockIdx.x*32, d0 = blockIdx.y*32;
    int tx = threadIdx.x, ty = threadIdx.y;
#pragma unroll
    for (int i=0;i<32;i+=8)
        t[ty+i][tx] = V[(size_t)(m*NKVL + kk0+ty+i)*DD + h*64 + d0+tx];
    __syncthreads();
#pragma unroll
    for (int i=0;i<32;i+=8){
        size_t idx = (size_t)(z*64 + d0+ty+i)*NKVL + kk0 + tx;
        Vh[idx] = __float2half_rn(t[tx][ty+i]);
    }
}

// ---------------- GEMM core macro ----------------
#define PSTG 40960
#define PJ_SMEM (2*PSTG)

#define PJ_ISSUE(kt, s) do{ \
    uint32_t st = sb + (s)*PSTG; int k0 = (kt)*32; \
    for (int i = tid; i < 512; i += 256){ \
        int r = i>>2; uint32_t ro = r*80 + (i&3)*16; int c8 = (i&3)*8; \
        size_t ga = (size_t)(bm+r)*DD + k0 + c8; \
        cp16(st + ro,         Ah + ga); \
        cp16(st + 10240 + ro, Am + ga); \
        size_t gb = (size_t)(bn+r)*DD + k0 + c8; \
        cp16(st + 20480 + ro, Bh + gb); \
        cp16(st + 30720 + ro, Bm + gb); \
    } CP_COMMIT(); }while(0)

#define PJ_MAINLOOP() \
    PJ_ISSUE(0, 0); \
    _Pragma("unroll 1") \
    for (int kt = 0; kt < 16; kt++){ \
        if (kt < 15){ \
            PJ_ISSUE(kt+1, (kt+1)&1); \
            asm volatile("cp.async.wait_group 1;":::"memory"); \
        } else { \
            asm volatile("cp.async.wait_group 0;":::"memory"); \
        } \
        __syncthreads(); \
        uint32_t sA  = sb + (kt&1)*PSTG; \
        uint32_t sAm = sA + 10240, sB = sA + 20480, sBm = sA + 30720; \
        _Pragma("unroll") \
        for (int ks = 0; ks < 2; ks++){ \
            uint32_t ah[4][4], am[4][4]; \
            _Pragma("unroll") \
            for (int mi = 0; mi < 4; mi++){ \
                uint32_t abase = (uint32_t)((wm + mi*16)*80 + ks*32) + aoffA; \
                ldm4(ah[mi][0],ah[mi][1],ah[mi][2],ah[mi][3], sA  + abase); \
                ldm4(am[mi][0],am[mi][1],am[mi][2],am[mi][3], sAm + abase); \
            } \
            _Pragma("unroll") \
            for (int njp = 0; njp < 2; njp++){ \
                uint32_t bbase = (uint32_t)((wn + njp*16)*80 + ks*32) + aoffB; \
                uint32_t bh0,bh1,bh2,bh3, bm0,bm1,bm2,bm3; \
                ldm4(bh0,bh1,bh2,bh3, sB  + bbase); \
                ldm4(bm0,bm1,bm2,bm3, sBm + bbase); \
                _Pragma("unroll") \
                for (int mi = 0; mi < 4; mi++){ \
                    mma16816(acc[mi][njp*2],   ah[mi], bh0, bh1); \
                    mma16816(acc[mi][njp*2],   ah[mi], bm0, bm1); \
                    mma16816(acc[mi][njp*2],   am[mi], bh0, bh1); \
                    mma16816(acc[mi][njp*2+1], ah[mi], bh2, bh3); \
                    mma16816(acc[mi][njp*2+1], ah[mi], bm2, bm3); \
                    mma16816(acc[mi][njp*2+1], am[mi], bh2, bh3); \
                } \
            } \
        } \
        __syncthreads(); \
    }

#define PJ_LANEOFF() \
    const uint32_t aoffA = (uint32_t)((lane & 7)*80 + ((lane >> 3) & 1)*640 \
                                      + (lane >> 4)*16); \
    const uint32_t aoffB = (uint32_t)((lane & 7)*80 + ((lane >> 3) & 1)*16 \
                                      + (lane >> 4)*640);

// ---------------- merged QKV projection (z = 0:Q 1:K 2:V) ----------------
__global__ void __launch_bounds__(256,2) qkv_proj(
    const hf* __restrict__ Xh, const hf* __restrict__ Xm,
    const hf* __restrict__ Wh, const hf* __restrict__ Wm,
    hf* __restrict__ Qh, hf* __restrict__ Kh, float* __restrict__ Vf)
{
    extern __shared__ char sp[];
    uint32_t sb = smem_u32(sp);
    const int tid = threadIdx.x, lane = tid & 31, wid = tid >> 5;
    const int ln4 = lane >> 2, q2 = (lane & 3)*2;
    const int wm = (wid & 1)*64, wn = (wid >> 1)*32;
    const int bm = blockIdx.y*128, bn = blockIdx.x*128;
    const int z = blockIdx.z;
    PJ_LANEOFF();
    const hf* Ah = Xh + (size_t)z*N4;
    const hf* Am = Xm + (size_t)z*N4;
    const hf* Bh = Wh + (size_t)z*DD*DD;
    const hf* Bm = Wm + (size_t)z*DD*DD;
    float acc[4][4][4];
#pragma unroll
    for (int a=0;a<4;a++)
#pragma unroll
      for (int b=0;b<4;b++)
#pragma unroll
        for (int c=0;c<4;c++) acc[a][b][c]=0.f;

    PJ_MAINLOOP();

    const float scale = (z == 0) ? SCALE*LOG2E : 1.0f;
#pragma unroll
    for (int mi = 0; mi < 4; mi++){
        int r0 = bm + wm + mi*16 + ln4;
#pragma unroll
        for (int nj = 0; nj < 4; nj++){
            int c = bn + wn + nj*8 + q2;
            float v0 = acc[mi][nj][0]*scale, v1 = acc[mi][nj][1]*scale;
            float v2 = acc[mi][nj][2]*scale, v3 = acc[mi][nj][3]*scale;
            if (z == 2){
                *(float2*)(Vf + (size_t)r0*DD + c)     = make_float2(v0, v1);
                *(float2*)(Vf + (size_t)(r0+8)*DD + c) = make_float2(v2, v3);
            } else {
                hf* Ch = (z == 0) ? Qh : Kh;
                __half2 H0 = __floats2half2_rn(v0, v1);
                __half2 H1 = __floats2half2_rn(v2, v3);
                *(uint32_t*)(Ch + (size_t)r0*DD + c)     = *(uint32_t*)&H0;
                *(uint32_t*)(Ch + (size_t)(r0+8)*DD + c) = *(uint32_t*)&H1;
            }
        }
    }
}

// ---------------- output projection ----------------
__global__ void __launch_bounds__(256,2) out_proj(
    const hf* __restrict__ Ah, const hf* __restrict__ Am,
    const hf* __restrict__ Bh, const hf* __restrict__ Bm,
    const float* __restrict__ bias, float* __restrict__ Cf)
{
    extern __shared__ char sp[];
    uint32_t sb = smem_u32(sp);
    const int tid = threadIdx.x, lane = tid & 31, wid = tid >> 5;
    const int ln4 = lane >> 2, q2 = (lane & 3)*2;
    const int wm = (wid & 1)*64, wn = (wid >> 1)*32;
    const int bm = blockIdx.y*128, bn = blockIdx.x*128;
    PJ_LANEOFF();
    float acc[4][4][4];
#pragma unroll
    for (int a=0;a<4;a++)
#pragma unroll
      for (int b=0;b<4;b++)
#pragma unroll
        for (int c=0;c<4;c++) acc[a][b][c]=0.f;

    PJ_MAINLOOP();

#pragma unroll
    for (int mi = 0; mi < 4; mi++){
        int r0 = bm + wm + mi*16 + ln4;
#pragma unroll
        for (int nj = 0; nj < 4; nj++){
            int c = bn + wn + nj*8 + q2;
            float b0 = bias[c], b1 = bias[c+1];
            *(float2*)(Cf + (size_t)r0*DD + c) =
                make_float2(acc[mi][nj][0] + b0, acc[mi][nj][1] + b1);
            *(float2*)(Cf + (size_t)(r0+8)*DD + c) =
                make_float2(acc[mi][nj][2] + b0, acc[mi][nj][3] + b1);
        }
    }
}

// ---------------- fused attention: fp16 single-pass QK ----------------
#define O_QH 0
#define O_KV 18432
#define KVSTG 18432
#define S_KH 0
#define S_VH 9216
#define O_HK (O_KV + 3*KVSTG)
#define HKSTG 5120
#define O_V1 (O_HK + 3*HKSTG)
#define AT_SMEM (O_V1 + 3*256)

__global__ void __launch_bounds__(256) attn_bf(
    const hf* __restrict__ Qh_g, const hf* __restrict__ Kh_g,
    const hf* __restrict__ Vh_g,
    const float* __restrict__ Tq, const float* __restrict__ Tk,
    const float* __restrict__ kw1, const float* __restrict__ kb1,
    const float* __restrict__ kw2, const float* __restrict__ kb2,
    hf* __restrict__ Cth, hf* __restrict__ Ctm)
{
    extern __shared__ char sp[];
    uint32_t sb = smem_u32(sp);

    const int tid = threadIdx.x, lane = tid & 31, wid = tid >> 5;
    const int ln4 = lane >> 2, q2 = (lane & 3)*2;
    const int m = blockIdx.z, h = blockIdx.y, q0 = blockIdx.x*128;
    const int rl0 = wid*16 + ln4;
    const uint32_t lmo = (uint32_t)((lane & 7)*144 + ((lane >> 3) >> 1)*32
                                    + ((lane >> 3) & 1)*16);

    for (int i = tid; i < 1024; i += 256){
        int r = i>>3; uint32_t ro = r*144 + (i&7)*16;
        size_t g = (size_t)(m*NQL+q0+r)*DD + h*64 + (i&7)*8;
        cp16(sb + O_QH + ro, Qh_g + g);
    }
#define KV_ISSUE(kk0, s) do{ \
    uint32_t st = sb + O_KV + (s)*KVSTG; \
    for (int i = tid; i < 512; i += 256){ \
        int r = i>>3; uint32_t ro = r*144 + (i&7)*16; int c8 = (i&7)*8; \
        size_t gk = (size_t)(m*NKVL + (kk0) + r)*DD + h*64 + c8; \
        cp16(st + S_KH + ro, Kh_g + gk); \
        size_t gv = (size_t)((m*HH+h)*64 + r)*NKVL + (kk0) + c8; \
        cp16(st + S_VH + ro, Vh_g + gv); \
    } CP_COMMIT(); }while(0)

#define HK_GEN(tile, s) do{ \
    if (tid < 64){ \
        float2 tk2 = *(const float2*)(Tk + (size_t)(m*NKVL + (tile)*64 + tid)*2); \
        float v1 = 0.f; \
        float* Hb = (float*)(sp + O_HK + (s)*HKSTG); \
        _Pragma("unroll") \
        for (int j = 0; j < 16; j++){ \
            float hk = tk2.x*kw1[j] + tk2.y*kw1[16+j]; \
            Hb[tid*20 + j] = hk; \
            v1 = fmaf(ws[j], hk, v1); \
        } \
        ((float*)(sp + O_V1))[(s)*64 + tid] = v1; \
    } }while(0)

    KV_ISSUE(0, 0);
    KV_ISSUE(64, 1);

    float ws[16], uq0[16], uq1[16];
    float2 ta = *(const float2*)(Tq + (size_t)(m*NQL + q0 + rl0)*2);
    float2 tb = *(const float2*)(Tq + (size_t)(m*NQL + q0 + rl0 + 8)*2);
    float U1r0 = (kb2[h] - 2.f)*LOG2E, U1r1 = U1r0;
#pragma unroll
    for (int j = 0; j < 16; j++){
        ws[j] = 0.5f*LOG2E*kw2[j*HH + h];
        float w0 = kw1[j], w1 = kw1[16+j], b = kb1[j];
        uq0[j] = ta.x*w0 + ta.y*w1 + b;
        uq1[j] = tb.x*w0 + tb.y*w1 + b;
        U1r0 = fmaf(ws[j], uq0[j], U1r0);
        U1r1 = fmaf(ws[j], uq1[j], U1r1);
    }
    HK_GEN(0, 0);
    HK_GEN(1, 1);

    asm volatile("cp.async.wait_group 1;":::"memory");
    __syncthreads();
    uint32_t qa[4][4];
    {
        const hf* Qh = (const hf*)(sp + O_QH);
#pragma unroll
        for (int ks = 0; ks < 4; ks++){
            int kb = ks*16 + q2;
            const hf* p = Qh + rl0*72 + kb;
            qa[ks][0]=*(const uint32_t*)p;     qa[ks][1]=*(const uint32_t*)(p+8*72);
            qa[ks][2]=*(const uint32_t*)(p+8); qa[ks][3]=*(const uint32_t*)(p+8*72+8);
        }
    }

    float oacc[8][4];
#pragma unroll
    for (int j=0;j<8;j++)
#pragma unroll
        for (int c=0;c<4;c++) oacc[j][c]=0.f;
    float l0 = 0.f, l1 = 0.f;

#pragma unroll 1
    for (int t = 0; t < 16; t++){
        if (t > 0){
            if (t < 15){
                asm volatile("cp.async.wait_group 1;":::"memory");
            } else {
                asm volatile("cp.async.wait_group 0;":::"memory");
            }
            __syncthreads();
        }
        if (t <= 13){
            int s2 = (t+2) % 3;
            KV_ISSUE((t+2)*64, s2);
            HK_GEN(t+2, s2);
        }
        const int scur = t % 3;
        const uint32_t stb = sb + O_KV + scur*KVSTG;
        const uint32_t kh_a = stb + S_KH + lmo;
        const uint32_t vh_a = stb + S_VH + lmo;
        const float* Hc = (const float*)(sp + O_HK + scur*HKSTG);
        const float* Vc = (const float*)(sp + O_V1) + scur*64;

        // ---- S = Q @ K^T, single-pass fp16 ----
        float sacc[8][4];
#pragma unroll
        for (int j = 0; j < 8; j++){
#pragma unroll
            for (int c = 0; c < 4; c++) sacc[j][c] = 0.f;
#pragma unroll
            for (int p = 0; p < 2; p++){
                uint32_t kh0,kh1,kh2,kh3;
                ldm4(kh0,kh1,kh2,kh3, kh_a + j*1152 + p*64);
                mma16816(sacc[j], qa[2*p],   kh0, kh1);
                mma16816(sacc[j], qa[2*p+1], kh2, kh3);
            }
        }

        // ---- bias + exp (2 chains per row for ILP) ----
        uint32_t pa[4][4];
#pragma unroll
        for (int j = 0; j < 8; j++){
            float pe[4];
#pragma unroll
            for (int e = 0; e < 2; e++){
                int c = j*8 + q2 + e;
                const float4* hp = (const float4*)(Hc + c*20);
                float4 f0 = hp[0], f1 = hp[1], f2 = hp[2], f3 = hp[3];
                float hv[16] = {f0.x,f0.y,f0.z,f0.w, f1.x,f1.y,f1.z,f1.w,
                                f2.x,f2.y,f2.z,f2.w, f3.x,f3.y,f3.z,f3.w};
                float v1c = Vc[c];
                float s0a = sacc[j][e]   + U1r0 - v1c, s0b = 0.f;
                float s1a = sacc[j][2+e] + U1r1 - v1c, s1b = 0.f;
#pragma unroll
                for (int jj = 0; jj < 8; jj++){
                    s0a = fmaf(ws[jj],   fabsf(uq0[jj]   - hv[jj]),   s0a);
                    s1a = fmaf(ws[jj],   fabsf(uq1[jj]   - hv[jj]),   s1a);
                    s0b = fmaf(ws[jj+8], fabsf(uq0[jj+8] - hv[jj+8]), s0b);
                    s1b = fmaf(ws[jj+8], fabsf(uq1[jj+8] - hv[jj+8]), s1b);
                }
                float e0 = exp2f(s0a + s0b), e1 = exp2f(s1a + s1b);
                l0 += e0; l1 += e1;
                pe[e] = e0; pe[2+e] = e1;
            }
            int tt2 = j >> 1, base = (j & 1)*2;
            __half2 P0 = __floats2half2_rn(pe[0], pe[1]);
            __half2 P1 = __floats2half2_rn(pe[2], pe[3]);
            pa[tt2][base]   = *(uint32_t*)&P0;
            pa[tt2][base+1] = *(uint32_t*)&P1;
        }

        // ---- O += P @ V^T, single-pass fp16 ----
#pragma unroll
        for (int j2 = 0; j2 < 8; j2++){
#pragma unroll
            for (int p = 0; p < 2; p++){
                uint32_t vh0,vh1,vh2,vh3;
                ldm4(vh0,vh1,vh2,vh3, vh_a + j2*1152 + p*64);
                mma16816(oacc[j2], pa[2*p],   vh0, vh1);
                mma16816(oacc[j2], pa[2*p+1], vh2, vh3);
            }
        }
    }

    l0 += __shfl_xor_sync(0xffffffffu, l0, 1);
    l0 += __shfl_xor_sync(0xffffffffu, l0, 2);
    l1 += __shfl_xor_sync(0xffffffffu, l1, 1);
    l1 += __shfl_xor_sync(0xffffffffu, l1, 2);
    float inv0 = 1.f/l0, inv1 = 1.f/l1;
    size_t o0 = (size_t)(m*NQL + q0 + rl0)*DD + h*64;
    size_t o1 = o0 + 8*DD;
#pragma unroll
    for (int j2 = 0; j2 < 8; j2++){
        int c = j2*8 + q2;
        uint32_t hh, mm;
        hsplit2(oacc[j2][0]*inv0, oacc[j2][1]*inv0, hh, mm);
        *(uint32_t*)(Cth + o0 + c) = hh; *(uint32_t*)(Ctm + o0 + c) = mm;
        hsplit2(oacc[j2][2]*inv1, oacc[j2][3]*inv1, hh, mm);
        *(uint32_t*)(Cth + o1 + c) = hh; *(uint32_t*)(Ctm + o1 + c) = mm;
    }
}

// ---------------- host launcher ----------------
extern "C" void kernel_launch(void* const* d_in, const int* in_sizes, int n_in,
                              void* d_out, int out_size)
{
    const float* xq    = (const float*)d_in[0];
    const float* xk    = (const float*)d_in[1];
    const float* xv    = (const float*)d_in[2];
    const float* tq    = (const float*)d_in[3];
    const float* tk    = (const float*)d_in[4];
    const float* w_q   = (const float*)d_in[5];
    const float* w_k   = (const float*)d_in[6];
    const float* w_v   = (const float*)d_in[7];
    const float* w_out = (const float*)d_in[8];
    const float* b_out = (const float*)d_in[9];
    const float* kw1   = (const float*)d_in[10];
    const float* kb1   = (const float*)d_in[11];
    const float* kw2   = (const float*)d_in[12];
    const float* kb2   = (const float*)d_in[13];
    float* out = (float*)d_out;

    hf *xh,*xm,*wh,*wm,*qh,*kh,*vth,*cth,*ctm;
    float *vf;
    cudaGetSymbolAddress((void**)&xh,  g_xh);
    cudaGetSymbolAddress((void**)&xm,  g_xm);
    cudaGetSymbolAddress((void**)&wh,  g_wh);
    cudaGetSymbolAddress((void**)&wm,  g_wm);
    cudaGetSymbolAddress((void**)&qh,  g_qh);
    cudaGetSymbolAddress((void**)&kh,  g_kh);
    cudaGetSymbolAddress((void**)&vf,  g_vf);
    cudaGetSymbolAddress((void**)&vth, g_vth);
    cudaGetSymbolAddress((void**)&cth, g_cth);
    cudaGetSymbolAddress((void**)&ctm, g_ctm);

    cudaFuncSetAttribute(qkv_proj, cudaFuncAttributeMaxDynamicSharedMemorySize, PJ_SMEM);
    cudaFuncSetAttribute(out_proj, cudaFuncAttributeMaxDynamicSharedMemorySize, PJ_SMEM);
    cudaFuncSetAttribute(attn_bf,  cudaFuncAttributeMaxDynamicSharedMemorySize, AT_SMEM);

    dim3 gp(N4/1024, 4);
    prep<<<gp, 256>>>(xq, xk, xv, w_q, w_k, w_v, w_out, xh, xm, wh, wm);

    dim3 gq(4, 64, 3);
    qkv_proj<<<gq,256,PJ_SMEM>>>(xh, xm, wh, wm, qh, kh, vf);

    dim3 gv(32, 2, 64), tb(32,8);
    vtrans<<<gv,tb>>>(vf, vth);

    dim3 ga(8, HH, MBN);
    attn_bf<<<ga,256,AT_SMEM>>>(qh, kh, vth,
                                tq, tk, kw1, kb1, kw2, kb2, cth, ctm);

    dim3 go(4, 64);
    out_proj<<<go,256,PJ_SMEM>>>(cth, ctm, wh+3*(size_t)DD*DD, wm+3*(size_t)DD*DD,
                                 b_out, out);
}

// round 16
// speedup vs baseline: 1.4002x; 1.0090x over previous
#include <cuda_runtime.h>
#include <cuda_fp16.h>
#include <cstdint>
#include <math.h>

typedef __half hf;

#define MBN   8
#define NQL   1024
#define NKVL  1024
#define HH    8
#define LOG2E 1.4426950408889634f
#define SCALE 0.125f
#define DD    512
#define N4    (MBN*NQL*DD)

__device__ hf    g_xh[3][N4], g_xm[3][N4];
__device__ hf    g_wh[4][DD*DD], g_wm[4][DD*DD];
__device__ hf    g_qh[N4], g_kh[N4];
__device__ float g_vf[N4];
__device__ hf    g_vth[N4];
__device__ hf    g_cth[N4], g_ctm[N4];
__device__ hf    g_bias[(size_t)MBN*HH*NQL*NKVL];   // 134 MB pairwise bias

// ---------------- helpers ----------------
__device__ __forceinline__ uint32_t smem_u32(const void* p){
    uint32_t a;
    asm("{ .reg .u64 t; cvta.to.shared.u64 t, %1; cvt.u32.u64 %0, t; }":"=r"(a):"l"(p));
    return a;
}
__device__ __forceinline__ void cp16(uint32_t s, const void* g){
    asm volatile("cp.async.cg.shared.global [%0], [%1], 16;"::"r"(s),"l"(g));
}
#define CP_COMMIT() asm volatile("cp.async.commit_group;":::"memory")

__device__ __forceinline__ void mma16816(float* c, const uint32_t* a,
                                         uint32_t b0, uint32_t b1){
    asm volatile(
      "mma.sync.aligned.m16n8k16.row.col.f32.f16.f16.f32 "
      "{%0,%1,%2,%3}, {%4,%5,%6,%7}, {%8,%9}, {%0,%1,%2,%3};"
      : "+f"(c[0]), "+f"(c[1]), "+f"(c[2]), "+f"(c[3])
      : "r"(a[0]), "r"(a[1]), "r"(a[2]), "r"(a[3]), "r"(b0), "r"(b1));
}
__device__ __forceinline__ void ldm4(uint32_t& r0, uint32_t& r1,
                                     uint32_t& r2, uint32_t& r3, uint32_t a){
    asm volatile("ldmatrix.sync.aligned.m8n8.x4.shared.b16 {%0,%1,%2,%3}, [%4];"
      : "=r"(r0),"=r"(r1),"=r"(r2),"=r"(r3) : "r"(a));
}
__device__ __forceinline__ void hsplit2(float a, float b, uint32_t& h, uint32_t& m){
    hf ha = __float2half_rn(a), hb = __float2half_rn(b);
    hf ma = __float2half_rn(a - __half2float(ha));
    hf mb = __float2half_rn(b - __half2float(hb));
    __half2 H = __halves2half2(ha, hb), M = __halves2half2(ma, mb);
    h = *(uint32_t*)&H; m = *(uint32_t*)&M;
}

// ---------------- prep: xsplit (z<3) + wtrans (z==3) ----------------
__global__ void prep(const float* __restrict__ x0, const float* __restrict__ x1,
                     const float* __restrict__ x2,
                     const float* __restrict__ W0, const float* __restrict__ W1,
                     const float* __restrict__ W2, const float* __restrict__ W3,
                     hf* __restrict__ xh, hf* __restrict__ xm,
                     hf* __restrict__ Wh, hf* __restrict__ Wm){
    int z = blockIdx.y;
    if (z < 3){
        const float* x = (z == 0) ? x0 : (z == 1) ? x1 : x2;
        size_t base = (size_t)z * N4;
        int i = (blockIdx.x*256 + threadIdx.x)*4;
        float4 v = *(const float4*)(x + i);
        uint32_t h0,m0,h1,m1;
        hsplit2(v.x,v.y,h0,m0); hsplit2(v.z,v.w,h1,m1);
        *(uint32_t*)(xh+base+i) = h0; *(uint32_t*)(xh+base+i+2) = h1;
        *(uint32_t*)(xm+base+i) = m0; *(uint32_t*)(xm+base+i+2) = m1;
    } else {
        int bidx = blockIdx.x;
        if (bidx >= 1024) return;
        int w  = bidx >> 8;
        int tI = bidx & 255;
        const float* W = (w==0)?W0:(w==1)?W1:(w==2)?W2:W3;
        hf* wh = Wh + (size_t)w*DD*DD;
        hf* wm = Wm + (size_t)w*DD*DD;
        __shared__ float t[32][33];
        int n0 = (tI & 15)*32, k0 = (tI >> 4)*32;
        int tx = threadIdx.x & 31, ty = threadIdx.x >> 5;
#pragma unroll
        for (int i=0;i<32;i+=8) t[ty+i][tx] = W[(size_t)(k0+ty+i)*DD + n0+tx];
        __syncthreads();
#pragma unroll
        for (int i=0;i<32;i+=8){
            float v = t[tx][ty+i];
            hf hh = __float2half_rn(v);
            size_t idx = (size_t)(n0+ty+i)*DD + k0+tx;
            wh[idx] = hh;
            wm[idx] = __float2half_rn(v - __half2float(hh));
        }
    }
}

// ---------------- pairwise bias precompute (head-factored) ----------------
// Bg[m][h][q][k] = LOG2E * sum_j kw2[j][h] * relu(uq[q][j] - hv[k][j])
// (per-(q,h) constants kb2, shifts cancel in softmax and are omitted)
__global__ void __launch_bounds__(128) bias_pre(
    const float* __restrict__ Tq, const float* __restrict__ Tk,
    const float* __restrict__ kw1, const float* __restrict__ kb1,
    const float* __restrict__ kw2, hf* __restrict__ Bg)
{
    const int q = blockIdx.x, m = blockIdx.y;
    const int tid = threadIdx.x;          // k-octet 0..127
    __shared__ float w2s[8][16];
    for (int i = tid; i < 128; i += 128)
        w2s[i>>4][i&15] = kw2[(i&15)*HH + (i>>4)] * LOG2E;
    __syncthreads();

    float k1a[16], k1b[16], uq[16];
    float2 tq = *(const float2*)(Tq + (size_t)(m*NQL+q)*2);
#pragma unroll
    for (int j = 0; j < 16; j++){
        k1a[j] = kw1[j]; k1b[j] = kw1[16+j];
        uq[j] = tq.x*k1a[j] + tq.y*k1b[j] + kb1[j];
    }
    float bt[8][8];   // [h][ko]
#pragma unroll
    for (int ko = 0; ko < 8; ko++){
        int k = tid*8 + ko;
        float2 tk = *(const float2*)(Tk + (size_t)(m*NKVL+k)*2);
        float r[16];
#pragma unroll
        for (int j = 0; j < 16; j++)
            r[j] = fmaxf(uq[j] - (tk.x*k1a[j] + tk.y*k1b[j]), 0.f);
#pragma unroll
        for (int h = 0; h < 8; h++){
            float s = 0.f;
#pragma unroll
            for (int j = 0; j < 16; j++) s = fmaf(w2s[h][j], r[j], s);
            bt[h][ko] = s;
        }
    }
#pragma unroll
    for (int h = 0; h < 8; h++){
        __half2 o[4];
#pragma unroll
        for (int p = 0; p < 4; p++)
            o[p] = __floats2half2_rn(bt[h][2*p], bt[h][2*p+1]);
        *(uint4*)(Bg + ((size_t)(m*HH+h)*NQL + q)*NKVL + tid*8) = *(uint4*)o;
    }
}

// ---------------- V f32 -> fp16 transposed ----------------
__global__ void vtrans(const float* __restrict__ V, hf* __restrict__ Vh){
    __shared__ float t[32][33];
    int z = blockIdx.z, m = z>>3, h = z&7;
    int kk0 = blockIdx.x*32, d0 = blockIdx.y*32;
    int tx = threadIdx.x, ty = threadIdx.y;
#pragma unroll
    for (int i=0;i<32;i+=8)
        t[ty+i][tx] = V[(size_t)(m*NKVL + kk0+ty+i)*DD + h*64 + d0+tx];
    __syncthreads();
#pragma unroll
    for (int i=0;i<32;i+=8){
        size_t idx = (size_t)(z*64 + d0+ty+i)*NKVL + kk0 + tx;
        Vh[idx] = __float2half_rn(t[tx][ty+i]);
    }
}

// ---------------- GEMM core macro ----------------
#define PSTG 40960
#define PJ_SMEM (2*PSTG)

#define PJ_ISSUE(kt, s) do{ \
    uint32_t st = sb + (s)*PSTG; int k0 = (kt)*32; \
    for (int i = tid; i < 512; i += 256){ \
        int r = i>>2; uint32_t ro = r*80 + (i&3)*16; int c8 = (i&3)*8; \
        size_t ga = (size_t)(bm+r)*DD + k0 + c8; \
        cp16(st + ro,         Ah + ga); \
        cp16(st + 10240 + ro, Am + ga); \
        size_t gb = (size_t)(bn+r)*DD + k0 + c8; \
        cp16(st + 20480 + ro, Bh + gb); \
        cp16(st + 30720 + ro, Bm + gb); \
    } CP_COMMIT(); }while(0)

#define PJ_MAINLOOP() \
    PJ_ISSUE(0, 0); \
    _Pragma("unroll 1") \
    for (int kt = 0; kt < 16; kt++){ \
        if (kt < 15){ \
            PJ_ISSUE(kt+1, (kt+1)&1); \
            asm volatile("cp.async.wait_group 1;":::"memory"); \
        } else { \
            asm volatile("cp.async.wait_group 0;":::"memory"); \
        } \
        __syncthreads(); \
        uint32_t sA  = sb + (kt&1)*PSTG; \
        uint32_t sAm = sA + 10240, sB = sA + 20480, sBm = sA + 30720; \
        _Pragma("unroll") \
        for (int ks = 0; ks < 2; ks++){ \
            uint32_t ah[4][4], am[4][4]; \
            _Pragma("unroll") \
            for (int mi = 0; mi < 4; mi++){ \
                uint32_t abase = (uint32_t)((wm + mi*16)*80 + ks*32) + aoffA; \
                ldm4(ah[mi][0],ah[mi][1],ah[mi][2],ah[mi][3], sA  + abase); \
                ldm4(am[mi][0],am[mi][1],am[mi][2],am[mi][3], sAm + abase); \
            } \
            _Pragma("unroll") \
            for (int njp = 0; njp < 2; njp++){ \
                uint32_t bbase = (uint32_t)((wn + njp*16)*80 + ks*32) + aoffB; \
                uint32_t bh0,bh1,bh2,bh3, bm0,bm1,bm2,bm3; \
                ldm4(bh0,bh1,bh2,bh3, sB  + bbase); \
                ldm4(bm0,bm1,bm2,bm3, sBm + bbase); \
                _Pragma("unroll") \
                for (int mi = 0; mi < 4; mi++){ \
                    mma16816(acc[mi][njp*2],   ah[mi], bh0, bh1); \
                    mma16816(acc[mi][njp*2],   ah[mi], bm0, bm1); \
                    mma16816(acc[mi][njp*2],   am[mi], bh0, bh1); \
                    mma16816(acc[mi][njp*2+1], ah[mi], bh2, bh3); \
                    mma16816(acc[mi][njp*2+1], ah[mi], bm2, bm3); \
                    mma16816(acc[mi][njp*2+1], am[mi], bh2, bh3); \
                } \
            } \
        } \
        __syncthreads(); \
    }

#define PJ_LANEOFF() \
    const uint32_t aoffA = (uint32_t)((lane & 7)*80 + ((lane >> 3) & 1)*640 \
                                      + (lane >> 4)*16); \
    const uint32_t aoffB = (uint32_t)((lane & 7)*80 + ((lane >> 3) & 1)*16 \
                                      + (lane >> 4)*640);

// ---------------- merged QKV projection (z = 0:Q 1:K 2:V) ----------------
__global__ void __launch_bounds__(256,2) qkv_proj(
    const hf* __restrict__ Xh, const hf* __restrict__ Xm,
    const hf* __restrict__ Wh, const hf* __restrict__ Wm,
    hf* __restrict__ Qh, hf* __restrict__ Kh, float* __restrict__ Vf)
{
    extern __shared__ char sp[];
    uint32_t sb = smem_u32(sp);
    const int tid = threadIdx.x, lane = tid & 31, wid = tid >> 5;
    const int ln4 = lane >> 2, q2 = (lane & 3)*2;
    const int wm = (wid & 1)*64, wn = (wid >> 1)*32;
    const int bm = blockIdx.y*128, bn = blockIdx.x*128;
    const int z = blockIdx.z;
    PJ_LANEOFF();
    const hf* Ah = Xh + (size_t)z*N4;
    const hf* Am = Xm + (size_t)z*N4;
    const hf* Bh = Wh + (size_t)z*DD*DD;
    const hf* Bm = Wm + (size_t)z*DD*DD;
    float acc[4][4][4];
#pragma unroll
    for (int a=0;a<4;a++)
#pragma unroll
      for (int b=0;b<4;b++)
#pragma unroll
        for (int c=0;c<4;c++) acc[a][b][c]=0.f;

    PJ_MAINLOOP();

    const float scale = (z == 0) ? SCALE*LOG2E : 1.0f;
#pragma unroll
    for (int mi = 0; mi < 4; mi++){
        int r0 = bm + wm + mi*16 + ln4;
#pragma unroll
        for (int nj = 0; nj < 4; nj++){
            int c = bn + wn + nj*8 + q2;
            float v0 = acc[mi][nj][0]*scale, v1 = acc[mi][nj][1]*scale;
            float v2 = acc[mi][nj][2]*scale, v3 = acc[mi][nj][3]*scale;
            if (z == 2){
                *(float2*)(Vf + (size_t)r0*DD + c)     = make_float2(v0, v1);
                *(float2*)(Vf + (size_t)(r0+8)*DD + c) = make_float2(v2, v3);
            } else {
                hf* Ch = (z == 0) ? Qh : Kh;
                __half2 H0 = __floats2half2_rn(v0, v1);
                __half2 H1 = __floats2half2_rn(v2, v3);
                *(uint32_t*)(Ch + (size_t)r0*DD + c)     = *(uint32_t*)&H0;
                *(uint32_t*)(Ch + (size_t)(r0+8)*DD + c) = *(uint32_t*)&H1;
            }
        }
    }
}

// ---------------- output projection ----------------
__global__ void __launch_bounds__(256,2) out_proj(
    const hf* __restrict__ Ah, const hf* __restrict__ Am,
    const hf* __restrict__ Bh, const hf* __restrict__ Bm,
    const float* __restrict__ bias, float* __restrict__ Cf)
{
    extern __shared__ char sp[];
    uint32_t sb = smem_u32(sp);
    const int tid = threadIdx.x, lane = tid & 31, wid = tid >> 5;
    const int ln4 = lane >> 2, q2 = (lane & 3)*2;
    const int wm = (wid & 1)*64, wn = (wid >> 1)*32;
    const int bm = blockIdx.y*128, bn = blockIdx.x*128;
    PJ_LANEOFF();
    float acc[4][4][4];
#pragma unroll
    for (int a=0;a<4;a++)
#pragma unroll
      for (int b=0;b<4;b++)
#pragma unroll
        for (int c=0;c<4;c++) acc[a][b][c]=0.f;

    PJ_MAINLOOP();

#pragma unroll
    for (int mi = 0; mi < 4; mi++){
        int r0 = bm + wm + mi*16 + ln4;
#pragma unroll
        for (int nj = 0; nj < 4; nj++){
            int c = bn + wn + nj*8 + q2;
            float b0 = bias[c], b1 = bias[c+1];
            *(float2*)(Cf + (size_t)r0*DD + c) =
                make_float2(acc[mi][nj][0] + b0, acc[mi][nj][1] + b1);
            *(float2*)(Cf + (size_t)(r0+8)*DD + c) =
                make_float2(acc[mi][nj][2] + b0, acc[mi][nj][3] + b1);
        }
    }
}

// ---------------- fused attention: precomputed bias, fp16 single-pass -------
#define O_QH 0
#define O_KV 18432
#define KVSTG 36864
#define S_KH 0
#define S_VH 9216
#define S_B  18432
#define AT_SMEM (O_KV + 3*KVSTG)

__global__ void __launch_bounds__(256) attn_bf(
    const hf* __restrict__ Qh_g, const hf* __restrict__ Kh_g,
    const hf* __restrict__ Vh_g, const hf* __restrict__ Bg,
    hf* __restrict__ Cth, hf* __restrict__ Ctm)
{
    extern __shared__ char sp[];
    uint32_t sb = smem_u32(sp);

    const int tid = threadIdx.x, lane = tid & 31, wid = tid >> 5;
    const int ln4 = lane >> 2, q2 = (lane & 3)*2;
    const int m = blockIdx.z, h = blockIdx.y, q0 = blockIdx.x*128;
    const int rl0 = wid*16 + ln4;
    const uint32_t lmo = (uint32_t)((lane & 7)*144 + ((lane >> 3) >> 1)*32
                                    + ((lane >> 3) & 1)*16);
    const hf* Bpl = Bg + ((size_t)(m*HH+h)*NQL)*NKVL;

    for (int i = tid; i < 1024; i += 256){
        int r = i>>3; uint32_t ro = r*144 + (i&7)*16;
        size_t g = (size_t)(m*NQL+q0+r)*DD + h*64 + (i&7)*8;
        cp16(sb + O_QH + ro, Qh_g + g);
    }
#define KV_ISSUE(kk0, s) do{ \
    uint32_t st = sb + O_KV + (s)*KVSTG; \
    for (int i = tid; i < 1024; i += 256){ \
        int r = i>>3; uint32_t ro = r*144 + (i&7)*16; int c8 = (i&7)*8; \
        if (i < 512){ \
            size_t gk = (size_t)(m*NKVL + (kk0) + r)*DD + h*64 + c8; \
            cp16(st + S_KH + ro, Kh_g + gk); \
            size_t gv = (size_t)((m*HH+h)*64 + r)*NKVL + (kk0) + c8; \
            cp16(st + S_VH + ro, Vh_g + gv); \
        } \
        cp16(st + S_B + ro, Bpl + (size_t)(q0+r)*NKVL + (kk0) + c8); \
    } CP_COMMIT(); }while(0)

    KV_ISSUE(0, 0);
    KV_ISSUE(64, 1);

    asm volatile("cp.async.wait_group 1;":::"memory");
    __syncthreads();
    uint32_t qa[4][4];
    {
        const hf* Qh = (const hf*)(sp + O_QH);
#pragma unroll
        for (int ks = 0; ks < 4; ks++){
            int kb = ks*16 + q2;
            const hf* p = Qh + rl0*72 + kb;
            qa[ks][0]=*(const uint32_t*)p;     qa[ks][1]=*(const uint32_t*)(p+8*72);
            qa[ks][2]=*(const uint32_t*)(p+8); qa[ks][3]=*(const uint32_t*)(p+8*72+8);
        }
    }

    float oacc[8][4];
#pragma unroll
    for (int j=0;j<8;j++)
#pragma unroll
        for (int c=0;c<4;c++) oacc[j][c]=0.f;
    float l0 = 0.f, l1 = 0.f;

#pragma unroll 1
    for (int t = 0; t < 16; t++){
        if (t > 0){
            if (t < 15){
                asm volatile("cp.async.wait_group 1;":::"memory");
            } else {
                asm volatile("cp.async.wait_group 0;":::"memory");
            }
            __syncthreads();
        }
        if (t <= 13){
            KV_ISSUE((t+2)*64, (t+2) % 3);
        }
        const int scur = t % 3;
        const uint32_t stb = sb + O_KV + scur*KVSTG;
        const uint32_t kh_a = stb + S_KH + lmo;
        const uint32_t vh_a = stb + S_VH + lmo;
        const char* Bst = sp + O_KV + scur*KVSTG + S_B;

        // ---- S = Q @ K^T, single-pass fp16 ----
        float sacc[8][4];
#pragma unroll
        for (int j = 0; j < 8; j++){
#pragma unroll
            for (int c = 0; c < 4; c++) sacc[j][c] = 0.f;
#pragma unroll
            for (int p = 0; p < 2; p++){
                uint32_t kh0,kh1,kh2,kh3;
                ldm4(kh0,kh1,kh2,kh3, kh_a + j*1152 + p*64);
                mma16816(sacc[j], qa[2*p],   kh0, kh1);
                mma16816(sacc[j], qa[2*p+1], kh2, kh3);
            }
        }

        // ---- s = sacc + bias(loaded); exp2; pack P ----
        uint32_t pa[4][4];
#pragma unroll
        for (int j = 0; j < 8; j++){
            int c = j*8 + q2;
            __half2 b0 = *(const __half2*)(Bst + rl0*144 + c*2);
            __half2 b1 = *(const __half2*)(Bst + (rl0+8)*144 + c*2);
            float2 f0 = __half22float2(b0), f1 = __half22float2(b1);
            float e0 = exp2f(sacc[j][0] + f0.x);
            float e1 = exp2f(sacc[j][1] + f0.y);
            float e2 = exp2f(sacc[j][2] + f1.x);
            float e3 = exp2f(sacc[j][3] + f1.y);
            l0 += e0 + e1; l1 += e2 + e3;
            int tt2 = j >> 1, base = (j & 1)*2;
            __half2 P0 = __floats2half2_rn(e0, e1);
            __half2 P1 = __floats2half2_rn(e2, e3);
            pa[tt2][base]   = *(uint32_t*)&P0;
            pa[tt2][base+1] = *(uint32_t*)&P1;
        }

        // ---- O += P @ V^T, single-pass fp16 ----
#pragma unroll
        for (int j2 = 0; j2 < 8; j2++){
#pragma unroll
            for (int p = 0; p < 2; p++){
                uint32_t vh0,vh1,vh2,vh3;
                ldm4(vh0,vh1,vh2,vh3, vh_a + j2*1152 + p*64);
                mma16816(oacc[j2], pa[2*p],   vh0, vh1);
                mma16816(oacc[j2], pa[2*p+1], vh2, vh3);
            }
        }
    }

    l0 += __shfl_xor_sync(0xffffffffu, l0, 1);
    l0 += __shfl_xor_sync(0xffffffffu, l0, 2);
    l1 += __shfl_xor_sync(0xffffffffu, l1, 1);
    l1 += __shfl_xor_sync(0xffffffffu, l1, 2);
    float inv0 = 1.f/l0, inv1 = 1.f/l1;
    size_t o0 = (size_t)(m*NQL + q0 + rl0)*DD + h*64;
    size_t o1 = o0 + 8*DD;
#pragma unroll
    for (int j2 = 0; j2 < 8; j2++){
        int c = j2*8 + q2;
        uint32_t hh, mm;
        hsplit2(oacc[j2][0]*inv0, oacc[j2][1]*inv0, hh, mm);
        *(uint32_t*)(Cth + o0 + c) = hh; *(uint32_t*)(Ctm + o0 + c) = mm;
        hsplit2(oacc[j2][2]*inv1, oacc[j2][3]*inv1, hh, mm);
        *(uint32_t*)(Cth + o1 + c) = hh; *(uint32_t*)(Ctm + o1 + c) = mm;
    }
}

// ---------------- host launcher ----------------
extern "C" void kernel_launch(void* const* d_in, const int* in_sizes, int n_in,
                              void* d_out, int out_size)
{
    const float* xq    = (const float*)d_in[0];
    const float* xk    = (const float*)d_in[1];
    const float* xv    = (const float*)d_in[2];
    const float* tq    = (const float*)d_in[3];
    const float* tk    = (const float*)d_in[4];
    const float* w_q   = (const float*)d_in[5];
    const float* w_k   = (const float*)d_in[6];
    const float* w_v   = (const float*)d_in[7];
    const float* w_out = (const float*)d_in[8];
    const float* b_out = (const float*)d_in[9];
    const float* kw1   = (const float*)d_in[10];
    const float* kb1   = (const float*)d_in[11];
    const float* kw2   = (const float*)d_in[12];
    const float* kb2   = (const float*)d_in[13];
    float* out = (float*)d_out;
    (void)kb2;   // cancels in softmax

    hf *xh,*xm,*wh,*wm,*qh,*kh,*vth,*cth,*ctm,*bp;
    float *vf;
    cudaGetSymbolAddress((void**)&xh,  g_xh);
    cudaGetSymbolAddress((void**)&xm,  g_xm);
    cudaGetSymbolAddress((void**)&wh,  g_wh);
    cudaGetSymbolAddress((void**)&wm,  g_wm);
    cudaGetSymbolAddress((void**)&qh,  g_qh);
    cudaGetSymbolAddress((void**)&kh,  g_kh);
    cudaGetSymbolAddress((void**)&vf,  g_vf);
    cudaGetSymbolAddress((void**)&vth, g_vth);
    cudaGetSymbolAddress((void**)&cth, g_cth);
    cudaGetSymbolAddress((void**)&ctm, g_ctm);
    cudaGetSymbolAddress((void**)&bp,  g_bias);

    cudaFuncSetAttribute(qkv_proj, cudaFuncAttributeMaxDynamicSharedMemorySize, PJ_SMEM);
    cudaFuncSetAttribute(out_proj, cudaFuncAttributeMaxDynamicSharedMemorySize, PJ_SMEM);
    cudaFuncSetAttribute(attn_bf,  cudaFuncAttributeMaxDynamicSharedMemorySize, AT_SMEM);

    dim3 gp(N4/1024, 4);
    prep<<<gp, 256>>>(xq, xk, xv, w_q, w_k, w_v, w_out, xh, xm, wh, wm);

    dim3 gb(NQL, MBN);
    bias_pre<<<gb, 128>>>(tq, tk, kw1, kb1, kw2, bp);

    dim3 gq(4, 64, 3);
    qkv_proj<<<gq,256,PJ_SMEM>>>(xh, xm, wh, wm, qh, kh, vf);

    dim3 gv(32, 2, 64), tb(32,8);
    vtrans<<<gv,tb>>>(vf, vth);

    dim3 ga(8, HH, MBN);
    attn_bf<<<ga,256,AT_SMEM>>>(qh, kh, vth, bp, cth, ctm);

    dim3 go(4, 64);
    out_proj<<<go,256,PJ_SMEM>>>(cth, ctm, wh+3*(size_t)DD*DD, wm+3*(size_t)DD*DD,
                                 b_out, out);
}

// round 17
// speedup vs baseline: 1.6684x; 1.1915x over previous
#include <cuda_runtime.h>
#include <cuda_fp16.h>
#include <cstdint>
#include <math.h>

typedef __half hf;

#define MBN   8
#define NQL   1024
#define NKVL  1024
#define HH    8
#define LOG2E 1.4426950408889634f
#define SCALE 0.125f
#define DD    512
#define N4    (MBN*NQL*DD)

__device__ hf    g_xh[3][N4], g_xm[3][N4];
__device__ hf    g_wh[4][DD*DD], g_wm[4][DD*DD];
__device__ hf    g_qh[N4], g_kh[N4];
__device__ float g_vf[N4];
__device__ hf    g_vth[N4];
__device__ hf    g_cth[N4];
__device__ hf    g_bias[(size_t)MBN*HH*NQL*NKVL];

// ---------------- helpers ----------------
__device__ __forceinline__ uint32_t smem_u32(const void* p){
    uint32_t a;
    asm("{ .reg .u64 t; cvta.to.shared.u64 t, %1; cvt.u32.u64 %0, t; }":"=r"(a):"l"(p));
    return a;
}
__device__ __forceinline__ void cp16(uint32_t s, const void* g){
    asm volatile("cp.async.cg.shared.global [%0], [%1], 16;"::"r"(s),"l"(g));
}
#define CP_COMMIT() asm volatile("cp.async.commit_group;":::"memory")

__device__ __forceinline__ void mma16816(float* c, const uint32_t* a,
                                         uint32_t b0, uint32_t b1){
    asm volatile(
      "mma.sync.aligned.m16n8k16.row.col.f32.f16.f16.f32 "
      "{%0,%1,%2,%3}, {%4,%5,%6,%7}, {%8,%9}, {%0,%1,%2,%3};"
      : "+f"(c[0]), "+f"(c[1]), "+f"(c[2]), "+f"(c[3])
      : "r"(a[0]), "r"(a[1]), "r"(a[2]), "r"(a[3]), "r"(b0), "r"(b1));
}
__device__ __forceinline__ void ldm4(uint32_t& r0, uint32_t& r1,
                                     uint32_t& r2, uint32_t& r3, uint32_t a){
    asm volatile("ldmatrix.sync.aligned.m8n8.x4.shared.b16 {%0,%1,%2,%3}, [%4];"
      : "=r"(r0),"=r"(r1),"=r"(r2),"=r"(r3) : "r"(a));
}
__device__ __forceinline__ void hsplit2(float a, float b, uint32_t& h, uint32_t& m){
    hf ha = __float2half_rn(a), hb = __float2half_rn(b);
    hf ma = __float2half_rn(a - __half2float(ha));
    hf mb = __float2half_rn(b - __half2float(hb));
    __half2 H = __halves2half2(ha, hb), M = __halves2half2(ma, mb);
    h = *(uint32_t*)&H; m = *(uint32_t*)&M;
}

// ---------------- prep: xsplit (z<3) + wtrans (z==3) ----------------
__global__ void prep(const float* __restrict__ x0, const float* __restrict__ x1,
                     const float* __restrict__ x2,
                     const float* __restrict__ W0, const float* __restrict__ W1,
                     const float* __restrict__ W2, const float* __restrict__ W3,
                     hf* __restrict__ xh, hf* __restrict__ xm,
                     hf* __restrict__ Wh, hf* __restrict__ Wm){
    int z = blockIdx.y;
    if (z < 3){
        const float* x = (z == 0) ? x0 : (z == 1) ? x1 : x2;
        size_t base = (size_t)z * N4;
        int i = (blockIdx.x*256 + threadIdx.x)*4;
        float4 v = *(const float4*)(x + i);
        uint32_t h0,m0,h1,m1;
        hsplit2(v.x,v.y,h0,m0); hsplit2(v.z,v.w,h1,m1);
        *(uint32_t*)(xh+base+i) = h0; *(uint32_t*)(xh+base+i+2) = h1;
        *(uint32_t*)(xm+base+i) = m0; *(uint32_t*)(xm+base+i+2) = m1;
    } else {
        int bidx = blockIdx.x;
        if (bidx >= 1024) return;
        int w  = bidx >> 8;
        int tI = bidx & 255;
        const float* W = (w==0)?W0:(w==1)?W1:(w==2)?W2:W3;
        hf* wh = Wh + (size_t)w*DD*DD;
        hf* wm = Wm + (size_t)w*DD*DD;
        __shared__ float t[32][33];
        int n0 = (tI & 15)*32, k0 = (tI >> 4)*32;
        int tx = threadIdx.x & 31, ty = threadIdx.x >> 5;
#pragma unroll
        for (int i=0;i<32;i+=8) t[ty+i][tx] = W[(size_t)(k0+ty+i)*DD + n0+tx];
        __syncthreads();
#pragma unroll
        for (int i=0;i<32;i+=8){
            float v = t[tx][ty+i];
            hf hh = __float2half_rn(v);
            size_t idx = (size_t)(n0+ty+i)*DD + k0+tx;
            wh[idx] = hh;
            wm[idx] = __float2half_rn(v - __half2float(hh));
        }
    }
}

// ---------------- pairwise bias precompute ----------------
__global__ void __launch_bounds__(128) bias_pre(
    const float* __restrict__ Tq, const float* __restrict__ Tk,
    const float* __restrict__ kw1, const float* __restrict__ kb1,
    const float* __restrict__ kw2, hf* __restrict__ Bg)
{
    const int q = blockIdx.x, m = blockIdx.y;
    const int tid = threadIdx.x;
    __shared__ float w2s[8][16];
    for (int i = tid; i < 128; i += 128)
        w2s[i>>4][i&15] = kw2[(i&15)*HH + (i>>4)] * LOG2E;
    __syncthreads();

    float k1a[16], k1b[16], uq[16];
    float2 tq = *(const float2*)(Tq + (size_t)(m*NQL+q)*2);
#pragma unroll
    for (int j = 0; j < 16; j++){
        k1a[j] = kw1[j]; k1b[j] = kw1[16+j];
        uq[j] = tq.x*k1a[j] + tq.y*k1b[j] + kb1[j];
    }
    float bt[8][8];
#pragma unroll
    for (int ko = 0; ko < 8; ko++){
        int k = tid*8 + ko;
        float2 tk = *(const float2*)(Tk + (size_t)(m*NKVL+k)*2);
        float r[16];
#pragma unroll
        for (int j = 0; j < 16; j++)
            r[j] = fmaxf(uq[j] - (tk.x*k1a[j] + tk.y*k1b[j]), 0.f);
#pragma unroll
        for (int h = 0; h < 8; h++){
            float s = 0.f;
#pragma unroll
            for (int j = 0; j < 16; j++) s = fmaf(w2s[h][j], r[j], s);
            bt[h][ko] = s;
        }
    }
#pragma unroll
    for (int h = 0; h < 8; h++){
        __half2 o[4];
#pragma unroll
        for (int p = 0; p < 4; p++)
            o[p] = __floats2half2_rn(bt[h][2*p], bt[h][2*p+1]);
        *(uint4*)(Bg + ((size_t)(m*HH+h)*NQL + q)*NKVL + tid*8) = *(uint4*)o;
    }
}

// ---------------- V f32 -> fp16 transposed ----------------
__global__ void vtrans(const float* __restrict__ V, hf* __restrict__ Vh){
    __shared__ float t[32][33];
    int z = blockIdx.z, m = z>>3, h = z&7;
    int kk0 = blockIdx.x*32, d0 = blockIdx.y*32;
    int tx = threadIdx.x, ty = threadIdx.y;
#pragma unroll
    for (int i=0;i<32;i+=8)
        t[ty+i][tx] = V[(size_t)(m*NKVL + kk0+ty+i)*DD + h*64 + d0+tx];
    __syncthreads();
#pragma unroll
    for (int i=0;i<32;i+=8){
        size_t idx = (size_t)(z*64 + d0+ty+i)*NKVL + kk0 + tx;
        Vh[idx] = __float2half_rn(t[tx][ty+i]);
    }
}

// ---------------- GEMM core (AMID/BMID select precision passes) ------------
#define PSTG 40960
#define PJ_SMEM (2*PSTG)

#define PJ_ISSUE(kt, s) do{ \
    uint32_t st = sb + (s)*PSTG; int k0 = (kt)*32; \
    for (int i = tid; i < 512; i += 256){ \
        int r = i>>2; uint32_t ro = r*80 + (i&3)*16; int c8 = (i&3)*8; \
        size_t ga = (size_t)(bm+r)*DD + k0 + c8; \
        cp16(st + ro, Ah + ga); \
        if (AMID) cp16(st + 10240 + ro, Am + ga); \
        size_t gb = (size_t)(bn+r)*DD + k0 + c8; \
        cp16(st + 20480 + ro, Bh + gb); \
        if (BMID) cp16(st + 30720 + ro, Bm + gb); \
    } CP_COMMIT(); }while(0)

#define PJ_MAINLOOP() \
    PJ_ISSUE(0, 0); \
    _Pragma("unroll 1") \
    for (int kt = 0; kt < 16; kt++){ \
        if (kt < 15){ \
            PJ_ISSUE(kt+1, (kt+1)&1); \
            asm volatile("cp.async.wait_group 1;":::"memory"); \
        } else { \
            asm volatile("cp.async.wait_group 0;":::"memory"); \
        } \
        __syncthreads(); \
        uint32_t sA  = sb + (kt&1)*PSTG; \
        uint32_t sAm = sA + 10240, sB = sA + 20480, sBm = sA + 30720; \
        _Pragma("unroll") \
        for (int ks = 0; ks < 2; ks++){ \
            uint32_t ah[4][4], am[4][4]; \
            _Pragma("unroll") \
            for (int mi = 0; mi < 4; mi++){ \
                uint32_t abase = (uint32_t)((wm + mi*16)*80 + ks*32) + aoffA; \
                ldm4(ah[mi][0],ah[mi][1],ah[mi][2],ah[mi][3], sA + abase); \
                if (AMID) ldm4(am[mi][0],am[mi][1],am[mi][2],am[mi][3], sAm + abase); \
            } \
            _Pragma("unroll") \
            for (int njp = 0; njp < 2; njp++){ \
                uint32_t bbase = (uint32_t)((wn + njp*16)*80 + ks*32) + aoffB; \
                uint32_t bh0,bh1,bh2,bh3, bm0,bm1,bm2,bm3; \
                ldm4(bh0,bh1,bh2,bh3, sB + bbase); \
                if (BMID) ldm4(bm0,bm1,bm2,bm3, sBm + bbase); \
                _Pragma("unroll") \
                for (int mi = 0; mi < 4; mi++){ \
                    mma16816(acc[mi][njp*2],   ah[mi], bh0, bh1); \
                    if (BMID) mma16816(acc[mi][njp*2],   ah[mi], bm0, bm1); \
                    if (AMID) mma16816(acc[mi][njp*2],   am[mi], bh0, bh1); \
                    mma16816(acc[mi][njp*2+1], ah[mi], bh2, bh3); \
                    if (BMID) mma16816(acc[mi][njp*2+1], ah[mi], bm2, bm3); \
                    if (AMID) mma16816(acc[mi][njp*2+1], am[mi], bh2, bh3); \
                } \
            } \
        } \
        __syncthreads(); \
    }

#define PJ_LANEOFF() \
    const uint32_t aoffA = (uint32_t)((lane & 7)*80 + ((lane >> 3) & 1)*640 \
                                      + (lane >> 4)*16); \
    const uint32_t aoffB = (uint32_t)((lane & 7)*80 + ((lane >> 3) & 1)*16 \
                                      + (lane >> 4)*640);

// ---------------- merged QKV projection (z = 0:Q 1:K 2:V) ----------------
__global__ void __launch_bounds__(256,2) qkv_proj(
    const hf* __restrict__ Xh, const hf* __restrict__ Xm,
    const hf* __restrict__ Wh, const hf* __restrict__ Wm,
    hf* __restrict__ Qh, hf* __restrict__ Kh, float* __restrict__ Vf)
{
    extern __shared__ char sp[];
    uint32_t sb = smem_u32(sp);
    const int tid = threadIdx.x, lane = tid & 31, wid = tid >> 5;
    const int ln4 = lane >> 2, q2 = (lane & 3)*2;
    const int wm = (wid & 1)*64, wn = (wid >> 1)*32;
    const int bm = blockIdx.y*128, bn = blockIdx.x*128;
    const int z = blockIdx.z;
    const int AMID = (z != 2), BMID = (z != 2);   // V: fp16-rounded anyway
    PJ_LANEOFF();
    const hf* Ah = Xh + (size_t)z*N4;
    const hf* Am = Xm + (size_t)z*N4;
    const hf* Bh = Wh + (size_t)z*DD*DD;
    const hf* Bm = Wm + (size_t)z*DD*DD;
    float acc[4][4][4];
#pragma unroll
    for (int a=0;a<4;a++)
#pragma unroll
      for (int b=0;b<4;b++)
#pragma unroll
        for (int c=0;c<4;c++) acc[a][b][c]=0.f;

    PJ_MAINLOOP();

    const float scale = (z == 0) ? SCALE*LOG2E : 1.0f;
#pragma unroll
    for (int mi = 0; mi < 4; mi++){
        int r0 = bm + wm + mi*16 + ln4;
#pragma unroll
        for (int nj = 0; nj < 4; nj++){
            int c = bn + wn + nj*8 + q2;
            float v0 = acc[mi][nj][0]*scale, v1 = acc[mi][nj][1]*scale;
            float v2 = acc[mi][nj][2]*scale, v3 = acc[mi][nj][3]*scale;
            if (z == 2){
                *(float2*)(Vf + (size_t)r0*DD + c)     = make_float2(v0, v1);
                *(float2*)(Vf + (size_t)(r0+8)*DD + c) = make_float2(v2, v3);
            } else {
                hf* Ch = (z == 0) ? Qh : Kh;
                __half2 H0 = __floats2half2_rn(v0, v1);
                __half2 H1 = __floats2half2_rn(v2, v3);
                *(uint32_t*)(Ch + (size_t)r0*DD + c)     = *(uint32_t*)&H0;
                *(uint32_t*)(Ch + (size_t)(r0+8)*DD + c) = *(uint32_t*)&H1;
            }
        }
    }
}

// ---------------- output projection (A single-pass, W 2-pass) --------------
__global__ void __launch_bounds__(256,2) out_proj(
    const hf* __restrict__ Ah, const hf* __restrict__ Am,
    const hf* __restrict__ Bh, const hf* __restrict__ Bm,
    const float* __restrict__ bias, float* __restrict__ Cf)
{
    extern __shared__ char sp[];
    uint32_t sb = smem_u32(sp);
    const int tid = threadIdx.x, lane = tid & 31, wid = tid >> 5;
    const int ln4 = lane >> 2, q2 = (lane & 3)*2;
    const int wm = (wid & 1)*64, wn = (wid >> 1)*32;
    const int bm = blockIdx.y*128, bn = blockIdx.x*128;
    const int AMID = 0, BMID = 1;
    PJ_LANEOFF();
    float acc[4][4][4];
#pragma unroll
    for (int a=0;a<4;a++)
#pragma unroll
      for (int b=0;b<4;b++)
#pragma unroll
        for (int c=0;c<4;c++) acc[a][b][c]=0.f;

    PJ_MAINLOOP();

#pragma unroll
    for (int mi = 0; mi < 4; mi++){
        int r0 = bm + wm + mi*16 + ln4;
#pragma unroll
        for (int nj = 0; nj < 4; nj++){
            int c = bn + wn + nj*8 + q2;
            float b0 = bias[c], b1 = bias[c+1];
            *(float2*)(Cf + (size_t)r0*DD + c) =
                make_float2(acc[mi][nj][0] + b0, acc[mi][nj][1] + b1);
            *(float2*)(Cf + (size_t)(r0+8)*DD + c) =
                make_float2(acc[mi][nj][2] + b0, acc[mi][nj][3] + b1);
        }
    }
}

// ---------------- fused attention: 2-stage, j-fused, 2 CTA/SM --------------
#define O_QH 0
#define O_KV 18432
#define KVSTG 36864
#define S_KH 0
#define S_VH 9216
#define S_B  18432
#define AT_SMEM (O_KV + 2*KVSTG)   // 92160

__global__ void __launch_bounds__(256,2) attn_bf(
    const hf* __restrict__ Qh_g, const hf* __restrict__ Kh_g,
    const hf* __restrict__ Vh_g, const hf* __restrict__ Bg,
    hf* __restrict__ Cth)
{
    extern __shared__ char sp[];
    uint32_t sb = smem_u32(sp);

    const int tid = threadIdx.x, lane = tid & 31, wid = tid >> 5;
    const int ln4 = lane >> 2, q2 = (lane & 3)*2;
    const int m = blockIdx.z, h = blockIdx.y, q0 = blockIdx.x*128;
    const int rl0 = wid*16 + ln4;
    const uint32_t lmo = (uint32_t)((lane & 7)*144 + ((lane >> 3) >> 1)*32
                                    + ((lane >> 3) & 1)*16);
    const hf* Bpl = Bg + ((size_t)(m*HH+h)*NQL)*NKVL;

    for (int i = tid; i < 1024; i += 256){
        int r = i>>3; uint32_t ro = r*144 + (i&7)*16;
        size_t g = (size_t)(m*NQL+q0+r)*DD + h*64 + (i&7)*8;
        cp16(sb + O_QH + ro, Qh_g + g);
    }
#define KV_ISSUE(kk0, s) do{ \
    uint32_t st = sb + O_KV + (s)*KVSTG; \
    for (int i = tid; i < 1024; i += 256){ \
        int r = i>>3; uint32_t ro = r*144 + (i&7)*16; int c8 = (i&7)*8; \
        if (i < 512){ \
            size_t gk = (size_t)(m*NKVL + (kk0) + r)*DD + h*64 + c8; \
            cp16(st + S_KH + ro, Kh_g + gk); \
            size_t gv = (size_t)((m*HH+h)*64 + r)*NKVL + (kk0) + c8; \
            cp16(st + S_VH + ro, Vh_g + gv); \
        } \
        cp16(st + S_B + ro, Bpl + (size_t)(q0+r)*NKVL + (kk0) + c8); \
    } CP_COMMIT(); }while(0)

    KV_ISSUE(0, 0);
    KV_ISSUE(64, 1);

    asm volatile("cp.async.wait_group 1;":::"memory");
    __syncthreads();
    uint32_t qa[4][4];
    {
        const hf* Qh = (const hf*)(sp + O_QH);
#pragma unroll
        for (int ks = 0; ks < 4; ks++){
            int kb = ks*16 + q2;
            const hf* p = Qh + rl0*72 + kb;
            qa[ks][0]=*(const uint32_t*)p;     qa[ks][1]=*(const uint32_t*)(p+8*72);
            qa[ks][2]=*(const uint32_t*)(p+8); qa[ks][3]=*(const uint32_t*)(p+8*72+8);
        }
    }

    float oacc[8][4];
#pragma unroll
    for (int j=0;j<8;j++)
#pragma unroll
        for (int c=0;c<4;c++) oacc[j][c]=0.f;
    float l0 = 0.f, l1 = 0.f;

#pragma unroll 1
    for (int t = 0; t < 16; t++){
        if (t < 15){
            asm volatile("cp.async.wait_group 1;":::"memory");
        } else {
            asm volatile("cp.async.wait_group 0;":::"memory");
        }
        __syncthreads();
        const int scur = t & 1;
        const uint32_t stb = sb + O_KV + scur*KVSTG;
        const uint32_t kh_a = stb + S_KH + lmo;
        const uint32_t vh_a = stb + S_VH + lmo;
        const char* Bst = sp + O_KV + scur*KVSTG + S_B;

        // ---- per-j: S-MMA -> +bias -> exp2 -> pack (sacc stays 4 regs) ----
        uint32_t pa[4][4];
#pragma unroll
        for (int j = 0; j < 8; j++){
            float sacc[4] = {0.f, 0.f, 0.f, 0.f};
#pragma unroll
            for (int p = 0; p < 2; p++){
                uint32_t kh0,kh1,kh2,kh3;
                ldm4(kh0,kh1,kh2,kh3, kh_a + j*1152 + p*64);
                mma16816(sacc, qa[2*p],   kh0, kh1);
                mma16816(sacc, qa[2*p+1], kh2, kh3);
            }
            int c = j*8 + q2;
            __half2 b0 = *(const __half2*)(Bst + rl0*144 + c*2);
            __half2 b1 = *(const __half2*)(Bst + (rl0+8)*144 + c*2);
            float2 f0 = __half22float2(b0), f1 = __half22float2(b1);
            float e0 = exp2f(sacc[0] + f0.x);
            float e1 = exp2f(sacc[1] + f0.y);
            float e2 = exp2f(sacc[2] + f1.x);
            float e3 = exp2f(sacc[3] + f1.y);
            l0 += e0 + e1; l1 += e2 + e3;
            int tt2 = j >> 1, base = (j & 1)*2;
            __half2 P0 = __floats2half2_rn(e0, e1);
            __half2 P1 = __floats2half2_rn(e2, e3);
            pa[tt2][base]   = *(uint32_t*)&P0;
            pa[tt2][base+1] = *(uint32_t*)&P1;
        }

        // ---- O += P @ V^T ----
#pragma unroll
        for (int j2 = 0; j2 < 8; j2++){
#pragma unroll
            for (int p = 0; p < 2; p++){
                uint32_t vh0,vh1,vh2,vh3;
                ldm4(vh0,vh1,vh2,vh3, vh_a + j2*1152 + p*64);
                mma16816(oacc[j2], pa[2*p],   vh0, vh1);
                mma16816(oacc[j2], pa[2*p+1], vh2, vh3);
            }
        }
        __syncthreads();
        if (t <= 13) KV_ISSUE((t+2)*64, scur);
    }

    l0 += __shfl_xor_sync(0xffffffffu, l0, 1);
    l0 += __shfl_xor_sync(0xffffffffu, l0, 2);
    l1 += __shfl_xor_sync(0xffffffffu, l1, 1);
    l1 += __shfl_xor_sync(0xffffffffu, l1, 2);
    float inv0 = 1.f/l0, inv1 = 1.f/l1;
    size_t o0 = (size_t)(m*NQL + q0 + rl0)*DD + h*64;
    size_t o1 = o0 + 8*DD;
#pragma unroll
    for (int j2 = 0; j2 < 8; j2++){
        int c = j2*8 + q2;
        __half2 H0 = __floats2half2_rn(oacc[j2][0]*inv0, oacc[j2][1]*inv0);
        __half2 H1 = __floats2half2_rn(oacc[j2][2]*inv1, oacc[j2][3]*inv1);
        *(uint32_t*)(Cth + o0 + c) = *(uint32_t*)&H0;
        *(uint32_t*)(Cth + o1 + c) = *(uint32_t*)&H1;
    }
}

// ---------------- host launcher ----------------
extern "C" void kernel_launch(void* const* d_in, const int* in_sizes, int n_in,
                              void* d_out, int out_size)
{
    const float* xq    = (const float*)d_in[0];
    const float* xk    = (const float*)d_in[1];
    const float* xv    = (const float*)d_in[2];
    const float* tq    = (const float*)d_in[3];
    const float* tk    = (const float*)d_in[4];
    const float* w_q   = (const float*)d_in[5];
    const float* w_k   = (const float*)d_in[6];
    const float* w_v   = (const float*)d_in[7];
    const float* w_out = (const float*)d_in[8];
    const float* b_out = (const float*)d_in[9];
    const float* kw1   = (const float*)d_in[10];
    const float* kb1   = (const float*)d_in[11];
    const float* kw2   = (const float*)d_in[12];
    const float* kb2   = (const float*)d_in[13];
    float* out = (float*)d_out;
    (void)kb2;

    hf *xh,*xm,*wh,*wm,*qh,*kh,*vth,*cth,*bp;
    float *vf;
    cudaGetSymbolAddress((void**)&xh,  g_xh);
    cudaGetSymbolAddress((void**)&xm,  g_xm);
    cudaGetSymbolAddress((void**)&wh,  g_wh);
    cudaGetSymbolAddress((void**)&wm,  g_wm);
    cudaGetSymbolAddress((void**)&qh,  g_qh);
    cudaGetSymbolAddress((void**)&kh,  g_kh);
    cudaGetSymbolAddress((void**)&vf,  g_vf);
    cudaGetSymbolAddress((void**)&vth, g_vth);
    cudaGetSymbolAddress((void**)&cth, g_cth);
    cudaGetSymbolAddress((void**)&bp,  g_bias);

    cudaFuncSetAttribute(qkv_proj, cudaFuncAttributeMaxDynamicSharedMemorySize, PJ_SMEM);
    cudaFuncSetAttribute(out_proj, cudaFuncAttributeMaxDynamicSharedMemorySize, PJ_SMEM);
    cudaFuncSetAttribute(attn_bf,  cudaFuncAttributeMaxDynamicSharedMemorySize, AT_SMEM);

    dim3 gp(N4/1024, 4);
    prep<<<gp, 256>>>(xq, xk, xv, w_q, w_k, w_v, w_out, xh, xm, wh, wm);

    dim3 gb(NQL, MBN);
    bias_pre<<<gb, 128>>>(tq, tk, kw1, kb1, kw2, bp);

    dim3 gq(4, 64, 3);
    qkv_proj<<<gq,256,PJ_SMEM>>>(xh, xm, wh, wm, qh, kh, vf);

    dim3 gv(32, 2, 64), tb(32,8);
    vtrans<<<gv,tb>>>(vf, vth);

    dim3 ga(8, HH, MBN);
    attn_bf<<<ga,256,AT_SMEM>>>(qh, kh, vth, bp, cth);

    dim3 go(4, 64);
    out_proj<<<go,256,PJ_SMEM>>>(cth, cth, wh+3*(size_t)DD*DD, wm+3*(size_t)DD*DD,
                                 b_out, out);
}